// round 9
// baseline (speedup 1.0000x reference)
#include <cuda_runtime.h>
#include <cuda_fp16.h>
#include <cstdint>

// Problem constants
constexpr int Bb = 4, Ts = 1024, Cc = 1024, Hh = 8, Dd = 128, Ff = 4096, Ll = 4;
constexpr int Mr = Bb * Ts;  // 4096

// ---------------- scratch (device globals; allocation-free rule) ----------
__device__ float  g_h[(size_t)Mr * Cc];                    // residual fp32
__device__ __half g_qkv[(size_t)3 * Hh * Mr * Dd];         // q,k rows; vT cols
__device__ __half g_xn[(size_t)Mr * Cc];                   // LN out fp16
__device__ __half g_o[(size_t)Mr * Cc];                    // attn out fp16
__device__ __half g_u[(size_t)Mr * Ff];                    // FFN hidden fp16
__device__ __half g_att[(size_t)Hh * Bb * Ts * Ts];        // logits -> probs fp16
__device__ __half g_wqkv_h[(size_t)Ll * 3 * Hh * Dd * Cc]; // fp16 weights [N,K]
__device__ __half g_wo_h[(size_t)Ll * Cc * Cc];
__device__ __half g_w1_h[(size_t)Ll * Cc * Ff];
__device__ __half g_w2_h[(size_t)Ll * Ff * Cc];

// ---------------- PTX helpers (sm_80-era; compiles for plain sm_103) ------
__device__ __forceinline__ uint32_t smem_u32(const void* p) {
    uint32_t a;
    asm("{ .reg .u64 t; cvta.to.shared.u64 t, %1; cvt.u32.u64 %0, t; }" : "=r"(a) : "l"(p));
    return a;
}
__device__ __forceinline__ void cp16(uint32_t s, const void* g) {
    asm volatile("cp.async.cg.shared.global [%0], [%1], 16;" :: "r"(s), "l"(g));
}
#define CP_COMMIT() asm volatile("cp.async.commit_group;" ::: "memory")
#define CP_WAIT(n)  asm volatile("cp.async.wait_group %0;" :: "n"(n) : "memory")

#define LDSM4(r, addr) \
    asm volatile("ldmatrix.sync.aligned.m8n8.x4.shared.b16 {%0,%1,%2,%3}, [%4];" \
        : "=r"((r)[0]), "=r"((r)[1]), "=r"((r)[2]), "=r"((r)[3]) : "r"(addr))

#define MMA16816(c, a, b) \
    asm volatile("mma.sync.aligned.m16n8k16.row.col.f32.f16.f16.f32 " \
        "{%0,%1,%2,%3}, {%4,%5,%6,%7}, {%8,%9}, {%0,%1,%2,%3};" \
        : "+f"((c)[0]), "+f"((c)[1]), "+f"((c)[2]), "+f"((c)[3]) \
        : "r"((a)[0]), "r"((a)[1]), "r"((a)[2]), "r"((a)[3]), \
          "r"((b)[0]), "r"((b)[1]))

// ---------------------------------------------------------------------------
// HMMA fp16 GEMM: C[M,N] = A[M,K] * Bt[N,K]^T, fp32 register accumulate.
// Block tile 256x128, 8 warps (4M x 2N) -> warp tile 64x64 (128 B LDSM/MMA).
// K-chunks of 64, 3-stage cp.async, occupancy 1 (~190 regs).
// SMEM rows: 128B payload + 16B pad (stride 144); A rows 0-255, B rows 256-383.
// z offsets: (z/div)*shi + (z%div)*slo per operand.
// EPI: 1 fp16 rows | 2 fp32 += acc+bias | 4 relu(acc+bias)->fp16 rows
//      5 QKV: z<16 fp16 rows, z>=16 vT transposed (ld = Mr)
// ---------------------------------------------------------------------------
constexpr int STG   = 55296;            // 384 rows * 144 B
constexpr int B_OFF = 36864;            // 256 rows * 144 B
constexpr int SM_MM = 3 * STG;          // 165888

template<int EPI>
__global__ void __launch_bounds__(256, 1)
gemm_mma(const __half* __restrict__ A, int lda,
         int aDiv, long long aShi, long long aSlo,
         const __half* __restrict__ B, int ldb,
         int bDiv, long long bShi, long long bSlo,
         float* __restrict__ Cm, int ldc,
         int cDiv, long long cShi, long long cSlo,
         const float* __restrict__ bias, int K)
{
    extern __shared__ char sm[];
    const uint32_t sb = smem_u32(sm);

    const int tid = threadIdx.x;
    const int lane = tid & 31;
    const int warp = tid >> 5;
    const int warpM = warp & 3;      // 4 M-warps (64 rows each)
    const int warpN = warp >> 2;     // 2 N-warps (64 cols each)

    const int z = blockIdx.z;
    A  += (long long)(z / aDiv) * aShi + (long long)(z % aDiv) * aSlo;
    B  += (long long)(z / bDiv) * bShi + (long long)(z % bDiv) * bSlo;
    const long long cOff = (long long)(z / cDiv) * cShi + (long long)(z % cDiv) * cSlo;

    const int rowBase = blockIdx.y * 256;
    const int colBase = blockIdx.x * 128;

    float acc[4][8][4];
#pragma unroll
    for (int i = 0; i < 4; i++)
#pragma unroll
        for (int j = 0; j < 8; j++)
#pragma unroll
            for (int q = 0; q < 4; q++) acc[i][j][q] = 0.f;

    const int nCh = K >> 6;              // K-chunks of 64
    const int ldr = tid >> 3;            // 0..31
    const int c16 = (tid & 7) * 16;      // byte col in 128B row

    auto load_chunk = [&](int i, int st) {
        const long long k0 = (long long)i * 64;
        const uint32_t sbase = sb + (uint32_t)st * STG;
#pragma unroll
        for (int g = 0; g < 12; g++) {
            const int rr = g * 32 + ldr;             // 0..383
            const uint32_t so = sbase + (uint32_t)(rr * 144 + c16);
            const char* src = (rr < 256)
                ? (const char*)(A + (long long)(rowBase + rr) * lda + k0) + c16
                : (const char*)(B + (long long)(colBase + rr - 256) * ldb + k0) + c16;
            cp16(so, src);
        }
    };

    load_chunk(0, 0); CP_COMMIT();
    load_chunk(1, 1); CP_COMMIT();

    for (int i = 0; i < nCh; i++) {
        if (i + 1 < nCh) { CP_WAIT(1); } else { CP_WAIT(0); }
        __syncthreads();
        if (i + 2 < nCh) { load_chunk(i + 2, (i + 2) % 3); CP_COMMIT(); }

        const uint32_t sbase = sb + (uint32_t)(i % 3) * STG;
#pragma unroll
        for (int ks = 0; ks < 4; ks++) {
            uint32_t ah[4][4], bh[8][2];
#pragma unroll
            for (int tm = 0; tm < 4; tm++) {
                const int row = warpM * 64 + tm * 16 + (lane & 15);
                const uint32_t addr =
                    sbase + (uint32_t)(row * 144 + ((lane >> 4) << 4) + ks * 32);
                LDSM4(ah[tm], addr);
            }
#pragma unroll
            for (int gn = 0; gn < 4; gn++) {
                const int n = warpN * 64 + gn * 16 + ((lane >> 4) & 1) * 8 + (lane & 7);
                const uint32_t addr =
                    sbase + (uint32_t)B_OFF +
                    (uint32_t)(n * 144 + ((lane >> 3) & 1) * 16 + ks * 32);
                uint32_t r0[4];
                LDSM4(r0, addr);
                bh[gn * 2][0] = r0[0]; bh[gn * 2][1] = r0[1];
                bh[gn * 2 + 1][0] = r0[2]; bh[gn * 2 + 1][1] = r0[3];
            }
#pragma unroll
            for (int tm = 0; tm < 4; tm++) {
#pragma unroll
                for (int tn = 0; tn < 8; tn++) {
                    MMA16816(acc[tm][tn], ah[tm], bh[tn]);
                }
            }
        }
    }

    // ---- epilogue from registers ----
    const int rB = rowBase + warpM * 64;
    const int cB = colBase + warpN * 64;
    const int lr = lane >> 2;
    const int lc = (lane & 3) * 2;
#pragma unroll
    for (int tm = 0; tm < 4; tm++) {
#pragma unroll
        for (int tn = 0; tn < 8; tn++) {
            const int row0 = rB + tm * 16 + lr;
            const int col  = cB + tn * 8 + lc;
            const float* a = acc[tm][tn];
            if (EPI == 2) {
                const float b0 = bias[col], b1 = bias[col + 1];
                float* p0 = Cm + cOff + (long long)row0 * ldc + col;
                float* p1 = Cm + cOff + (long long)(row0 + 8) * ldc + col;
                p0[0] += a[0] + b0;  p0[1] += a[1] + b1;
                p1[0] += a[2] + b0;  p1[1] += a[3] + b1;
            } else if (EPI == 5 && z >= 16) {
                // v: store transposed vT[col, row], ld = Mr
                __half* base = (__half*)Cm + cOff;
#pragma unroll
                for (int half_ = 0; half_ < 2; half_++) {
                    const int row = row0 + half_ * 8;
                    base[(long long)col * Mr + row] =
                        __float2half_rn(a[half_ * 2 + 0]);
                    base[(long long)(col + 1) * Mr + row] =
                        __float2half_rn(a[half_ * 2 + 1]);
                }
            } else if (EPI == 4) {
                const float b0 = bias[col], b1 = bias[col + 1];
                __half* ph = (__half*)Cm + cOff;
#pragma unroll
                for (int half_ = 0; half_ < 2; half_++) {
                    float t0 = a[half_ * 2 + 0] + b0;
                    float t1 = a[half_ * 2 + 1] + b1;
                    t0 = t0 > 0.f ? t0 : 0.f;
                    t1 = t1 > 0.f ? t1 : 0.f;
                    *(__half2*)(ph + (long long)(row0 + half_ * 8) * ldc + col) =
                        __halves2half2(__float2half_rn(t0), __float2half_rn(t1));
                }
            } else {  // EPI 1 or 5(q,k): fp16 row store
                __half* ph = (__half*)Cm + cOff;
#pragma unroll
                for (int half_ = 0; half_ < 2; half_++) {
                    *(__half2*)(ph + (long long)(row0 + half_ * 8) * ldc + col) =
                        __halves2half2(__float2half_rn(a[half_ * 2 + 0]),
                                       __float2half_rn(a[half_ * 2 + 1]));
                }
            }
        }
    }
}

// ---------------------------------------------------------------------------
// Weight transpose + fp16 convert: W[z][K,N] fp32 -> [z-map][N,K] fp16
// ---------------------------------------------------------------------------
__global__ void __launch_bounds__(256)
transpose_h(const float* __restrict__ W, long long inSlo,
            __half* __restrict__ hi,
            int outDiv, long long outShi, long long outSlo, int K, int N)
{
    const int z = blockIdx.z;
    W += (long long)z * inSlo;
    const long long oOff = (long long)(z / outDiv) * outShi + (long long)(z % outDiv) * outSlo;
    __shared__ float t[32][33];
    const int tx = threadIdx.x & 31, ty = threadIdx.x >> 5;
    const int n0 = blockIdx.x * 32, k0 = blockIdx.y * 32;
#pragma unroll
    for (int i = 0; i < 4; i++)
        t[ty + i * 8][tx] = W[(long long)(k0 + ty + i * 8) * N + n0 + tx];
    __syncthreads();
#pragma unroll
    for (int i = 0; i < 4; i++) {
        const float v = t[tx][ty + i * 8];
        hi[oOff + (long long)(n0 + ty + i * 8) * K + k0 + tx] = __float2half_rn(v);
    }
}

// ---------------------------------------------------------------------------
// LayerNorm, rows of 1024. FP16OUT: fp16 out, else fp32.
// ---------------------------------------------------------------------------
template<bool FP16OUT>
__global__ void __launch_bounds__(256)
ln_kernel(const float* __restrict__ x, float* __restrict__ y,
          __half* __restrict__ yh,
          const float* __restrict__ s, const float* __restrict__ b)
{
    __shared__ float red[256];
    const int tid = threadIdx.x;
    const long long row = blockIdx.x;
    const float* xr = x + row * 1024;

    float4 v = *(const float4*)(xr + tid * 4);
    red[tid] = v.x + v.y + v.z + v.w;
    __syncthreads();
    for (int o = 128; o > 0; o >>= 1) {
        if (tid < o) red[tid] += red[tid + o];
        __syncthreads();
    }
    const float mean = red[0] * (1.f / 1024.f);
    __syncthreads();

    float dx = v.x - mean, dy = v.y - mean, dz = v.z - mean, dw = v.w - mean;
    red[tid] = dx * dx + dy * dy + dz * dz + dw * dw;
    __syncthreads();
    for (int o = 128; o > 0; o >>= 1) {
        if (tid < o) red[tid] += red[tid + o];
        __syncthreads();
    }
    const float var = red[0] * (1.f / 1024.f);
    const float rs = rsqrtf(var + 1e-5f);

    const int c = tid * 4;
    float t0 = dx * rs * s[c + 0] + b[c + 0];
    float t1 = dy * rs * s[c + 1] + b[c + 1];
    float t2 = dz * rs * s[c + 2] + b[c + 2];
    float t3 = dw * rs * s[c + 3] + b[c + 3];
    if (FP16OUT) {
        __half* ph = yh + row * 1024 + c;
        *(__half2*)ph = __halves2half2(__float2half_rn(t0), __float2half_rn(t1));
        *(__half2*)(ph + 2) = __halves2half2(__float2half_rn(t2), __float2half_rn(t3));
    } else {
        float4 o4 = {t0, t1, t2, t3};
        *(float4*)(y + row * 1024 + c) = o4;
    }
}

// ---------------------------------------------------------------------------
// Softmax over rows of 1024: reads fp16 logits, writes fp32 atts (output)
// and fp16 probs in place of the logits.
// ---------------------------------------------------------------------------
__global__ void __launch_bounds__(256)
softmax_kernel(__half* __restrict__ logit, float* __restrict__ atts_out)
{
    __shared__ float red[256];
    const int tid = threadIdx.x;
    const long long row = blockIdx.x;
    __half* pr = logit + row * 1024;
    const float sc = 0.08838834764831845f;  // 1/sqrt(128)

    __half2 h01 = *(__half2*)(pr + tid * 4);
    __half2 h23 = *(__half2*)(pr + tid * 4 + 2);
    float v0 = __half2float(__low2half(h01)) * sc;
    float v1 = __half2float(__high2half(h01)) * sc;
    float v2 = __half2float(__low2half(h23)) * sc;
    float v3 = __half2float(__high2half(h23)) * sc;

    float mx = fmaxf(fmaxf(v0, v1), fmaxf(v2, v3));
    red[tid] = mx;
    __syncthreads();
    for (int o = 128; o > 0; o >>= 1) {
        if (tid < o) red[tid] = fmaxf(red[tid], red[tid + o]);
        __syncthreads();
    }
    const float m = red[0];
    __syncthreads();

    v0 = __expf(v0 - m); v1 = __expf(v1 - m);
    v2 = __expf(v2 - m); v3 = __expf(v3 - m);
    red[tid] = v0 + v1 + v2 + v3;
    __syncthreads();
    for (int o = 128; o > 0; o >>= 1) {
        if (tid < o) red[tid] += red[tid + o];
        __syncthreads();
    }
    const float inv = 1.f / red[0];
    v0 *= inv; v1 *= inv; v2 *= inv; v3 *= inv;

    float4 o4 = {v0, v1, v2, v3};
    *(float4*)(atts_out + row * 1024 + tid * 4) = o4;
    *(__half2*)(pr + tid * 4) =
        __halves2half2(__float2half_rn(v0), __float2half_rn(v1));
    *(__half2*)(pr + tid * 4 + 2) =
        __halves2half2(__float2half_rn(v2), __float2half_rn(v3));
}

__global__ void __launch_bounds__(256)
add_pos_kernel(const float4* __restrict__ x, const float4* __restrict__ pos,
               float4* __restrict__ h)
{
    const int i = blockIdx.x * 256 + threadIdx.x;
    const int pi = i & (Ts * Cc / 4 - 1);
    float4 a = x[i], p = pos[pi];
    a.x += p.x; a.y += p.y; a.z += p.z; a.w += p.w;
    h[i] = a;
}

// ---------------------------------------------------------------------------
extern "C" void kernel_launch(void* const* d_in, const int* in_sizes, int n_in,
                              void* d_out, int out_size)
{
    const float* x     = (const float*)d_in[0];
    const float* pos   = (const float*)d_in[1];
    const float* Wq    = (const float*)d_in[2];
    const float* Wk    = (const float*)d_in[3];
    const float* Wv    = (const float*)d_in[4];
    const float* Wo    = (const float*)d_in[5];
    const float* bo    = (const float*)d_in[6];
    const float* ln1_s = (const float*)d_in[7];
    const float* ln1_b = (const float*)d_in[8];
    const float* ln2_s = (const float*)d_in[9];
    const float* ln2_b = (const float*)d_in[10];
    const float* W1    = (const float*)d_in[11];
    const float* b1    = (const float*)d_in[12];
    const float* W2    = (const float*)d_in[13];
    const float* b2    = (const float*)d_in[14];
    const float* lnf_s = (const float*)d_in[15];
    const float* lnf_b = (const float*)d_in[16];

    float* out  = (float*)d_out;
    float* outx = out;
    float* atts = out + (long long)Mr * Cc;

    float* h;
    __half *qkv, *xn, *o, *u, *att, *wqkv_h, *wo_h, *w1_h, *w2_h;
    cudaGetSymbolAddress((void**)&h,      g_h);
    cudaGetSymbolAddress((void**)&qkv,    g_qkv);
    cudaGetSymbolAddress((void**)&xn,     g_xn);
    cudaGetSymbolAddress((void**)&o,      g_o);
    cudaGetSymbolAddress((void**)&u,      g_u);
    cudaGetSymbolAddress((void**)&att,    g_att);
    cudaGetSymbolAddress((void**)&wqkv_h, g_wqkv_h);
    cudaGetSymbolAddress((void**)&wo_h,   g_wo_h);
    cudaGetSymbolAddress((void**)&w1_h,   g_w1_h);
    cudaGetSymbolAddress((void**)&w2_h,   g_w2_h);

    cudaFuncSetAttribute(gemm_mma<1>, cudaFuncAttributeMaxDynamicSharedMemorySize, SM_MM);
    cudaFuncSetAttribute(gemm_mma<2>, cudaFuncAttributeMaxDynamicSharedMemorySize, SM_MM);
    cudaFuncSetAttribute(gemm_mma<4>, cudaFuncAttributeMaxDynamicSharedMemorySize, SM_MM);
    cudaFuncSetAttribute(gemm_mma<5>, cudaFuncAttributeMaxDynamicSharedMemorySize, SM_MM);

    const long long DK   = (long long)Dd * Cc;       // 131072
    const long long HDK  = Hh * DK;
    const long long HMrD = (long long)Hh * Mr * Dd;
    const long long QZ   = (long long)Ts * Dd;
    const long long SZ   = (long long)Ts * Ts;
    const long long HBTT = (long long)Hh * Bb * Ts * Ts;

    add_pos_kernel<<<Mr * Cc / 1024, 256>>>((const float4*)x, (const float4*)pos, (float4*)h);
    transpose_h<<<dim3(Dd / 32, Cc / 32, Ll * Hh), 256>>>(
        Wq, DK, wqkv_h + 0 * HDK, Hh, 3 * HDK, DK, Cc, Dd);
    transpose_h<<<dim3(Dd / 32, Cc / 32, Ll * Hh), 256>>>(
        Wk, DK, wqkv_h + 1 * HDK, Hh, 3 * HDK, DK, Cc, Dd);
    transpose_h<<<dim3(Dd / 32, Cc / 32, Ll * Hh), 256>>>(
        Wv, DK, wqkv_h + 2 * HDK, Hh, 3 * HDK, DK, Cc, Dd);

    for (int l = 0; l < Ll; l++) {
        float* atts_l = atts + (long long)l * HBTT;

        // LN1 -> xn fp16
        ln_kernel<true><<<Mr, 256>>>(h, nullptr, xn, ln1_s + l * Cc, ln1_b + l * Cc);

        // QKV: z = s*8+h (24). q,k: fp16 rows; v: vT (ld=Mr). M=4096 -> gy=16
        gemm_mma<5><<<dim3(1, 16, 24), 256, SM_MM>>>(
            xn, Cc, 1, 0, 0,
            wqkv_h + (long long)l * 3 * HDK, Cc, 1, DK, 0,
            (float*)qkv, Dd, 1, (long long)Mr * Dd, 0,
            nullptr, Cc);

        if (l == 0) {
            transpose_h<<<dim3(Cc / 32, Cc / 32, Ll), 256>>>(
                Wo, (long long)Cc * Cc, wo_h, 1, (long long)Cc * Cc, 0, Cc, Cc);
            transpose_h<<<dim3(Ff / 32, Cc / 32, Ll), 256>>>(
                W1, (long long)Cc * Ff, w1_h, 1, (long long)Ff * Cc, 0, Cc, Ff);
            transpose_h<<<dim3(Cc / 32, Ff / 32, Ll), 256>>>(
                W2, (long long)Ff * Cc, w2_h, 1, (long long)Cc * Ff, 0, Ff, Cc);
        }

        // scores = q k^T -> fp16 logits; z = h*Bb + b. M=1024 -> gy=4
        gemm_mma<1><<<dim3(8, 4, 32), 256, SM_MM>>>(
            qkv, Dd, Bb, (long long)Mr * Dd, QZ,
            qkv + HMrD, Dd, Bb, (long long)Mr * Dd, QZ,
            (float*)att, Ts, 1, SZ, 0,
            nullptr, Dd);

        // softmax: fp16 logits -> fp32 atts (output) + fp16 probs in place
        softmax_kernel<<<Hh * Bb * Ts, 256>>>(att, atts_l);

        // o = att @ vT -> fp16 concat [B*T, C]. M=1024 -> gy=4
        gemm_mma<1><<<dim3(1, 4, 32), 256, SM_MM>>>(
            att, Ts, 1, SZ, 0,
            qkv + 2 * HMrD, Mr, Bb, (long long)Mr * Dd, Ts,
            (float*)o, Cc, Bb, 128, (long long)Ts * Cc,
            nullptr, Ts);

        // proj: h += o @ Wo + bo. M=4096 -> gy=16
        gemm_mma<2><<<dim3(8, 16, 1), 256, SM_MM>>>(
            o, Cc, 1, 0, 0,
            wo_h + (long long)l * Cc * Cc, Cc, 1, 0, 0,
            h, Cc, 1, 0, 0,
            bo + l * Cc, Cc);

        // LN2 -> xn fp16
        ln_kernel<true><<<Mr, 256>>>(h, nullptr, xn, ln2_s + l * Cc, ln2_b + l * Cc);

        // FFN1: u = relu(xn @ W1 + b1) -> fp16
        gemm_mma<4><<<dim3(32, 16, 1), 256, SM_MM>>>(
            xn, Cc, 1, 0, 0,
            w1_h + (long long)l * Cc * Ff, Cc, 1, 0, 0,
            (float*)u, Ff, 1, 0, 0,
            b1 + l * Ff, Cc);

        // FFN2: h += u @ W2 + b2
        gemm_mma<2><<<dim3(8, 16, 1), 256, SM_MM>>>(
            u, Ff, 1, 0, 0,
            w2_h + (long long)l * Ff * Cc, Ff, 1, 0, 0,
            h, Cc, 1, 0, 0,
            b2 + l * Cc, Ff);
    }

    ln_kernel<false><<<Mr, 256>>>(h, outx, nullptr, lnf_s, lnf_b);
}

// round 10
// speedup vs baseline: 1.1172x; 1.1172x over previous
#include <cuda_runtime.h>
#include <cuda_fp16.h>
#include <cstdint>

// Problem constants
constexpr int Bb = 4, Ts = 1024, Cc = 1024, Hh = 8, Dd = 128, Ff = 4096, Ll = 4;
constexpr int Mr = Bb * Ts;  // 4096

// ---------------- scratch (device globals; allocation-free rule) ----------
__device__ float  g_h[(size_t)Mr * Cc];                    // residual fp32
__device__ __half g_qkv[(size_t)3 * Hh * Mr * Dd];         // q,k rows; vT cols
__device__ __half g_xn[(size_t)Mr * Cc];                   // LN out fp16
__device__ __half g_o[(size_t)Mr * Cc];                    // attn out fp16
__device__ __half g_u[(size_t)Mr * Ff];                    // FFN hidden fp16
__device__ __half g_att[(size_t)Hh * Bb * Ts * Ts];        // logits -> probs fp16
__device__ __half g_wqkv_h[(size_t)Ll * 3 * Hh * Dd * Cc]; // fp16 weights [N,K]
__device__ __half g_wo_h[(size_t)Ll * Cc * Cc];
__device__ __half g_w1_h[(size_t)Ll * Cc * Ff];
__device__ __half g_w2_h[(size_t)Ll * Ff * Cc];

// ---------------- PTX helpers (sm_80-era; compiles for plain sm_103) ------
__device__ __forceinline__ uint32_t smem_u32(const void* p) {
    uint32_t a;
    asm("{ .reg .u64 t; cvta.to.shared.u64 t, %1; cvt.u32.u64 %0, t; }" : "=r"(a) : "l"(p));
    return a;
}
__device__ __forceinline__ void cp16(uint32_t s, const void* g) {
    asm volatile("cp.async.cg.shared.global [%0], [%1], 16;" :: "r"(s), "l"(g));
}
#define CP_COMMIT() asm volatile("cp.async.commit_group;" ::: "memory")
#define CP_WAIT(n)  asm volatile("cp.async.wait_group %0;" :: "n"(n) : "memory")

#define LDSM4(r, addr) \
    asm volatile("ldmatrix.sync.aligned.m8n8.x4.shared.b16 {%0,%1,%2,%3}, [%4];" \
        : "=r"((r)[0]), "=r"((r)[1]), "=r"((r)[2]), "=r"((r)[3]) : "r"(addr))

#define MMA16816(c, a, b) \
    asm volatile("mma.sync.aligned.m16n8k16.row.col.f32.f16.f16.f32 " \
        "{%0,%1,%2,%3}, {%4,%5,%6,%7}, {%8,%9}, {%0,%1,%2,%3};" \
        : "+f"((c)[0]), "+f"((c)[1]), "+f"((c)[2]), "+f"((c)[3]) \
        : "r"((a)[0]), "r"((a)[1]), "r"((a)[2]), "r"((a)[3]), \
          "r"((b)[0]), "r"((b)[1]))

// ---------------------------------------------------------------------------
// HMMA fp16 GEMM (R8 config): C[M,N] = A[M,K] * Bt[N,K]^T, fp32 accum.
// Block 128x128, 8 warps (4M x 2N), K-chunks of 64, 3-stage cp.async, occ 2.
// SMEM rows: 128B payload + 16B pad (stride 144) -> conflict-free LDSM.
// z offsets: (z/div)*shi + (z%div)*slo per operand.
// EPI: 1 fp16 rows | 2 fp32 += acc+bias | 4 relu(acc+bias)->fp16 rows
//      5 QKV: z<16 fp16 rows, z>=16 vT transposed (ld = Mr)
// ---------------------------------------------------------------------------
constexpr int STG   = 36864;            // 128 rows * 144 B * 2 matrices
constexpr int B_OFF = 18432;
constexpr int SM_MM = 3 * STG;          // 110592

template<int EPI>
__global__ void __launch_bounds__(256, 2)
gemm_mma(const __half* __restrict__ A, int lda,
         int aDiv, long long aShi, long long aSlo,
         const __half* __restrict__ B, int ldb,
         int bDiv, long long bShi, long long bSlo,
         float* __restrict__ Cm, int ldc,
         int cDiv, long long cShi, long long cSlo,
         const float* __restrict__ bias, int K)
{
    extern __shared__ char sm[];
    const uint32_t sb = smem_u32(sm);

    const int tid = threadIdx.x;
    const int lane = tid & 31;
    const int warp = tid >> 5;
    const int warpM = warp & 3;
    const int warpN = warp >> 2;

    const int z = blockIdx.z;
    A  += (long long)(z / aDiv) * aShi + (long long)(z % aDiv) * aSlo;
    B  += (long long)(z / bDiv) * bShi + (long long)(z % bDiv) * bSlo;
    const long long cOff = (long long)(z / cDiv) * cShi + (long long)(z % cDiv) * cSlo;

    const int rowBase = blockIdx.y * 128;
    const int colBase = blockIdx.x * 128;

    float acc[2][8][4];
#pragma unroll
    for (int i = 0; i < 2; i++)
#pragma unroll
        for (int j = 0; j < 8; j++)
#pragma unroll
            for (int q = 0; q < 4; q++) acc[i][j][q] = 0.f;

    const int nCh = K >> 6;              // K-chunks of 64
    const int ldr = tid >> 3;            // 0..31
    const int c16 = (tid & 7) * 16;      // byte col in 128B row

    auto load_chunk = [&](int i, int st) {
        const long long k0 = (long long)i * 64;
        const uint32_t sbase = sb + (uint32_t)st * STG;
#pragma unroll
        for (int g = 0; g < 4; g++) {
            const int rr = g * 32 + ldr;
            const uint32_t so = sbase + (uint32_t)(rr * 144 + c16);
            cp16(so,
                 (const char*)(A + (long long)(rowBase + rr) * lda + k0) + c16);
            cp16(so + B_OFF,
                 (const char*)(B + (long long)(colBase + rr) * ldb + k0) + c16);
        }
    };

    load_chunk(0, 0); CP_COMMIT();
    load_chunk(1, 1); CP_COMMIT();

    for (int i = 0; i < nCh; i++) {
        if (i + 1 < nCh) { CP_WAIT(1); } else { CP_WAIT(0); }
        __syncthreads();
        if (i + 2 < nCh) { load_chunk(i + 2, (i + 2) % 3); CP_COMMIT(); }

        const uint32_t sbase = sb + (uint32_t)(i % 3) * STG;
#pragma unroll
        for (int ks = 0; ks < 4; ks++) {
            uint32_t ah[2][4], bh[8][2];
#pragma unroll
            for (int tm = 0; tm < 2; tm++) {
                const int row = warpM * 32 + tm * 16 + (lane & 15);
                const uint32_t addr =
                    sbase + (uint32_t)(row * 144 + ((lane >> 4) << 4) + ks * 32);
                LDSM4(ah[tm], addr);
            }
#pragma unroll
            for (int gn = 0; gn < 4; gn++) {
                const int n = warpN * 64 + gn * 16 + ((lane >> 4) & 1) * 8 + (lane & 7);
                const uint32_t addr =
                    sbase + (uint32_t)B_OFF +
                    (uint32_t)(n * 144 + ((lane >> 3) & 1) * 16 + ks * 32);
                uint32_t r0[4];
                LDSM4(r0, addr);
                bh[gn * 2][0] = r0[0]; bh[gn * 2][1] = r0[1];
                bh[gn * 2 + 1][0] = r0[2]; bh[gn * 2 + 1][1] = r0[3];
            }
#pragma unroll
            for (int tm = 0; tm < 2; tm++) {
#pragma unroll
                for (int tn = 0; tn < 8; tn++) {
                    MMA16816(acc[tm][tn], ah[tm], bh[tn]);
                }
            }
        }
    }

    // ---- epilogue from registers ----
    const int rB = rowBase + warpM * 32;
    const int cB = colBase + warpN * 64;
    const int lr = lane >> 2;
    const int lc = (lane & 3) * 2;
#pragma unroll
    for (int tm = 0; tm < 2; tm++) {
#pragma unroll
        for (int tn = 0; tn < 8; tn++) {
            const int row0 = rB + tm * 16 + lr;
            const int col  = cB + tn * 8 + lc;
            const float* a = acc[tm][tn];
            if (EPI == 2) {
                const float b0 = bias[col], b1 = bias[col + 1];
                float* p0 = Cm + cOff + (long long)row0 * ldc + col;
                float* p1 = Cm + cOff + (long long)(row0 + 8) * ldc + col;
                p0[0] += a[0] + b0;  p0[1] += a[1] + b1;
                p1[0] += a[2] + b0;  p1[1] += a[3] + b1;
            } else if (EPI == 5 && z >= 16) {
                // v: store transposed vT[col, row], ld = Mr
                __half* base = (__half*)Cm + cOff;
#pragma unroll
                for (int half_ = 0; half_ < 2; half_++) {
                    const int row = row0 + half_ * 8;
                    base[(long long)col * Mr + row] =
                        __float2half_rn(a[half_ * 2 + 0]);
                    base[(long long)(col + 1) * Mr + row] =
                        __float2half_rn(a[half_ * 2 + 1]);
                }
            } else if (EPI == 4) {
                const float b0 = bias[col], b1 = bias[col + 1];
                __half* ph = (__half*)Cm + cOff;
#pragma unroll
                for (int half_ = 0; half_ < 2; half_++) {
                    float t0 = a[half_ * 2 + 0] + b0;
                    float t1 = a[half_ * 2 + 1] + b1;
                    t0 = t0 > 0.f ? t0 : 0.f;
                    t1 = t1 > 0.f ? t1 : 0.f;
                    *(__half2*)(ph + (long long)(row0 + half_ * 8) * ldc + col) =
                        __halves2half2(__float2half_rn(t0), __float2half_rn(t1));
                }
            } else {  // EPI 1 or 5(q,k): fp16 row store
                __half* ph = (__half*)Cm + cOff;
#pragma unroll
                for (int half_ = 0; half_ < 2; half_++) {
                    *(__half2*)(ph + (long long)(row0 + half_ * 8) * ldc + col) =
                        __halves2half2(__float2half_rn(a[half_ * 2 + 0]),
                                       __float2half_rn(a[half_ * 2 + 1]));
                }
            }
        }
    }
}

// ---------------------------------------------------------------------------
// Merged QKV weight transpose: z in [0,96): s=z/32 picks Wq/Wk/Wv, zz=z%32
// is l*8+h. W[zz][K=C rows, N=D cols] fp32 -> out[l][s][h][N=D rows, K=C].
// ---------------------------------------------------------------------------
__global__ void __launch_bounds__(256)
transpose_qkv(const float* __restrict__ Wq, const float* __restrict__ Wk,
              const float* __restrict__ Wv, __half* __restrict__ outw)
{
    const long long DK  = (long long)Dd * Cc;
    const long long HDK = Hh * DK;
    const int z = blockIdx.z;
    const int s = z >> 5;          // 0,1,2
    const int zz = z & 31;         // l*8+h
    const float* W = (s == 0 ? Wq : s == 1 ? Wk : Wv) + (long long)zz * DK;
    const int l = zz >> 3, hd = zz & 7;
    __half* outp = outw + (long long)l * 3 * HDK + (long long)s * HDK + (long long)hd * DK;

    __shared__ float t[32][33];
    const int tx = threadIdx.x & 31, ty = threadIdx.x >> 5;
    const int n0 = blockIdx.x * 32, k0 = blockIdx.y * 32;
#pragma unroll
    for (int i = 0; i < 4; i++)
        t[ty + i * 8][tx] = W[(long long)(k0 + ty + i * 8) * Dd + n0 + tx];
    __syncthreads();
#pragma unroll
    for (int i = 0; i < 4; i++) {
        const float v = t[tx][ty + i * 8];
        outp[(long long)(n0 + ty + i * 8) * Cc + k0 + tx] = __float2half_rn(v);
    }
}

// ---------------------------------------------------------------------------
// Generic weight transpose + fp16 convert: W[z][K,N] fp32 -> [z][N,K] fp16
// ---------------------------------------------------------------------------
__global__ void __launch_bounds__(256)
transpose_h(const float* __restrict__ W, long long inSlo,
            __half* __restrict__ hi, long long outSlo, int K, int N)
{
    const int z = blockIdx.z;
    W += (long long)z * inSlo;
    const long long oOff = (long long)z * outSlo;
    __shared__ float t[32][33];
    const int tx = threadIdx.x & 31, ty = threadIdx.x >> 5;
    const int n0 = blockIdx.x * 32, k0 = blockIdx.y * 32;
#pragma unroll
    for (int i = 0; i < 4; i++)
        t[ty + i * 8][tx] = W[(long long)(k0 + ty + i * 8) * N + n0 + tx];
    __syncthreads();
#pragma unroll
    for (int i = 0; i < 4; i++) {
        const float v = t[tx][ty + i * 8];
        hi[oOff + (long long)(n0 + ty + i * 8) * K + k0 + tx] = __float2half_rn(v);
    }
}

// ---------------------------------------------------------------------------
// LayerNorm, rows of 1024.
// MODE 0: fp32 out (final, streaming store). MODE 1: fp16 out.
// MODE 2: input = x + pos (fused add_pos); writes h fp32 AND fp16 xn.
// ---------------------------------------------------------------------------
template<int MODE>
__global__ void __launch_bounds__(256)
ln_kernel(const float* __restrict__ x, const float* __restrict__ pos,
          float* __restrict__ y, __half* __restrict__ yh,
          const float* __restrict__ s, const float* __restrict__ b)
{
    __shared__ float red[256];
    const int tid = threadIdx.x;
    const long long row = blockIdx.x;

    float4 v = *(const float4*)(x + row * 1024 + tid * 4);
    if (MODE == 2) {
        const long long prow = row & (Ts - 1);
        float4 p = *(const float4*)(pos + prow * 1024 + tid * 4);
        v.x += p.x; v.y += p.y; v.z += p.z; v.w += p.w;
        *(float4*)(y + row * 1024 + tid * 4) = v;   // h = x + pos
    }
    red[tid] = v.x + v.y + v.z + v.w;
    __syncthreads();
    for (int o = 128; o > 0; o >>= 1) {
        if (tid < o) red[tid] += red[tid + o];
        __syncthreads();
    }
    const float mean = red[0] * (1.f / 1024.f);
    __syncthreads();

    float dx = v.x - mean, dy = v.y - mean, dz = v.z - mean, dw = v.w - mean;
    red[tid] = dx * dx + dy * dy + dz * dz + dw * dw;
    __syncthreads();
    for (int o = 128; o > 0; o >>= 1) {
        if (tid < o) red[tid] += red[tid + o];
        __syncthreads();
    }
    const float var = red[0] * (1.f / 1024.f);
    const float rs = rsqrtf(var + 1e-5f);

    const int c = tid * 4;
    float t0 = dx * rs * s[c + 0] + b[c + 0];
    float t1 = dy * rs * s[c + 1] + b[c + 1];
    float t2 = dz * rs * s[c + 2] + b[c + 2];
    float t3 = dw * rs * s[c + 3] + b[c + 3];
    if (MODE == 0) {
        float4 o4 = {t0, t1, t2, t3};
        __stcs((float4*)(y + row * 1024 + c), o4);   // final output, no reuse
    } else {
        __half* ph = yh + row * 1024 + c;
        *(__half2*)ph = __halves2half2(__float2half_rn(t0), __float2half_rn(t1));
        *(__half2*)(ph + 2) = __halves2half2(__float2half_rn(t2), __float2half_rn(t3));
    }
}

// ---------------------------------------------------------------------------
// Softmax over rows of 1024: reads fp16 logits, writes fp32 atts (output,
// streaming store — never re-read) and fp16 probs in place of the logits.
// ---------------------------------------------------------------------------
__global__ void __launch_bounds__(256)
softmax_kernel(__half* __restrict__ logit, float* __restrict__ atts_out)
{
    __shared__ float red[256];
    const int tid = threadIdx.x;
    const long long row = blockIdx.x;
    __half* pr = logit + row * 1024;
    const float sc = 0.08838834764831845f;  // 1/sqrt(128)

    __half2 h01 = *(__half2*)(pr + tid * 4);
    __half2 h23 = *(__half2*)(pr + tid * 4 + 2);
    float v0 = __half2float(__low2half(h01)) * sc;
    float v1 = __half2float(__high2half(h01)) * sc;
    float v2 = __half2float(__low2half(h23)) * sc;
    float v3 = __half2float(__high2half(h23)) * sc;

    float mx = fmaxf(fmaxf(v0, v1), fmaxf(v2, v3));
    red[tid] = mx;
    __syncthreads();
    for (int o = 128; o > 0; o >>= 1) {
        if (tid < o) red[tid] = fmaxf(red[tid], red[tid + o]);
        __syncthreads();
    }
    const float m = red[0];
    __syncthreads();

    v0 = __expf(v0 - m); v1 = __expf(v1 - m);
    v2 = __expf(v2 - m); v3 = __expf(v3 - m);
    red[tid] = v0 + v1 + v2 + v3;
    __syncthreads();
    for (int o = 128; o > 0; o >>= 1) {
        if (tid < o) red[tid] += red[tid + o];
        __syncthreads();
    }
    const float inv = 1.f / red[0];
    v0 *= inv; v1 *= inv; v2 *= inv; v3 *= inv;

    float4 o4 = {v0, v1, v2, v3};
    __stcs((float4*)(atts_out + row * 1024 + tid * 4), o4);
    *(__half2*)(pr + tid * 4) =
        __halves2half2(__float2half_rn(v0), __float2half_rn(v1));
    *(__half2*)(pr + tid * 4 + 2) =
        __halves2half2(__float2half_rn(v2), __float2half_rn(v3));
}

// ---------------------------------------------------------------------------
extern "C" void kernel_launch(void* const* d_in, const int* in_sizes, int n_in,
                              void* d_out, int out_size)
{
    const float* x     = (const float*)d_in[0];
    const float* pos   = (const float*)d_in[1];
    const float* Wq    = (const float*)d_in[2];
    const float* Wk    = (const float*)d_in[3];
    const float* Wv    = (const float*)d_in[4];
    const float* Wo    = (const float*)d_in[5];
    const float* bo    = (const float*)d_in[6];
    const float* ln1_s = (const float*)d_in[7];
    const float* ln1_b = (const float*)d_in[8];
    const float* ln2_s = (const float*)d_in[9];
    const float* ln2_b = (const float*)d_in[10];
    const float* W1    = (const float*)d_in[11];
    const float* b1    = (const float*)d_in[12];
    const float* W2    = (const float*)d_in[13];
    const float* b2    = (const float*)d_in[14];
    const float* lnf_s = (const float*)d_in[15];
    const float* lnf_b = (const float*)d_in[16];

    float* out  = (float*)d_out;
    float* outx = out;
    float* atts = out + (long long)Mr * Cc;

    float* h;
    __half *qkv, *xn, *o, *u, *att, *wqkv_h, *wo_h, *w1_h, *w2_h;
    cudaGetSymbolAddress((void**)&h,      g_h);
    cudaGetSymbolAddress((void**)&qkv,    g_qkv);
    cudaGetSymbolAddress((void**)&xn,     g_xn);
    cudaGetSymbolAddress((void**)&o,      g_o);
    cudaGetSymbolAddress((void**)&u,      g_u);
    cudaGetSymbolAddress((void**)&att,    g_att);
    cudaGetSymbolAddress((void**)&wqkv_h, g_wqkv_h);
    cudaGetSymbolAddress((void**)&wo_h,   g_wo_h);
    cudaGetSymbolAddress((void**)&w1_h,   g_w1_h);
    cudaGetSymbolAddress((void**)&w2_h,   g_w2_h);

    cudaFuncSetAttribute(gemm_mma<1>, cudaFuncAttributeMaxDynamicSharedMemorySize, SM_MM);
    cudaFuncSetAttribute(gemm_mma<2>, cudaFuncAttributeMaxDynamicSharedMemorySize, SM_MM);
    cudaFuncSetAttribute(gemm_mma<4>, cudaFuncAttributeMaxDynamicSharedMemorySize, SM_MM);
    cudaFuncSetAttribute(gemm_mma<5>, cudaFuncAttributeMaxDynamicSharedMemorySize, SM_MM);

    const long long DK   = (long long)Dd * Cc;       // 131072
    const long long HDK  = Hh * DK;
    const long long HMrD = (long long)Hh * Mr * Dd;
    const long long QZ   = (long long)Ts * Dd;
    const long long SZ   = (long long)Ts * Ts;
    const long long HBTT = (long long)Hh * Bb * Ts * Ts;

    // Merged QKV weight transpose (one launch, 96 z-blocks)
    transpose_qkv<<<dim3(Dd / 32, Cc / 32, 96), 256>>>(Wq, Wk, Wv, wqkv_h);

    for (int l = 0; l < Ll; l++) {
        float* atts_l = atts + (long long)l * HBTT;

        // LN1 (l==0 fuses add_pos: writes h = x+pos and xn)
        if (l == 0)
            ln_kernel<2><<<Mr, 256>>>(x, pos, h, xn, ln1_s, ln1_b);
        else
            ln_kernel<1><<<Mr, 256>>>(h, nullptr, nullptr, xn,
                                      ln1_s + l * Cc, ln1_b + l * Cc);

        // QKV: z = s*8+h (24). q,k: fp16 rows; v: vT (ld=Mr).
        gemm_mma<5><<<dim3(1, 32, 24), 256, SM_MM>>>(
            xn, Cc, 1, 0, 0,
            wqkv_h + (long long)l * 3 * HDK, Cc, 1, DK, 0,
            (float*)qkv, Dd, 1, (long long)Mr * Dd, 0,
            nullptr, Cc);

        if (l == 0) {
            // remaining weight transposes (before first use)
            transpose_h<<<dim3(Cc / 32, Cc / 32, Ll), 256>>>(
                Wo, (long long)Cc * Cc, wo_h, (long long)Cc * Cc, Cc, Cc);
            transpose_h<<<dim3(Ff / 32, Cc / 32, Ll), 256>>>(
                W1, (long long)Cc * Ff, w1_h, (long long)Ff * Cc, Cc, Ff);
            transpose_h<<<dim3(Cc / 32, Ff / 32, Ll), 256>>>(
                W2, (long long)Ff * Cc, w2_h, (long long)Cc * Ff, Ff, Cc);
        }

        // scores = q k^T -> fp16 logits in g_att; z = h*Bb + b
        gemm_mma<1><<<dim3(8, 8, 32), 256, SM_MM>>>(
            qkv, Dd, Bb, (long long)Mr * Dd, QZ,
            qkv + HMrD, Dd, Bb, (long long)Mr * Dd, QZ,
            (float*)att, Ts, 1, SZ, 0,
            nullptr, Dd);

        // softmax: fp16 logits -> fp32 atts (streaming) + fp16 probs in place
        softmax_kernel<<<Hh * Bb * Ts, 256>>>(att, atts_l);

        // o = att @ vT -> fp16 concat [B*T, C]
        gemm_mma<1><<<dim3(1, 8, 32), 256, SM_MM>>>(
            att, Ts, 1, SZ, 0,
            qkv + 2 * HMrD, Mr, Bb, (long long)Mr * Dd, Ts,
            (float*)o, Cc, Bb, 128, (long long)Ts * Cc,
            nullptr, Ts);

        // proj: h += o @ Wo + bo
        gemm_mma<2><<<dim3(8, 32, 1), 256, SM_MM>>>(
            o, Cc, 1, 0, 0,
            wo_h + (long long)l * Cc * Cc, Cc, 1, 0, 0,
            h, Cc, 1, 0, 0,
            bo + l * Cc, Cc);

        // LN2 -> xn fp16
        ln_kernel<1><<<Mr, 256>>>(h, nullptr, nullptr, xn,
                                  ln2_s + l * Cc, ln2_b + l * Cc);

        // FFN1: u = relu(xn @ W1 + b1) -> fp16
        gemm_mma<4><<<dim3(32, 32, 1), 256, SM_MM>>>(
            xn, Cc, 1, 0, 0,
            w1_h + (long long)l * Cc * Ff, Cc, 1, 0, 0,
            (float*)u, Ff, 1, 0, 0,
            b1 + l * Ff, Cc);

        // FFN2: h += u @ W2 + b2
        gemm_mma<2><<<dim3(8, 32, 1), 256, SM_MM>>>(
            u, Ff, 1, 0, 0,
            w2_h + (long long)l * Ff * Cc, Ff, 1, 0, 0,
            h, Cc, 1, 0, 0,
            b2 + l * Cc, Ff);
    }

    // final LN -> fp32 output (streaming store)
    ln_kernel<0><<<Mr, 256>>>(h, nullptr, outx, nullptr, lnf_s, lnf_b);
}

// round 11
// speedup vs baseline: 1.1543x; 1.0332x over previous
#include <cuda_runtime.h>
#include <cuda_fp16.h>
#include <cstdint>

// Problem constants
constexpr int Bb = 4, Ts = 1024, Cc = 1024, Hh = 8, Dd = 128, Ff = 4096, Ll = 4;
constexpr int Mr = Bb * Ts;  // 4096

// ---------------- scratch (device globals; allocation-free rule) ----------
__device__ float  g_h[(size_t)Mr * Cc];                    // residual fp32
__device__ __half g_qkv[(size_t)3 * Hh * Mr * Dd];         // q,k rows; vT cols
__device__ __half g_xn[(size_t)Mr * Cc];                   // LN out fp16
__device__ __half g_o[(size_t)Mr * Cc];                    // attn out fp16
__device__ __half g_u[(size_t)Mr * Ff];                    // FFN hidden fp16
__device__ __half g_wqkv_h[(size_t)Ll * 3 * Hh * Dd * Cc]; // fp16 weights [N,K]
__device__ __half g_wo_h[(size_t)Ll * Cc * Cc];
__device__ __half g_w1_h[(size_t)Ll * Cc * Ff];
__device__ __half g_w2_h[(size_t)Ll * Ff * Cc];

// ---------------- PTX helpers (sm_80-era; compiles for plain sm_103) ------
__device__ __forceinline__ uint32_t smem_u32(const void* p) {
    uint32_t a;
    asm("{ .reg .u64 t; cvta.to.shared.u64 t, %1; cvt.u32.u64 %0, t; }" : "=r"(a) : "l"(p));
    return a;
}
__device__ __forceinline__ void cp16(uint32_t s, const void* g) {
    asm volatile("cp.async.cg.shared.global [%0], [%1], 16;" :: "r"(s), "l"(g));
}
#define CP_COMMIT() asm volatile("cp.async.commit_group;" ::: "memory")
#define CP_WAIT(n)  asm volatile("cp.async.wait_group %0;" :: "n"(n) : "memory")

#define LDSM4(r, addr) \
    asm volatile("ldmatrix.sync.aligned.m8n8.x4.shared.b16 {%0,%1,%2,%3}, [%4];" \
        : "=r"((r)[0]), "=r"((r)[1]), "=r"((r)[2]), "=r"((r)[3]) : "r"(addr))

#define MMA16816(c, a, b) \
    asm volatile("mma.sync.aligned.m16n8k16.row.col.f32.f16.f16.f32 " \
        "{%0,%1,%2,%3}, {%4,%5,%6,%7}, {%8,%9}, {%0,%1,%2,%3};" \
        : "+f"((c)[0]), "+f"((c)[1]), "+f"((c)[2]), "+f"((c)[3]) \
        : "r"((a)[0]), "r"((a)[1]), "r"((a)[2]), "r"((a)[3]), \
          "r"((b)[0]), "r"((b)[1]))

// ---------------------------------------------------------------------------
// HMMA fp16 GEMM (R8 config): C[M,N] = A[M,K] * Bt[N,K]^T, fp32 accum.
// Block 128x128, 8 warps (4M x 2N), K-chunks of 64, 3-stage cp.async, occ 2.
// EPI: 2 fp32 += acc+bias | 4 relu(acc+bias)->fp16 rows
//      5 QKV: z<16 fp16 rows, z>=16 vT transposed (ld = Mr)
// ---------------------------------------------------------------------------
constexpr int STG   = 36864;            // 128 rows * 144 B * 2 matrices
constexpr int B_OFF = 18432;
constexpr int SM_MM = 3 * STG;          // 110592

template<int EPI>
__global__ void __launch_bounds__(256, 2)
gemm_mma(const __half* __restrict__ A, int lda,
         int aDiv, long long aShi, long long aSlo,
         const __half* __restrict__ B, int ldb,
         int bDiv, long long bShi, long long bSlo,
         float* __restrict__ Cm, int ldc,
         int cDiv, long long cShi, long long cSlo,
         const float* __restrict__ bias, int K)
{
    extern __shared__ char sm[];
    const uint32_t sb = smem_u32(sm);

    const int tid = threadIdx.x;
    const int lane = tid & 31;
    const int warp = tid >> 5;
    const int warpM = warp & 3;
    const int warpN = warp >> 2;

    const int z = blockIdx.z;
    A  += (long long)(z / aDiv) * aShi + (long long)(z % aDiv) * aSlo;
    B  += (long long)(z / bDiv) * bShi + (long long)(z % bDiv) * bSlo;
    const long long cOff = (long long)(z / cDiv) * cShi + (long long)(z % cDiv) * cSlo;

    const int rowBase = blockIdx.y * 128;
    const int colBase = blockIdx.x * 128;

    float acc[2][8][4];
#pragma unroll
    for (int i = 0; i < 2; i++)
#pragma unroll
        for (int j = 0; j < 8; j++)
#pragma unroll
            for (int q = 0; q < 4; q++) acc[i][j][q] = 0.f;

    const int nCh = K >> 6;
    const int ldr = tid >> 3;            // 0..31
    const int c16 = (tid & 7) * 16;      // byte col in 128B row

    auto load_chunk = [&](int i, int st) {
        const long long k0 = (long long)i * 64;
        const uint32_t sbase = sb + (uint32_t)st * STG;
#pragma unroll
        for (int g = 0; g < 4; g++) {
            const int rr = g * 32 + ldr;
            const uint32_t so = sbase + (uint32_t)(rr * 144 + c16);
            cp16(so,
                 (const char*)(A + (long long)(rowBase + rr) * lda + k0) + c16);
            cp16(so + B_OFF,
                 (const char*)(B + (long long)(colBase + rr) * ldb + k0) + c16);
        }
    };

    load_chunk(0, 0); CP_COMMIT();
    load_chunk(1, 1); CP_COMMIT();

    for (int i = 0; i < nCh; i++) {
        if (i + 1 < nCh) { CP_WAIT(1); } else { CP_WAIT(0); }
        __syncthreads();
        if (i + 2 < nCh) { load_chunk(i + 2, (i + 2) % 3); CP_COMMIT(); }

        const uint32_t sbase = sb + (uint32_t)(i % 3) * STG;
#pragma unroll
        for (int ks = 0; ks < 4; ks++) {
            uint32_t ah[2][4], bh[8][2];
#pragma unroll
            for (int tm = 0; tm < 2; tm++) {
                const int row = warpM * 32 + tm * 16 + (lane & 15);
                const uint32_t addr =
                    sbase + (uint32_t)(row * 144 + ((lane >> 4) << 4) + ks * 32);
                LDSM4(ah[tm], addr);
            }
#pragma unroll
            for (int gn = 0; gn < 4; gn++) {
                const int n = warpN * 64 + gn * 16 + ((lane >> 4) & 1) * 8 + (lane & 7);
                const uint32_t addr =
                    sbase + (uint32_t)B_OFF +
                    (uint32_t)(n * 144 + ((lane >> 3) & 1) * 16 + ks * 32);
                uint32_t r0[4];
                LDSM4(r0, addr);
                bh[gn * 2][0] = r0[0]; bh[gn * 2][1] = r0[1];
                bh[gn * 2 + 1][0] = r0[2]; bh[gn * 2 + 1][1] = r0[3];
            }
#pragma unroll
            for (int tm = 0; tm < 2; tm++) {
#pragma unroll
                for (int tn = 0; tn < 8; tn++) {
                    MMA16816(acc[tm][tn], ah[tm], bh[tn]);
                }
            }
        }
    }

    // ---- epilogue from registers ----
    const int rB = rowBase + warpM * 32;
    const int cB = colBase + warpN * 64;
    const int lr = lane >> 2;
    const int lc = (lane & 3) * 2;
#pragma unroll
    for (int tm = 0; tm < 2; tm++) {
#pragma unroll
        for (int tn = 0; tn < 8; tn++) {
            const int row0 = rB + tm * 16 + lr;
            const int col  = cB + tn * 8 + lc;
            const float* a = acc[tm][tn];
            if (EPI == 2) {
                const float b0 = bias[col], b1 = bias[col + 1];
                float* p0 = Cm + cOff + (long long)row0 * ldc + col;
                float* p1 = Cm + cOff + (long long)(row0 + 8) * ldc + col;
                p0[0] += a[0] + b0;  p0[1] += a[1] + b1;
                p1[0] += a[2] + b0;  p1[1] += a[3] + b1;
            } else if (EPI == 5 && z >= 16) {
                __half* base = (__half*)Cm + cOff;
#pragma unroll
                for (int half_ = 0; half_ < 2; half_++) {
                    const int row = row0 + half_ * 8;
                    base[(long long)col * Mr + row] =
                        __float2half_rn(a[half_ * 2 + 0]);
                    base[(long long)(col + 1) * Mr + row] =
                        __float2half_rn(a[half_ * 2 + 1]);
                }
            } else if (EPI == 4) {
                const float b0 = bias[col], b1 = bias[col + 1];
                __half* ph = (__half*)Cm + cOff;
#pragma unroll
                for (int half_ = 0; half_ < 2; half_++) {
                    float t0 = a[half_ * 2 + 0] + b0;
                    float t1 = a[half_ * 2 + 1] + b1;
                    t0 = t0 > 0.f ? t0 : 0.f;
                    t1 = t1 > 0.f ? t1 : 0.f;
                    *(__half2*)(ph + (long long)(row0 + half_ * 8) * ldc + col) =
                        __halves2half2(__float2half_rn(t0), __float2half_rn(t1));
                }
            } else {  // EPI 5 (q,k): fp16 row store
                __half* ph = (__half*)Cm + cOff;
#pragma unroll
                for (int half_ = 0; half_ < 2; half_++) {
                    *(__half2*)(ph + (long long)(row0 + half_ * 8) * ldc + col) =
                        __halves2half2(__float2half_rn(a[half_ * 2 + 0]),
                                       __float2half_rn(a[half_ * 2 + 1]));
                }
            }
        }
    }
}

// ---------------------------------------------------------------------------
// Fused attention: per block = (h, b, 64 q-rows).
// Phase 1: S[64,1024] = q·k^T (fp16 scores -> smem, 8 k-tiles, 2-stage).
// Softmax in smem (fp32 math): writes fp32 atts (streaming) + fp16 probs.
// Phase 2: O[64,128] = P·vT (3-stage vT pipeline), fp16 concat store.
// smem: probs 64x2064 | q 64x272 | k/v region 69632 B.  Total 219136 B.
// ---------------------------------------------------------------------------
constexpr int PR_STRIDE = 2064;                  // 2048 + 16 pad
constexpr int Q_OFF  = 64 * PR_STRIDE;           // 132096
constexpr int KV_OFF = Q_OFF + 64 * 272;         // 149504
constexpr int SM_ATT = KV_OFF + 2 * 34816;       // 219136

__global__ void __launch_bounds__(256, 1)
fused_attn(const __half* __restrict__ qkv, float* __restrict__ atts_l,
           __half* __restrict__ o)
{
    extern __shared__ char sm[];
    const uint32_t sb = smem_u32(sm);

    const int tid = threadIdx.x;
    const int lane = tid & 31;
    const int warp = tid >> 5;
    const int warpM = warp & 1;      // 2 M-warps (32 rows)
    const int warpN = warp >> 1;     // 4 N-warps (32 cols)

    const int qt = blockIdx.x;       // q tile (64 rows): 0..15
    const int hb = blockIdx.y;       // h*Bb + b: 0..31
    const int hh = hb >> 2, bb = hb & 3;

    const long long MrD = (long long)Mr * Dd;
    const __half* qbase = qkv + hh * MrD + (long long)(bb * Ts + qt * 64) * Dd;
    const __half* kbase = qkv + (long long)Hh * MrD + hh * MrD + (long long)(bb * Ts) * Dd;
    const __half* vbase = qkv + 2ll * Hh * MrD + hh * MrD + (long long)(bb * Ts);

    const uint32_t qs = sb + Q_OFF;
    const uint32_t kv = sb + KV_OFF;

    // ---- load q tile (64 rows x 256 B) ----
    {
        const int r = tid >> 2;
        const int c = (tid & 3) * 16;
#pragma unroll
        for (int g = 0; g < 4; g++)
            cp16(qs + (uint32_t)(r * 272 + c + g * 64),
                 (const char*)(qbase + (long long)r * Dd) + c + g * 64);
    }
    CP_COMMIT();

    auto load_k = [&](int kt, int st) {
        const int r = tid >> 1;
        const int c = (tid & 1) * 16;
        const char* src = (const char*)(kbase + (long long)(kt * 128 + r) * Dd);
        const uint32_t dst = kv + (uint32_t)st * 34816 + (uint32_t)(r * 272);
#pragma unroll
        for (int g = 0; g < 8; g++)
            cp16(dst + c + g * 32, src + c + g * 32);
    };
    auto load_v = [&](int kc, int st) {
        const int r = tid >> 1;
        const int c = (tid & 1) * 16;
        const char* src = (const char*)(vbase + (long long)r * Mr + kc * 64);
        const uint32_t dst = kv + (uint32_t)st * 18432 + (uint32_t)(r * 144);
#pragma unroll
        for (int g = 0; g < 4; g++)
            cp16(dst + c + g * 32, src + c + g * 32);
    };

    const int lr = lane >> 2;
    const int lc = (lane & 3) * 2;

    // ================= phase 1: scores =================
    load_k(0, 0); CP_COMMIT();
    for (int kt = 0; kt < 8; kt++) {
        CP_WAIT(0);
        __syncthreads();
        if (kt + 1 < 8) { load_k(kt + 1, (kt + 1) & 1); CP_COMMIT(); }

        const uint32_t kbuf = kv + (uint32_t)(kt & 1) * 34816;
        float acc[2][4][4];
#pragma unroll
        for (int i = 0; i < 2; i++)
#pragma unroll
            for (int j = 0; j < 4; j++)
#pragma unroll
                for (int q = 0; q < 4; q++) acc[i][j][q] = 0.f;

#pragma unroll
        for (int ks = 0; ks < 8; ks++) {
            uint32_t ah[2][4], bh[4][2];
#pragma unroll
            for (int tm = 0; tm < 2; tm++) {
                const int row = warpM * 32 + tm * 16 + (lane & 15);
                LDSM4(ah[tm], qs + (uint32_t)(row * 272 + ((lane >> 4) << 4) + ks * 32));
            }
#pragma unroll
            for (int gn = 0; gn < 2; gn++) {
                const int n = warpN * 32 + gn * 16 + ((lane >> 4) & 1) * 8 + (lane & 7);
                uint32_t r0[4];
                LDSM4(r0, kbuf + (uint32_t)(n * 272 + ((lane >> 3) & 1) * 16 + ks * 32));
                bh[gn * 2][0] = r0[0]; bh[gn * 2][1] = r0[1];
                bh[gn * 2 + 1][0] = r0[2]; bh[gn * 2 + 1][1] = r0[3];
            }
#pragma unroll
            for (int tm = 0; tm < 2; tm++)
#pragma unroll
                for (int tn = 0; tn < 4; tn++)
                    MMA16816(acc[tm][tn], ah[tm], bh[tn]);
        }

        // store fp16 scores into probs smem
#pragma unroll
        for (int tm = 0; tm < 2; tm++) {
#pragma unroll
            for (int tn = 0; tn < 4; tn++) {
                const int row0 = warpM * 32 + tm * 16 + lr;
                const int col = kt * 128 + warpN * 32 + tn * 8 + lc;
                const float* a = acc[tm][tn];
#pragma unroll
                for (int half_ = 0; half_ < 2; half_++) {
                    *(__half2*)(sm + (row0 + half_ * 8) * PR_STRIDE + col * 2) =
                        __halves2half2(__float2half_rn(a[half_ * 2 + 0]),
                                       __float2half_rn(a[half_ * 2 + 1]));
                }
            }
        }
    }
    __syncthreads();   // all scores in smem

    // preload first two vT chunks (overlaps with softmax)
    load_v(0, 0); CP_COMMIT();
    load_v(1, 1); CP_COMMIT();

    // ================= softmax (warp per 8 rows) =================
    {
        const float sc = 0.08838834764831845f;  // 1/sqrt(128)
        for (int rr = 0; rr < 8; rr++) {
            const int row = warp * 8 + rr;
            __half2* prow = (__half2*)(sm + row * PR_STRIDE);
            float v[32];
            float mx = -1e30f;
#pragma unroll
            for (int i = 0; i < 16; i++) {
                const __half2 h2 = prow[i * 32 + lane];
                const float a = __half2float(__low2half(h2)) * sc;
                const float b = __half2float(__high2half(h2)) * sc;
                v[2 * i] = a; v[2 * i + 1] = b;
                mx = fmaxf(mx, fmaxf(a, b));
            }
#pragma unroll
            for (int off = 16; off; off >>= 1)
                mx = fmaxf(mx, __shfl_xor_sync(0xFFFFFFFFu, mx, off));
            float s = 0.f;
#pragma unroll
            for (int i = 0; i < 32; i++) { v[i] = __expf(v[i] - mx); s += v[i]; }
#pragma unroll
            for (int off = 16; off; off >>= 1)
                s += __shfl_xor_sync(0xFFFFFFFFu, s, off);
            const float inv = 1.f / s;

            float* arow = atts_l + ((long long)hb * Ts + qt * 64 + row) * 1024;
#pragma unroll
            for (int i = 0; i < 16; i++) {
                const float a = v[2 * i] * inv, b = v[2 * i + 1] * inv;
                prow[i * 32 + lane] =
                    __halves2half2(__float2half_rn(a), __float2half_rn(b));
                __stcs((float2*)(arow + (i * 32 + lane) * 2), make_float2(a, b));
            }
        }
    }
    __syncthreads();   // normalized probs visible to all warps

    // ================= phase 2: O = P @ vT =================
    float acc2[2][4][4];
#pragma unroll
    for (int i = 0; i < 2; i++)
#pragma unroll
        for (int j = 0; j < 4; j++)
#pragma unroll
            for (int q = 0; q < 4; q++) acc2[i][j][q] = 0.f;

    for (int kc = 0; kc < 16; kc++) {
        if (kc + 1 < 16) { CP_WAIT(1); } else { CP_WAIT(0); }
        __syncthreads();
        if (kc + 2 < 16) { load_v(kc + 2, (kc + 2) % 3); CP_COMMIT(); }

        const uint32_t vbuf = kv + (uint32_t)(kc % 3) * 18432;
#pragma unroll
        for (int ks = 0; ks < 4; ks++) {
            uint32_t ah[2][4], bh[4][2];
#pragma unroll
            for (int tm = 0; tm < 2; tm++) {
                const int row = warpM * 32 + tm * 16 + (lane & 15);
                LDSM4(ah[tm], sb + (uint32_t)(row * PR_STRIDE + kc * 128 +
                                              ((lane >> 4) << 4) + ks * 32));
            }
#pragma unroll
            for (int gn = 0; gn < 2; gn++) {
                const int n = warpN * 32 + gn * 16 + ((lane >> 4) & 1) * 8 + (lane & 7);
                uint32_t r0[4];
                LDSM4(r0, vbuf + (uint32_t)(n * 144 + ((lane >> 3) & 1) * 16 + ks * 32));
                bh[gn * 2][0] = r0[0]; bh[gn * 2][1] = r0[1];
                bh[gn * 2 + 1][0] = r0[2]; bh[gn * 2 + 1][1] = r0[3];
            }
#pragma unroll
            for (int tm = 0; tm < 2; tm++)
#pragma unroll
                for (int tn = 0; tn < 4; tn++)
                    MMA16816(acc2[tm][tn], ah[tm], bh[tn]);
        }
    }

    // epilogue: o fp16 concat layout [B*T, C]
#pragma unroll
    for (int tm = 0; tm < 2; tm++) {
#pragma unroll
        for (int tn = 0; tn < 4; tn++) {
            const int row0 = warpM * 32 + tm * 16 + lr;
            const int col = warpN * 32 + tn * 8 + lc;
            const float* a = acc2[tm][tn];
#pragma unroll
            for (int half_ = 0; half_ < 2; half_++) {
                const long long grow = (long long)(bb * Ts + qt * 64 + row0 + half_ * 8);
                *(__half2*)(o + grow * Cc + hh * 128 + col) =
                    __halves2half2(__float2half_rn(a[half_ * 2 + 0]),
                                   __float2half_rn(a[half_ * 2 + 1]));
            }
        }
    }
}

// ---------------------------------------------------------------------------
// Merged QKV weight transpose: z in [0,96): s=z/32 picks Wq/Wk/Wv, zz=z%32.
// ---------------------------------------------------------------------------
__global__ void __launch_bounds__(256)
transpose_qkv(const float* __restrict__ Wq, const float* __restrict__ Wk,
              const float* __restrict__ Wv, __half* __restrict__ outw)
{
    const long long DK  = (long long)Dd * Cc;
    const long long HDK = Hh * DK;
    const int z = blockIdx.z;
    const int s = z >> 5;
    const int zz = z & 31;
    const float* W = (s == 0 ? Wq : s == 1 ? Wk : Wv) + (long long)zz * DK;
    const int l = zz >> 3, hd = zz & 7;
    __half* outp = outw + (long long)l * 3 * HDK + (long long)s * HDK + (long long)hd * DK;

    __shared__ float t[32][33];
    const int tx = threadIdx.x & 31, ty = threadIdx.x >> 5;
    const int n0 = blockIdx.x * 32, k0 = blockIdx.y * 32;
#pragma unroll
    for (int i = 0; i < 4; i++)
        t[ty + i * 8][tx] = W[(long long)(k0 + ty + i * 8) * Dd + n0 + tx];
    __syncthreads();
#pragma unroll
    for (int i = 0; i < 4; i++) {
        const float v = t[tx][ty + i * 8];
        outp[(long long)(n0 + ty + i * 8) * Cc + k0 + tx] = __float2half_rn(v);
    }
}

// ---------------------------------------------------------------------------
__global__ void __launch_bounds__(256)
transpose_h(const float* __restrict__ W, long long inSlo,
            __half* __restrict__ hi, long long outSlo, int K, int N)
{
    const int z = blockIdx.z;
    W += (long long)z * inSlo;
    const long long oOff = (long long)z * outSlo;
    __shared__ float t[32][33];
    const int tx = threadIdx.x & 31, ty = threadIdx.x >> 5;
    const int n0 = blockIdx.x * 32, k0 = blockIdx.y * 32;
#pragma unroll
    for (int i = 0; i < 4; i++)
        t[ty + i * 8][tx] = W[(long long)(k0 + ty + i * 8) * N + n0 + tx];
    __syncthreads();
#pragma unroll
    for (int i = 0; i < 4; i++) {
        const float v = t[tx][ty + i * 8];
        hi[oOff + (long long)(n0 + ty + i * 8) * K + k0 + tx] = __float2half_rn(v);
    }
}

// ---------------------------------------------------------------------------
// LayerNorm. MODE 0: fp32 out (streaming). MODE 1: fp16 out.
// MODE 2: input = x + pos; writes h fp32 AND fp16 xn.
// ---------------------------------------------------------------------------
template<int MODE>
__global__ void __launch_bounds__(256)
ln_kernel(const float* __restrict__ x, const float* __restrict__ pos,
          float* __restrict__ y, __half* __restrict__ yh,
          const float* __restrict__ s, const float* __restrict__ b)
{
    __shared__ float red[256];
    const int tid = threadIdx.x;
    const long long row = blockIdx.x;

    float4 v = *(const float4*)(x + row * 1024 + tid * 4);
    if (MODE == 2) {
        const long long prow = row & (Ts - 1);
        float4 p = *(const float4*)(pos + prow * 1024 + tid * 4);
        v.x += p.x; v.y += p.y; v.z += p.z; v.w += p.w;
        *(float4*)(y + row * 1024 + tid * 4) = v;
    }
    red[tid] = v.x + v.y + v.z + v.w;
    __syncthreads();
    for (int o = 128; o > 0; o >>= 1) {
        if (tid < o) red[tid] += red[tid + o];
        __syncthreads();
    }
    const float mean = red[0] * (1.f / 1024.f);
    __syncthreads();

    float dx = v.x - mean, dy = v.y - mean, dz = v.z - mean, dw = v.w - mean;
    red[tid] = dx * dx + dy * dy + dz * dz + dw * dw;
    __syncthreads();
    for (int o = 128; o > 0; o >>= 1) {
        if (tid < o) red[tid] += red[tid + o];
        __syncthreads();
    }
    const float var = red[0] * (1.f / 1024.f);
    const float rs = rsqrtf(var + 1e-5f);

    const int c = tid * 4;
    float t0 = dx * rs * s[c + 0] + b[c + 0];
    float t1 = dy * rs * s[c + 1] + b[c + 1];
    float t2 = dz * rs * s[c + 2] + b[c + 2];
    float t3 = dw * rs * s[c + 3] + b[c + 3];
    if (MODE == 0) {
        float4 o4 = {t0, t1, t2, t3};
        __stcs((float4*)(y + row * 1024 + c), o4);
    } else {
        __half* ph = yh + row * 1024 + c;
        *(__half2*)ph = __halves2half2(__float2half_rn(t0), __float2half_rn(t1));
        *(__half2*)(ph + 2) = __halves2half2(__float2half_rn(t2), __float2half_rn(t3));
    }
}

// ---------------------------------------------------------------------------
extern "C" void kernel_launch(void* const* d_in, const int* in_sizes, int n_in,
                              void* d_out, int out_size)
{
    const float* x     = (const float*)d_in[0];
    const float* pos   = (const float*)d_in[1];
    const float* Wq    = (const float*)d_in[2];
    const float* Wk    = (const float*)d_in[3];
    const float* Wv    = (const float*)d_in[4];
    const float* Wo    = (const float*)d_in[5];
    const float* bo    = (const float*)d_in[6];
    const float* ln1_s = (const float*)d_in[7];
    const float* ln1_b = (const float*)d_in[8];
    const float* ln2_s = (const float*)d_in[9];
    const float* ln2_b = (const float*)d_in[10];
    const float* W1    = (const float*)d_in[11];
    const float* b1    = (const float*)d_in[12];
    const float* W2    = (const float*)d_in[13];
    const float* b2    = (const float*)d_in[14];
    const float* lnf_s = (const float*)d_in[15];
    const float* lnf_b = (const float*)d_in[16];

    float* out  = (float*)d_out;
    float* outx = out;
    float* atts = out + (long long)Mr * Cc;

    float* h;
    __half *qkv, *xn, *o, *u, *wqkv_h, *wo_h, *w1_h, *w2_h;
    cudaGetSymbolAddress((void**)&h,      g_h);
    cudaGetSymbolAddress((void**)&qkv,    g_qkv);
    cudaGetSymbolAddress((void**)&xn,     g_xn);
    cudaGetSymbolAddress((void**)&o,      g_o);
    cudaGetSymbolAddress((void**)&u,      g_u);
    cudaGetSymbolAddress((void**)&wqkv_h, g_wqkv_h);
    cudaGetSymbolAddress((void**)&wo_h,   g_wo_h);
    cudaGetSymbolAddress((void**)&w1_h,   g_w1_h);
    cudaGetSymbolAddress((void**)&w2_h,   g_w2_h);

    cudaFuncSetAttribute(gemm_mma<2>, cudaFuncAttributeMaxDynamicSharedMemorySize, SM_MM);
    cudaFuncSetAttribute(gemm_mma<4>, cudaFuncAttributeMaxDynamicSharedMemorySize, SM_MM);
    cudaFuncSetAttribute(gemm_mma<5>, cudaFuncAttributeMaxDynamicSharedMemorySize, SM_MM);
    cudaFuncSetAttribute(fused_attn,  cudaFuncAttributeMaxDynamicSharedMemorySize, SM_ATT);

    const long long DK   = (long long)Dd * Cc;       // 131072
    const long long HDK  = Hh * DK;
    const long long HBTT = (long long)Hh * Bb * Ts * Ts;

    // Merged QKV weight transpose (one launch, 96 z-blocks)
    transpose_qkv<<<dim3(Dd / 32, Cc / 32, 96), 256>>>(Wq, Wk, Wv, wqkv_h);

    for (int l = 0; l < Ll; l++) {
        float* atts_l = atts + (long long)l * HBTT;

        // LN1 (l==0 fuses add_pos)
        if (l == 0)
            ln_kernel<2><<<Mr, 256>>>(x, pos, h, xn, ln1_s, ln1_b);
        else
            ln_kernel<1><<<Mr, 256>>>(h, nullptr, nullptr, xn,
                                      ln1_s + l * Cc, ln1_b + l * Cc);

        // QKV: z = s*8+h (24). q,k: fp16 rows; v: vT (ld=Mr).
        gemm_mma<5><<<dim3(1, 32, 24), 256, SM_MM>>>(
            xn, Cc, 1, 0, 0,
            wqkv_h + (long long)l * 3 * HDK, Cc, 1, DK, 0,
            (float*)qkv, Dd, 1, (long long)Mr * Dd, 0,
            nullptr, Cc);

        if (l == 0) {
            transpose_h<<<dim3(Cc / 32, Cc / 32, Ll), 256>>>(
                Wo, (long long)Cc * Cc, wo_h, (long long)Cc * Cc, Cc, Cc);
            transpose_h<<<dim3(Ff / 32, Cc / 32, Ll), 256>>>(
                W1, (long long)Cc * Ff, w1_h, (long long)Ff * Cc, Cc, Ff);
            transpose_h<<<dim3(Cc / 32, Ff / 32, Ll), 256>>>(
                W2, (long long)Ff * Cc, w2_h, (long long)Cc * Ff, Ff, Cc);
        }

        // fused scores + softmax + att@V
        fused_attn<<<dim3(16, 32), 256, SM_ATT>>>(qkv, atts_l, o);

        // proj: h += o @ Wo + bo
        gemm_mma<2><<<dim3(8, 32, 1), 256, SM_MM>>>(
            o, Cc, 1, 0, 0,
            wo_h + (long long)l * Cc * Cc, Cc, 1, 0, 0,
            h, Cc, 1, 0, 0,
            bo + l * Cc, Cc);

        // LN2 -> xn fp16
        ln_kernel<1><<<Mr, 256>>>(h, nullptr, nullptr, xn,
                                  ln2_s + l * Cc, ln2_b + l * Cc);

        // FFN1: u = relu(xn @ W1 + b1) -> fp16
        gemm_mma<4><<<dim3(32, 32, 1), 256, SM_MM>>>(
            xn, Cc, 1, 0, 0,
            w1_h + (long long)l * Cc * Ff, Cc, 1, 0, 0,
            (float*)u, Ff, 1, 0, 0,
            b1 + l * Ff, Cc);

        // FFN2: h += u @ W2 + b2
        gemm_mma<2><<<dim3(8, 32, 1), 256, SM_MM>>>(
            u, Ff, 1, 0, 0,
            w2_h + (long long)l * Ff * Cc, Ff, 1, 0, 0,
            h, Cc, 1, 0, 0,
            b2 + l * Cc, Ff);
    }

    // final LN -> fp32 output (streaming store)
    ln_kernel<0><<<Mr, 256>>>(h, nullptr, outx, nullptr, lnf_s, lnf_b);
}

// round 12
// speedup vs baseline: 1.1634x; 1.0079x over previous
#include <cuda_runtime.h>
#include <cuda_fp16.h>
#include <cstdint>

// Problem constants
constexpr int Bb = 4, Ts = 1024, Cc = 1024, Hh = 8, Dd = 128, Ff = 4096, Ll = 4;
constexpr int Mr = Bb * Ts;  // 4096

// ---------------- scratch (device globals; allocation-free rule) ----------
__device__ float  g_h[(size_t)Mr * Cc];                    // residual fp32
__device__ __half g_qkv[(size_t)3 * Hh * Mr * Dd];         // q,k rows; vT cols
__device__ __half g_xn[(size_t)Mr * Cc];                   // LN out fp16
__device__ __half g_o[(size_t)Mr * Cc];                    // attn out fp16
__device__ __half g_u[(size_t)Mr * Ff];                    // FFN hidden fp16
__device__ __half g_wqkv_h[(size_t)Ll * 3 * Hh * Dd * Cc]; // fp16 weights [N,K]
__device__ __half g_wo_h[(size_t)Ll * Cc * Cc];
__device__ __half g_w1_h[(size_t)Ll * Cc * Ff];
__device__ __half g_w2_h[(size_t)Ll * Ff * Cc];

// ---------------- PTX helpers (sm_80-era; compiles for plain sm_103) ------
__device__ __forceinline__ uint32_t smem_u32(const void* p) {
    uint32_t a;
    asm("{ .reg .u64 t; cvta.to.shared.u64 t, %1; cvt.u32.u64 %0, t; }" : "=r"(a) : "l"(p));
    return a;
}
__device__ __forceinline__ void cp16(uint32_t s, const void* g) {
    asm volatile("cp.async.cg.shared.global [%0], [%1], 16;" :: "r"(s), "l"(g));
}
#define CP_COMMIT() asm volatile("cp.async.commit_group;" ::: "memory")
#define CP_WAIT(n)  asm volatile("cp.async.wait_group %0;" :: "n"(n) : "memory")

#define LDSM4(r, addr) \
    asm volatile("ldmatrix.sync.aligned.m8n8.x4.shared.b16 {%0,%1,%2,%3}, [%4];" \
        : "=r"((r)[0]), "=r"((r)[1]), "=r"((r)[2]), "=r"((r)[3]) : "r"(addr))

#define MMA16816(c, a, b) \
    asm volatile("mma.sync.aligned.m16n8k16.row.col.f32.f16.f16.f32 " \
        "{%0,%1,%2,%3}, {%4,%5,%6,%7}, {%8,%9}, {%0,%1,%2,%3};" \
        : "+f"((c)[0]), "+f"((c)[1]), "+f"((c)[2]), "+f"((c)[3]) \
        : "r"((a)[0]), "r"((a)[1]), "r"((a)[2]), "r"((a)[3]), \
          "r"((b)[0]), "r"((b)[1]))

// ---------------------------------------------------------------------------
// HMMA fp16 GEMM (R8 config): C[M,N] = A[M,K] * Bt[N,K]^T, fp32 accum.
// Block 128x128, 8 warps (4M x 2N), K-chunks of 64, 3-stage cp.async, occ 2.
// EPI: 2 fp32 += acc+bias | 4 relu(acc+bias)->fp16 rows
//      5 QKV: z<16 fp16 rows, z>=16 vT transposed (ld = Mr)
// ---------------------------------------------------------------------------
constexpr int STG   = 36864;            // 128 rows * 144 B * 2 matrices
constexpr int B_OFF = 18432;
constexpr int SM_MM = 3 * STG;          // 110592

template<int EPI>
__global__ void __launch_bounds__(256, 2)
gemm_mma(const __half* __restrict__ A, int lda,
         int aDiv, long long aShi, long long aSlo,
         const __half* __restrict__ B, int ldb,
         int bDiv, long long bShi, long long bSlo,
         float* __restrict__ Cm, int ldc,
         int cDiv, long long cShi, long long cSlo,
         const float* __restrict__ bias, int K)
{
    extern __shared__ char sm[];
    const uint32_t sb = smem_u32(sm);

    const int tid = threadIdx.x;
    const int lane = tid & 31;
    const int warp = tid >> 5;
    const int warpM = warp & 3;
    const int warpN = warp >> 2;

    const int z = blockIdx.z;
    A  += (long long)(z / aDiv) * aShi + (long long)(z % aDiv) * aSlo;
    B  += (long long)(z / bDiv) * bShi + (long long)(z % bDiv) * bSlo;
    const long long cOff = (long long)(z / cDiv) * cShi + (long long)(z % cDiv) * cSlo;

    const int rowBase = blockIdx.y * 128;
    const int colBase = blockIdx.x * 128;

    float acc[2][8][4];
#pragma unroll
    for (int i = 0; i < 2; i++)
#pragma unroll
        for (int j = 0; j < 8; j++)
#pragma unroll
            for (int q = 0; q < 4; q++) acc[i][j][q] = 0.f;

    const int nCh = K >> 6;
    const int ldr = tid >> 3;            // 0..31
    const int c16 = (tid & 7) * 16;      // byte col in 128B row

    auto load_chunk = [&](int i, int st) {
        const long long k0 = (long long)i * 64;
        const uint32_t sbase = sb + (uint32_t)st * STG;
#pragma unroll
        for (int g = 0; g < 4; g++) {
            const int rr = g * 32 + ldr;
            const uint32_t so = sbase + (uint32_t)(rr * 144 + c16);
            cp16(so,
                 (const char*)(A + (long long)(rowBase + rr) * lda + k0) + c16);
            cp16(so + B_OFF,
                 (const char*)(B + (long long)(colBase + rr) * ldb + k0) + c16);
        }
    };

    load_chunk(0, 0); CP_COMMIT();
    load_chunk(1, 1); CP_COMMIT();

    for (int i = 0; i < nCh; i++) {
        if (i + 1 < nCh) { CP_WAIT(1); } else { CP_WAIT(0); }
        __syncthreads();
        if (i + 2 < nCh) { load_chunk(i + 2, (i + 2) % 3); CP_COMMIT(); }

        const uint32_t sbase = sb + (uint32_t)(i % 3) * STG;
#pragma unroll
        for (int ks = 0; ks < 4; ks++) {
            uint32_t ah[2][4], bh[8][2];
#pragma unroll
            for (int tm = 0; tm < 2; tm++) {
                const int row = warpM * 32 + tm * 16 + (lane & 15);
                const uint32_t addr =
                    sbase + (uint32_t)(row * 144 + ((lane >> 4) << 4) + ks * 32);
                LDSM4(ah[tm], addr);
            }
#pragma unroll
            for (int gn = 0; gn < 4; gn++) {
                const int n = warpN * 64 + gn * 16 + ((lane >> 4) & 1) * 8 + (lane & 7);
                const uint32_t addr =
                    sbase + (uint32_t)B_OFF +
                    (uint32_t)(n * 144 + ((lane >> 3) & 1) * 16 + ks * 32);
                uint32_t r0[4];
                LDSM4(r0, addr);
                bh[gn * 2][0] = r0[0]; bh[gn * 2][1] = r0[1];
                bh[gn * 2 + 1][0] = r0[2]; bh[gn * 2 + 1][1] = r0[3];
            }
#pragma unroll
            for (int tm = 0; tm < 2; tm++) {
#pragma unroll
                for (int tn = 0; tn < 8; tn++) {
                    MMA16816(acc[tm][tn], ah[tm], bh[tn]);
                }
            }
        }
    }

    // ---- epilogue from registers ----
    const int rB = rowBase + warpM * 32;
    const int cB = colBase + warpN * 64;
    const int lr = lane >> 2;
    const int lc = (lane & 3) * 2;
#pragma unroll
    for (int tm = 0; tm < 2; tm++) {
#pragma unroll
        for (int tn = 0; tn < 8; tn++) {
            const int row0 = rB + tm * 16 + lr;
            const int col  = cB + tn * 8 + lc;
            const float* a = acc[tm][tn];
            if (EPI == 2) {
                const float b0 = bias[col], b1 = bias[col + 1];
                float* p0 = Cm + cOff + (long long)row0 * ldc + col;
                float* p1 = Cm + cOff + (long long)(row0 + 8) * ldc + col;
                p0[0] += a[0] + b0;  p0[1] += a[1] + b1;
                p1[0] += a[2] + b0;  p1[1] += a[3] + b1;
            } else if (EPI == 5 && z >= 16) {
                __half* base = (__half*)Cm + cOff;
#pragma unroll
                for (int half_ = 0; half_ < 2; half_++) {
                    const int row = row0 + half_ * 8;
                    base[(long long)col * Mr + row] =
                        __float2half_rn(a[half_ * 2 + 0]);
                    base[(long long)(col + 1) * Mr + row] =
                        __float2half_rn(a[half_ * 2 + 1]);
                }
            } else if (EPI == 4) {
                const float b0 = bias[col], b1 = bias[col + 1];
                __half* ph = (__half*)Cm + cOff;
#pragma unroll
                for (int half_ = 0; half_ < 2; half_++) {
                    float t0 = a[half_ * 2 + 0] + b0;
                    float t1 = a[half_ * 2 + 1] + b1;
                    t0 = t0 > 0.f ? t0 : 0.f;
                    t1 = t1 > 0.f ? t1 : 0.f;
                    *(__half2*)(ph + (long long)(row0 + half_ * 8) * ldc + col) =
                        __halves2half2(__float2half_rn(t0), __float2half_rn(t1));
                }
            } else {  // EPI 5 (q,k): fp16 row store
                __half* ph = (__half*)Cm + cOff;
#pragma unroll
                for (int half_ = 0; half_ < 2; half_++) {
                    *(__half2*)(ph + (long long)(row0 + half_ * 8) * ldc + col) =
                        __halves2half2(__float2half_rn(a[half_ * 2 + 0]),
                                       __float2half_rn(a[half_ * 2 + 1]));
                }
            }
        }
    }
}

// ---------------------------------------------------------------------------
// Fused attention: per block = (h, b, 64 q-rows).
// Phase 1: S[64,1024] = q·k^T (fp16 scores -> smem, 8 k-tiles, 2-stage).
// Softmax in smem (fp32 math, coalesced 8B/16B accesses): fp32 atts
// (float4 streaming) + fp16 probs in place.
// Phase 2: O[64,128] = P·vT (8 chunks of 128 k-cols, 2-stage).
// smem: probs 64x2064 | q 64x272 | k/v region 2x34816.  Total 219136 B.
// ---------------------------------------------------------------------------
constexpr int PR_STRIDE = 2064;                  // 2048 + 16 pad
constexpr int Q_OFF  = 64 * PR_STRIDE;           // 132096
constexpr int KV_OFF = Q_OFF + 64 * 272;         // 149504
constexpr int SM_ATT = KV_OFF + 2 * 34816;       // 219136

__global__ void __launch_bounds__(256, 1)
fused_attn(const __half* __restrict__ qkv, float* __restrict__ atts_l,
           __half* __restrict__ o)
{
    extern __shared__ char sm[];
    const uint32_t sb = smem_u32(sm);

    const int tid = threadIdx.x;
    const int lane = tid & 31;
    const int warp = tid >> 5;
    const int warpM = warp & 1;      // 2 M-warps (32 rows)
    const int warpN = warp >> 1;     // 4 N-warps (32 cols)

    const int qt = blockIdx.x;       // q tile (64 rows): 0..15
    const int hb = blockIdx.y;       // h*Bb + b: 0..31
    const int hh = hb >> 2, bb = hb & 3;

    const long long MrD = (long long)Mr * Dd;
    const __half* qbase = qkv + hh * MrD + (long long)(bb * Ts + qt * 64) * Dd;
    const __half* kbase = qkv + (long long)Hh * MrD + hh * MrD + (long long)(bb * Ts) * Dd;
    const __half* vbase = qkv + 2ll * Hh * MrD + hh * MrD + (long long)(bb * Ts);

    const uint32_t qs = sb + Q_OFF;
    const uint32_t kv = sb + KV_OFF;

    // ---- load q tile (64 rows x 256 B) ----
    {
        const int r = tid >> 2;
        const int c = (tid & 3) * 16;
#pragma unroll
        for (int g = 0; g < 4; g++)
            cp16(qs + (uint32_t)(r * 272 + c + g * 64),
                 (const char*)(qbase + (long long)r * Dd) + c + g * 64);
    }
    CP_COMMIT();

    auto load_k = [&](int kt, int st) {
        const int r = tid >> 1;
        const int c = (tid & 1) * 16;
        const char* src = (const char*)(kbase + (long long)(kt * 128 + r) * Dd);
        const uint32_t dst = kv + (uint32_t)st * 34816 + (uint32_t)(r * 272);
#pragma unroll
        for (int g = 0; g < 8; g++)
            cp16(dst + c + g * 32, src + c + g * 32);
    };
    // v chunk = 128 d-rows x 128 k-cols (256 B payload / row, stride 272)
    auto load_v = [&](int kc, int st) {
        const int r = tid >> 1;
        const int c = (tid & 1) * 16;
        const char* src = (const char*)(vbase + (long long)r * Mr + kc * 128);
        const uint32_t dst = kv + (uint32_t)st * 34816 + (uint32_t)(r * 272);
#pragma unroll
        for (int g = 0; g < 8; g++)
            cp16(dst + c + g * 32, src + c + g * 32);
    };

    const int lr = lane >> 2;
    const int lc = (lane & 3) * 2;

    // ================= phase 1: scores =================
    load_k(0, 0); CP_COMMIT();
    for (int kt = 0; kt < 8; kt++) {
        CP_WAIT(0);
        __syncthreads();
        if (kt + 1 < 8) { load_k(kt + 1, (kt + 1) & 1); CP_COMMIT(); }

        const uint32_t kbuf = kv + (uint32_t)(kt & 1) * 34816;
        float acc[2][4][4];
#pragma unroll
        for (int i = 0; i < 2; i++)
#pragma unroll
            for (int j = 0; j < 4; j++)
#pragma unroll
                for (int q = 0; q < 4; q++) acc[i][j][q] = 0.f;

#pragma unroll
        for (int ks = 0; ks < 8; ks++) {
            uint32_t ah[2][4], bh[4][2];
#pragma unroll
            for (int tm = 0; tm < 2; tm++) {
                const int row = warpM * 32 + tm * 16 + (lane & 15);
                LDSM4(ah[tm], qs + (uint32_t)(row * 272 + ((lane >> 4) << 4) + ks * 32));
            }
#pragma unroll
            for (int gn = 0; gn < 2; gn++) {
                const int n = warpN * 32 + gn * 16 + ((lane >> 4) & 1) * 8 + (lane & 7);
                uint32_t r0[4];
                LDSM4(r0, kbuf + (uint32_t)(n * 272 + ((lane >> 3) & 1) * 16 + ks * 32));
                bh[gn * 2][0] = r0[0]; bh[gn * 2][1] = r0[1];
                bh[gn * 2 + 1][0] = r0[2]; bh[gn * 2 + 1][1] = r0[3];
            }
#pragma unroll
            for (int tm = 0; tm < 2; tm++)
#pragma unroll
                for (int tn = 0; tn < 4; tn++)
                    MMA16816(acc[tm][tn], ah[tm], bh[tn]);
        }

        // store fp16 scores into probs smem
#pragma unroll
        for (int tm = 0; tm < 2; tm++) {
#pragma unroll
            for (int tn = 0; tn < 4; tn++) {
                const int row0 = warpM * 32 + tm * 16 + lr;
                const int col = kt * 128 + warpN * 32 + tn * 8 + lc;
                const float* a = acc[tm][tn];
#pragma unroll
                for (int half_ = 0; half_ < 2; half_++) {
                    *(__half2*)(sm + (row0 + half_ * 8) * PR_STRIDE + col * 2) =
                        __halves2half2(__float2half_rn(a[half_ * 2 + 0]),
                                       __float2half_rn(a[half_ * 2 + 1]));
                }
            }
        }
    }
    __syncthreads();   // all scores in smem

    // preload first vT chunk (overlaps with softmax)
    load_v(0, 0); CP_COMMIT();

    // ================= softmax (warp per 8 rows, coalesced) =================
    {
        const float sc = 0.08838834764831845f;  // 1/sqrt(128)
        for (int rr = 0; rr < 8; rr++) {
            const int row = warp * 8 + rr;
            __half2* prow = (__half2*)(sm + row * PR_STRIDE);
            float v[32];
            float mx = -1e30f;
#pragma unroll
            for (int j = 0; j < 8; j++) {
                const int idx = j * 64 + lane * 2;       // 8B-aligned pair
                const __half2 a2 = prow[idx];
                const __half2 b2 = prow[idx + 1];
                float f0 = __half2float(__low2half(a2)) * sc;
                float f1 = __half2float(__high2half(a2)) * sc;
                float f2 = __half2float(__low2half(b2)) * sc;
                float f3 = __half2float(__high2half(b2)) * sc;
                v[4 * j] = f0; v[4 * j + 1] = f1; v[4 * j + 2] = f2; v[4 * j + 3] = f3;
                mx = fmaxf(mx, fmaxf(fmaxf(f0, f1), fmaxf(f2, f3)));
            }
#pragma unroll
            for (int off = 16; off; off >>= 1)
                mx = fmaxf(mx, __shfl_xor_sync(0xFFFFFFFFu, mx, off));
            float s = 0.f;
#pragma unroll
            for (int i = 0; i < 32; i++) { v[i] = __expf(v[i] - mx); s += v[i]; }
#pragma unroll
            for (int off = 16; off; off >>= 1)
                s += __shfl_xor_sync(0xFFFFFFFFu, s, off);
            const float inv = 1.f / s;

            float* arow = atts_l + ((long long)hb * Ts + qt * 64 + row) * 1024;
#pragma unroll
            for (int j = 0; j < 8; j++) {
                const int idx = j * 64 + lane * 2;
                const float f0 = v[4 * j] * inv, f1 = v[4 * j + 1] * inv;
                const float f2 = v[4 * j + 2] * inv, f3 = v[4 * j + 3] * inv;
                prow[idx]     = __halves2half2(__float2half_rn(f0), __float2half_rn(f1));
                prow[idx + 1] = __halves2half2(__float2half_rn(f2), __float2half_rn(f3));
                float4 o4 = {f0, f1, f2, f3};
                __stcs((float4*)(arow + j * 128 + lane * 4), o4);
            }
        }
    }
    __syncthreads();   // normalized probs visible to all warps

    // ================= phase 2: O = P @ vT (8 chunks of 128 cols) ==========
    float acc2[2][4][4];
#pragma unroll
    for (int i = 0; i < 2; i++)
#pragma unroll
        for (int j = 0; j < 4; j++)
#pragma unroll
            for (int q = 0; q < 4; q++) acc2[i][j][q] = 0.f;

    for (int kc = 0; kc < 8; kc++) {
        CP_WAIT(0);
        __syncthreads();
        if (kc + 1 < 8) { load_v(kc + 1, (kc + 1) & 1); CP_COMMIT(); }

        const uint32_t vbuf = kv + (uint32_t)(kc & 1) * 34816;
#pragma unroll
        for (int ks = 0; ks < 8; ks++) {
            uint32_t ah[2][4], bh[4][2];
#pragma unroll
            for (int tm = 0; tm < 2; tm++) {
                const int row = warpM * 32 + tm * 16 + (lane & 15);
                LDSM4(ah[tm], sb + (uint32_t)(row * PR_STRIDE + kc * 256 +
                                              ((lane >> 4) << 4) + ks * 32));
            }
#pragma unroll
            for (int gn = 0; gn < 2; gn++) {
                const int n = warpN * 32 + gn * 16 + ((lane >> 4) & 1) * 8 + (lane & 7);
                uint32_t r0[4];
                LDSM4(r0, vbuf + (uint32_t)(n * 272 + ((lane >> 3) & 1) * 16 + ks * 32));
                bh[gn * 2][0] = r0[0]; bh[gn * 2][1] = r0[1];
                bh[gn * 2 + 1][0] = r0[2]; bh[gn * 2 + 1][1] = r0[3];
            }
#pragma unroll
            for (int tm = 0; tm < 2; tm++)
#pragma unroll
                for (int tn = 0; tn < 4; tn++)
                    MMA16816(acc2[tm][tn], ah[tm], bh[tn]);
        }
    }

    // epilogue: o fp16 concat layout [B*T, C]
#pragma unroll
    for (int tm = 0; tm < 2; tm++) {
#pragma unroll
        for (int tn = 0; tn < 4; tn++) {
            const int row0 = warpM * 32 + tm * 16 + lr;
            const int col = warpN * 32 + tn * 8 + lc;
            const float* a = acc2[tm][tn];
#pragma unroll
            for (int half_ = 0; half_ < 2; half_++) {
                const long long grow = (long long)(bb * Ts + qt * 64 + row0 + half_ * 8);
                *(__half2*)(o + grow * Cc + hh * 128 + col) =
                    __halves2half2(__float2half_rn(a[half_ * 2 + 0]),
                                   __float2half_rn(a[half_ * 2 + 1]));
            }
        }
    }
}

// ---------------------------------------------------------------------------
// Merged QKV weight transpose: z in [0,96): s=z/32 picks Wq/Wk/Wv, zz=z%32.
// ---------------------------------------------------------------------------
__global__ void __launch_bounds__(256)
transpose_qkv(const float* __restrict__ Wq, const float* __restrict__ Wk,
              const float* __restrict__ Wv, __half* __restrict__ outw)
{
    const long long DK  = (long long)Dd * Cc;
    const long long HDK = Hh * DK;
    const int z = blockIdx.z;
    const int s = z >> 5;
    const int zz = z & 31;
    const float* W = (s == 0 ? Wq : s == 1 ? Wk : Wv) + (long long)zz * DK;
    const int l = zz >> 3, hd = zz & 7;
    __half* outp = outw + (long long)l * 3 * HDK + (long long)s * HDK + (long long)hd * DK;

    __shared__ float t[32][33];
    const int tx = threadIdx.x & 31, ty = threadIdx.x >> 5;
    const int n0 = blockIdx.x * 32, k0 = blockIdx.y * 32;
#pragma unroll
    for (int i = 0; i < 4; i++)
        t[ty + i * 8][tx] = W[(long long)(k0 + ty + i * 8) * Dd + n0 + tx];
    __syncthreads();
#pragma unroll
    for (int i = 0; i < 4; i++) {
        const float v = t[tx][ty + i * 8];
        outp[(long long)(n0 + ty + i * 8) * Cc + k0 + tx] = __float2half_rn(v);
    }
}

// ---------------------------------------------------------------------------
__global__ void __launch_bounds__(256)
transpose_h(const float* __restrict__ W, long long inSlo,
            __half* __restrict__ hi, long long outSlo, int K, int N)
{
    const int z = blockIdx.z;
    W += (long long)z * inSlo;
    const long long oOff = (long long)z * outSlo;
    __shared__ float t[32][33];
    const int tx = threadIdx.x & 31, ty = threadIdx.x >> 5;
    const int n0 = blockIdx.x * 32, k0 = blockIdx.y * 32;
#pragma unroll
    for (int i = 0; i < 4; i++)
        t[ty + i * 8][tx] = W[(long long)(k0 + ty + i * 8) * N + n0 + tx];
    __syncthreads();
#pragma unroll
    for (int i = 0; i < 4; i++) {
        const float v = t[tx][ty + i * 8];
        hi[oOff + (long long)(n0 + ty + i * 8) * K + k0 + tx] = __float2half_rn(v);
    }
}

// ---------------------------------------------------------------------------
// LayerNorm (warp-shuffle reductions, 2 barriers).
// MODE 0: fp32 out (streaming). MODE 1: fp16 out.
// MODE 2: input = x + pos; writes h fp32 AND fp16 xn.
// ---------------------------------------------------------------------------
template<int MODE>
__global__ void __launch_bounds__(256)
ln_kernel(const float* __restrict__ x, const float* __restrict__ pos,
          float* __restrict__ y, __half* __restrict__ yh,
          const float* __restrict__ s, const float* __restrict__ b)
{
    __shared__ float red[16];
    const int tid = threadIdx.x;
    const int lane = tid & 31;
    const int warp = tid >> 5;
    const long long row = blockIdx.x;

    float4 v = *(const float4*)(x + row * 1024 + tid * 4);
    if (MODE == 2) {
        const long long prow = row & (Ts - 1);
        float4 p = *(const float4*)(pos + prow * 1024 + tid * 4);
        v.x += p.x; v.y += p.y; v.z += p.z; v.w += p.w;
        *(float4*)(y + row * 1024 + tid * 4) = v;
    }

    float sm1 = v.x + v.y + v.z + v.w;
#pragma unroll
    for (int off = 16; off; off >>= 1)
        sm1 += __shfl_xor_sync(0xFFFFFFFFu, sm1, off);
    if (lane == 0) red[warp] = sm1;
    __syncthreads();
    float tot = 0.f;
#pragma unroll
    for (int w = 0; w < 8; w++) tot += red[w];
    const float mean = tot * (1.f / 1024.f);

    float dx = v.x - mean, dy = v.y - mean, dz = v.z - mean, dw = v.w - mean;
    float sm2 = dx * dx + dy * dy + dz * dz + dw * dw;
#pragma unroll
    for (int off = 16; off; off >>= 1)
        sm2 += __shfl_xor_sync(0xFFFFFFFFu, sm2, off);
    if (lane == 0) red[8 + warp] = sm2;
    __syncthreads();
    float tot2 = 0.f;
#pragma unroll
    for (int w = 0; w < 8; w++) tot2 += red[8 + w];
    const float rs = rsqrtf(tot2 * (1.f / 1024.f) + 1e-5f);

    const int c = tid * 4;
    float t0 = dx * rs * s[c + 0] + b[c + 0];
    float t1 = dy * rs * s[c + 1] + b[c + 1];
    float t2 = dz * rs * s[c + 2] + b[c + 2];
    float t3 = dw * rs * s[c + 3] + b[c + 3];
    if (MODE == 0) {
        float4 o4 = {t0, t1, t2, t3};
        __stcs((float4*)(y + row * 1024 + c), o4);
    } else {
        __half* ph = yh + row * 1024 + c;
        *(__half2*)ph = __halves2half2(__float2half_rn(t0), __float2half_rn(t1));
        *(__half2*)(ph + 2) = __halves2half2(__float2half_rn(t2), __float2half_rn(t3));
    }
}

// ---------------------------------------------------------------------------
extern "C" void kernel_launch(void* const* d_in, const int* in_sizes, int n_in,
                              void* d_out, int out_size)
{
    const float* x     = (const float*)d_in[0];
    const float* pos   = (const float*)d_in[1];
    const float* Wq    = (const float*)d_in[2];
    const float* Wk    = (const float*)d_in[3];
    const float* Wv    = (const float*)d_in[4];
    const float* Wo    = (const float*)d_in[5];
    const float* bo    = (const float*)d_in[6];
    const float* ln1_s = (const float*)d_in[7];
    const float* ln1_b = (const float*)d_in[8];
    const float* ln2_s = (const float*)d_in[9];
    const float* ln2_b = (const float*)d_in[10];
    const float* W1    = (const float*)d_in[11];
    const float* b1    = (const float*)d_in[12];
    const float* W2    = (const float*)d_in[13];
    const float* b2    = (const float*)d_in[14];
    const float* lnf_s = (const float*)d_in[15];
    const float* lnf_b = (const float*)d_in[16];

    float* out  = (float*)d_out;
    float* outx = out;
    float* atts = out + (long long)Mr * Cc;

    float* h;
    __half *qkv, *xn, *o, *u, *wqkv_h, *wo_h, *w1_h, *w2_h;
    cudaGetSymbolAddress((void**)&h,      g_h);
    cudaGetSymbolAddress((void**)&qkv,    g_qkv);
    cudaGetSymbolAddress((void**)&xn,     g_xn);
    cudaGetSymbolAddress((void**)&o,      g_o);
    cudaGetSymbolAddress((void**)&u,      g_u);
    cudaGetSymbolAddress((void**)&wqkv_h, g_wqkv_h);
    cudaGetSymbolAddress((void**)&wo_h,   g_wo_h);
    cudaGetSymbolAddress((void**)&w1_h,   g_w1_h);
    cudaGetSymbolAddress((void**)&w2_h,   g_w2_h);

    cudaFuncSetAttribute(gemm_mma<2>, cudaFuncAttributeMaxDynamicSharedMemorySize, SM_MM);
    cudaFuncSetAttribute(gemm_mma<4>, cudaFuncAttributeMaxDynamicSharedMemorySize, SM_MM);
    cudaFuncSetAttribute(gemm_mma<5>, cudaFuncAttributeMaxDynamicSharedMemorySize, SM_MM);
    cudaFuncSetAttribute(fused_attn,  cudaFuncAttributeMaxDynamicSharedMemorySize, SM_ATT);

    const long long DK   = (long long)Dd * Cc;       // 131072
    const long long HDK  = Hh * DK;
    const long long HBTT = (long long)Hh * Bb * Ts * Ts;

    // Weight transposes first (launches 1-4) so ncu -s 5 captures QKV GEMM (#6).
    transpose_qkv<<<dim3(Dd / 32, Cc / 32, 96), 256>>>(Wq, Wk, Wv, wqkv_h);     // 1
    transpose_h<<<dim3(Cc / 32, Cc / 32, Ll), 256>>>(
        Wo, (long long)Cc * Cc, wo_h, (long long)Cc * Cc, Cc, Cc);              // 2
    transpose_h<<<dim3(Ff / 32, Cc / 32, Ll), 256>>>(
        W1, (long long)Cc * Ff, w1_h, (long long)Ff * Cc, Cc, Ff);              // 3
    transpose_h<<<dim3(Cc / 32, Ff / 32, Ll), 256>>>(
        W2, (long long)Ff * Cc, w2_h, (long long)Cc * Ff, Ff, Cc);              // 4

    for (int l = 0; l < Ll; l++) {
        float* atts_l = atts + (long long)l * HBTT;

        // LN1 (l==0 fuses add_pos)                                            (5)
        if (l == 0)
            ln_kernel<2><<<Mr, 256>>>(x, pos, h, xn, ln1_s, ln1_b);
        else
            ln_kernel<1><<<Mr, 256>>>(h, nullptr, nullptr, xn,
                                      ln1_s + l * Cc, ln1_b + l * Cc);

        // QKV: z = s*8+h (24). q,k: fp16 rows; v: vT (ld=Mr).                 (6)
        gemm_mma<5><<<dim3(1, 32, 24), 256, SM_MM>>>(
            xn, Cc, 1, 0, 0,
            wqkv_h + (long long)l * 3 * HDK, Cc, 1, DK, 0,
            (float*)qkv, Dd, 1, (long long)Mr * Dd, 0,
            nullptr, Cc);

        // fused scores + softmax + att@V
        fused_attn<<<dim3(16, 32), 256, SM_ATT>>>(qkv, atts_l, o);

        // proj: h += o @ Wo + bo
        gemm_mma<2><<<dim3(8, 32, 1), 256, SM_MM>>>(
            o, Cc, 1, 0, 0,
            wo_h + (long long)l * Cc * Cc, Cc, 1, 0, 0,
            h, Cc, 1, 0, 0,
            bo + l * Cc, Cc);

        // LN2 -> xn fp16
        ln_kernel<1><<<Mr, 256>>>(h, nullptr, nullptr, xn,
                                  ln2_s + l * Cc, ln2_b + l * Cc);

        // FFN1: u = relu(xn @ W1 + b1) -> fp16
        gemm_mma<4><<<dim3(32, 32, 1), 256, SM_MM>>>(
            xn, Cc, 1, 0, 0,
            w1_h + (long long)l * Cc * Ff, Cc, 1, 0, 0,
            (float*)u, Ff, 1, 0, 0,
            b1 + l * Ff, Cc);

        // FFN2: h += u @ W2 + b2
        gemm_mma<2><<<dim3(8, 32, 1), 256, SM_MM>>>(
            u, Ff, 1, 0, 0,
            w2_h + (long long)l * Ff * Cc, Ff, 1, 0, 0,
            h, Cc, 1, 0, 0,
            b2 + l * Cc, Ff);
    }

    // final LN -> fp32 output (streaming store)
    ln_kernel<0><<<Mr, 256>>>(h, nullptr, outx, nullptr, lnf_s, lnf_b);
}

// round 13
// speedup vs baseline: 1.1671x; 1.0032x over previous
#include <cuda_runtime.h>
#include <cuda_fp16.h>
#include <cstdint>

// Problem constants
constexpr int Bb = 4, Ts = 1024, Cc = 1024, Hh = 8, Dd = 128, Ff = 4096, Ll = 4;
constexpr int Mr = Bb * Ts;  // 4096

// ---------------- scratch (device globals; allocation-free rule) ----------
__device__ float  g_h[(size_t)Mr * Cc];                    // residual fp32
__device__ __half g_qkv[(size_t)3 * Hh * Mr * Dd];         // q,k rows; vT cols
__device__ __half g_xn[(size_t)Mr * Cc];                   // LN out fp16
__device__ __half g_o[(size_t)Mr * Cc];                    // attn out fp16
__device__ __half g_u[(size_t)Mr * Ff];                    // FFN hidden fp16
__device__ __half g_wqkv_h[(size_t)Ll * 3 * Hh * Dd * Cc]; // fp16 weights [N,K]
__device__ __half g_wo_h[(size_t)Ll * Cc * Cc];
__device__ __half g_w1_h[(size_t)Ll * Cc * Ff];
__device__ __half g_w2_h[(size_t)Ll * Ff * Cc];

// ---------------- PTX helpers (sm_80-era; compiles for plain sm_103) ------
__device__ __forceinline__ uint32_t smem_u32(const void* p) {
    uint32_t a;
    asm("{ .reg .u64 t; cvta.to.shared.u64 t, %1; cvt.u32.u64 %0, t; }" : "=r"(a) : "l"(p));
    return a;
}
__device__ __forceinline__ void cp16(uint32_t s, const void* g) {
    asm volatile("cp.async.cg.shared.global [%0], [%1], 16;" :: "r"(s), "l"(g));
}
#define CP_COMMIT() asm volatile("cp.async.commit_group;" ::: "memory")
#define CP_WAIT(n)  asm volatile("cp.async.wait_group %0;" :: "n"(n) : "memory")

#define LDSM4(r, addr) \
    asm volatile("ldmatrix.sync.aligned.m8n8.x4.shared.b16 {%0,%1,%2,%3}, [%4];" \
        : "=r"((r)[0]), "=r"((r)[1]), "=r"((r)[2]), "=r"((r)[3]) : "r"(addr))

#define MMA16816(c, a, b) \
    asm volatile("mma.sync.aligned.m16n8k16.row.col.f32.f16.f16.f32 " \
        "{%0,%1,%2,%3}, {%4,%5,%6,%7}, {%8,%9}, {%0,%1,%2,%3};" \
        : "+f"((c)[0]), "+f"((c)[1]), "+f"((c)[2]), "+f"((c)[3]) \
        : "r"((a)[0]), "r"((a)[1]), "r"((a)[2]), "r"((a)[3]), \
          "r"((b)[0]), "r"((b)[1]))

// ---------------------------------------------------------------------------
// HMMA fp16 GEMM (R8 config): C[M,N] = A[M,K] * Bt[N,K]^T, fp32 accum.
// Block 128x128, 8 warps (4M x 2N), K-chunks of 64, 3-stage cp.async, occ 2.
// EPI: 2 fp32 += acc+bias | 4 relu(acc+bias)->fp16 rows
//      5 QKV: z<16 fp16 rows, z>=16 vT transposed via smem staging (ld = Mr)
// ---------------------------------------------------------------------------
constexpr int STG   = 36864;            // 128 rows * 144 B * 2 matrices
constexpr int B_OFF = 18432;
constexpr int SM_MM = 3 * STG;          // 110592

template<int EPI>
__global__ void __launch_bounds__(256, 2)
gemm_mma(const __half* __restrict__ A, int lda,
         int aDiv, long long aShi, long long aSlo,
         const __half* __restrict__ B, int ldb,
         int bDiv, long long bShi, long long bSlo,
         float* __restrict__ Cm, int ldc,
         int cDiv, long long cShi, long long cSlo,
         const float* __restrict__ bias, int K)
{
    extern __shared__ char sm[];
    const uint32_t sb = smem_u32(sm);

    const int tid = threadIdx.x;
    const int lane = tid & 31;
    const int warp = tid >> 5;
    const int warpM = warp & 3;
    const int warpN = warp >> 2;

    const int z = blockIdx.z;
    A  += (long long)(z / aDiv) * aShi + (long long)(z % aDiv) * aSlo;
    B  += (long long)(z / bDiv) * bShi + (long long)(z % bDiv) * bSlo;
    const long long cOff = (long long)(z / cDiv) * cShi + (long long)(z % cDiv) * cSlo;

    const int rowBase = blockIdx.y * 128;
    const int colBase = blockIdx.x * 128;

    float acc[2][8][4];
#pragma unroll
    for (int i = 0; i < 2; i++)
#pragma unroll
        for (int j = 0; j < 8; j++)
#pragma unroll
            for (int q = 0; q < 4; q++) acc[i][j][q] = 0.f;

    const int nCh = K >> 6;
    const int ldr = tid >> 3;            // 0..31
    const int c16 = (tid & 7) * 16;      // byte col in 128B row

    auto load_chunk = [&](int i, int st) {
        const long long k0 = (long long)i * 64;
        const uint32_t sbase = sb + (uint32_t)st * STG;
#pragma unroll
        for (int g = 0; g < 4; g++) {
            const int rr = g * 32 + ldr;
            const uint32_t so = sbase + (uint32_t)(rr * 144 + c16);
            cp16(so,
                 (const char*)(A + (long long)(rowBase + rr) * lda + k0) + c16);
            cp16(so + B_OFF,
                 (const char*)(B + (long long)(colBase + rr) * ldb + k0) + c16);
        }
    };

    load_chunk(0, 0); CP_COMMIT();
    load_chunk(1, 1); CP_COMMIT();

    for (int i = 0; i < nCh; i++) {
        if (i + 1 < nCh) { CP_WAIT(1); } else { CP_WAIT(0); }
        __syncthreads();
        if (i + 2 < nCh) { load_chunk(i + 2, (i + 2) % 3); CP_COMMIT(); }

        const uint32_t sbase = sb + (uint32_t)(i % 3) * STG;
#pragma unroll
        for (int ks = 0; ks < 4; ks++) {
            uint32_t ah[2][4], bh[8][2];
#pragma unroll
            for (int tm = 0; tm < 2; tm++) {
                const int row = warpM * 32 + tm * 16 + (lane & 15);
                const uint32_t addr =
                    sbase + (uint32_t)(row * 144 + ((lane >> 4) << 4) + ks * 32);
                LDSM4(ah[tm], addr);
            }
#pragma unroll
            for (int gn = 0; gn < 4; gn++) {
                const int n = warpN * 64 + gn * 16 + ((lane >> 4) & 1) * 8 + (lane & 7);
                const uint32_t addr =
                    sbase + (uint32_t)B_OFF +
                    (uint32_t)(n * 144 + ((lane >> 3) & 1) * 16 + ks * 32);
                uint32_t r0[4];
                LDSM4(r0, addr);
                bh[gn * 2][0] = r0[0]; bh[gn * 2][1] = r0[1];
                bh[gn * 2 + 1][0] = r0[2]; bh[gn * 2 + 1][1] = r0[3];
            }
#pragma unroll
            for (int tm = 0; tm < 2; tm++) {
#pragma unroll
                for (int tn = 0; tn < 8; tn++) {
                    MMA16816(acc[tm][tn], ah[tm], bh[tn]);
                }
            }
        }
    }

    const int lr = lane >> 2;
    const int lc = (lane & 3) * 2;

    if (EPI == 5 && blockIdx.z >= 16) {
        // ---- vT epilogue: stage transposed tile in smem, coalesced store ----
        __syncthreads();                         // all warps done with pipeline smem
        __half* st = (__half*)sm;                // [128 cols][136 halves stride]
#pragma unroll
        for (int tm = 0; tm < 2; tm++) {
#pragma unroll
            for (int tn = 0; tn < 8; tn++) {
                const int lrow = warpM * 32 + tm * 16 + lr;
                const int lcol = warpN * 64 + tn * 8 + lc;
                const float* a = acc[tm][tn];
                st[lcol * 136 + lrow]           = __float2half_rn(a[0]);
                st[(lcol + 1) * 136 + lrow]     = __float2half_rn(a[1]);
                st[lcol * 136 + lrow + 8]       = __float2half_rn(a[2]);
                st[(lcol + 1) * 136 + lrow + 8] = __float2half_rn(a[3]);
            }
        }
        __syncthreads();
        // 256 chunks of 128 B: chunk = (col row of vT, half-segment)
        __half* base = (__half*)Cm + cOff;
        const int cr = tid >> 1;                 // 0..127 (d index)
        const int part = tid & 1;                // 0/1 (which 64-half segment)
        const uint4* src = (const uint4*)((const char*)st + cr * 272 + part * 128);
        uint4* dst = (uint4*)(base + (long long)(colBase + cr) * Mr + rowBase + part * 64);
#pragma unroll
        for (int i = 0; i < 8; i++) dst[i] = src[i];
        return;
    }

    // ---- standard epilogues from registers ----
    const int rB = rowBase + warpM * 32;
    const int cB = colBase + warpN * 64;
#pragma unroll
    for (int tm = 0; tm < 2; tm++) {
#pragma unroll
        for (int tn = 0; tn < 8; tn++) {
            const int row0 = rB + tm * 16 + lr;
            const int col  = cB + tn * 8 + lc;
            const float* a = acc[tm][tn];
            if (EPI == 2) {
                const float b0 = bias[col], b1 = bias[col + 1];
                float* p0 = Cm + cOff + (long long)row0 * ldc + col;
                float* p1 = Cm + cOff + (long long)(row0 + 8) * ldc + col;
                p0[0] += a[0] + b0;  p0[1] += a[1] + b1;
                p1[0] += a[2] + b0;  p1[1] += a[3] + b1;
            } else if (EPI == 4) {
                const float b0 = bias[col], b1 = bias[col + 1];
                __half* ph = (__half*)Cm + cOff;
#pragma unroll
                for (int half_ = 0; half_ < 2; half_++) {
                    float t0 = a[half_ * 2 + 0] + b0;
                    float t1 = a[half_ * 2 + 1] + b1;
                    t0 = t0 > 0.f ? t0 : 0.f;
                    t1 = t1 > 0.f ? t1 : 0.f;
                    *(__half2*)(ph + (long long)(row0 + half_ * 8) * ldc + col) =
                        __halves2half2(__float2half_rn(t0), __float2half_rn(t1));
                }
            } else {  // EPI 5 (q,k): fp16 row store
                __half* ph = (__half*)Cm + cOff;
#pragma unroll
                for (int half_ = 0; half_ < 2; half_++) {
                    *(__half2*)(ph + (long long)(row0 + half_ * 8) * ldc + col) =
                        __halves2half2(__float2half_rn(a[half_ * 2 + 0]),
                                       __float2half_rn(a[half_ * 2 + 1]));
                }
            }
        }
    }
}

// ---------------------------------------------------------------------------
// Fused attention: per block = (h, b, 64 q-rows). (R12 version, unchanged)
// ---------------------------------------------------------------------------
constexpr int PR_STRIDE = 2064;                  // 2048 + 16 pad
constexpr int Q_OFF  = 64 * PR_STRIDE;           // 132096
constexpr int KV_OFF = Q_OFF + 64 * 272;         // 149504
constexpr int SM_ATT = KV_OFF + 2 * 34816;       // 219136

__global__ void __launch_bounds__(256, 1)
fused_attn(const __half* __restrict__ qkv, float* __restrict__ atts_l,
           __half* __restrict__ o)
{
    extern __shared__ char sm[];
    const uint32_t sb = smem_u32(sm);

    const int tid = threadIdx.x;
    const int lane = tid & 31;
    const int warp = tid >> 5;
    const int warpM = warp & 1;      // 2 M-warps (32 rows)
    const int warpN = warp >> 1;     // 4 N-warps (32 cols)

    const int qt = blockIdx.x;       // q tile (64 rows): 0..15
    const int hb = blockIdx.y;       // h*Bb + b: 0..31
    const int hh = hb >> 2, bb = hb & 3;

    const long long MrD = (long long)Mr * Dd;
    const __half* qbase = qkv + hh * MrD + (long long)(bb * Ts + qt * 64) * Dd;
    const __half* kbase = qkv + (long long)Hh * MrD + hh * MrD + (long long)(bb * Ts) * Dd;
    const __half* vbase = qkv + 2ll * Hh * MrD + hh * MrD + (long long)(bb * Ts);

    const uint32_t qs = sb + Q_OFF;
    const uint32_t kv = sb + KV_OFF;

    {
        const int r = tid >> 2;
        const int c = (tid & 3) * 16;
#pragma unroll
        for (int g = 0; g < 4; g++)
            cp16(qs + (uint32_t)(r * 272 + c + g * 64),
                 (const char*)(qbase + (long long)r * Dd) + c + g * 64);
    }
    CP_COMMIT();

    auto load_k = [&](int kt, int st) {
        const int r = tid >> 1;
        const int c = (tid & 1) * 16;
        const char* src = (const char*)(kbase + (long long)(kt * 128 + r) * Dd);
        const uint32_t dst = kv + (uint32_t)st * 34816 + (uint32_t)(r * 272);
#pragma unroll
        for (int g = 0; g < 8; g++)
            cp16(dst + c + g * 32, src + c + g * 32);
    };
    auto load_v = [&](int kc, int st) {
        const int r = tid >> 1;
        const int c = (tid & 1) * 16;
        const char* src = (const char*)(vbase + (long long)r * Mr + kc * 128);
        const uint32_t dst = kv + (uint32_t)st * 34816 + (uint32_t)(r * 272);
#pragma unroll
        for (int g = 0; g < 8; g++)
            cp16(dst + c + g * 32, src + c + g * 32);
    };

    const int lr = lane >> 2;
    const int lc = (lane & 3) * 2;

    // ================= phase 1: scores =================
    load_k(0, 0); CP_COMMIT();
    for (int kt = 0; kt < 8; kt++) {
        CP_WAIT(0);
        __syncthreads();
        if (kt + 1 < 8) { load_k(kt + 1, (kt + 1) & 1); CP_COMMIT(); }

        const uint32_t kbuf = kv + (uint32_t)(kt & 1) * 34816;
        float acc[2][4][4];
#pragma unroll
        for (int i = 0; i < 2; i++)
#pragma unroll
            for (int j = 0; j < 4; j++)
#pragma unroll
                for (int q = 0; q < 4; q++) acc[i][j][q] = 0.f;

#pragma unroll
        for (int ks = 0; ks < 8; ks++) {
            uint32_t ah[2][4], bh[4][2];
#pragma unroll
            for (int tm = 0; tm < 2; tm++) {
                const int row = warpM * 32 + tm * 16 + (lane & 15);
                LDSM4(ah[tm], qs + (uint32_t)(row * 272 + ((lane >> 4) << 4) + ks * 32));
            }
#pragma unroll
            for (int gn = 0; gn < 2; gn++) {
                const int n = warpN * 32 + gn * 16 + ((lane >> 4) & 1) * 8 + (lane & 7);
                uint32_t r0[4];
                LDSM4(r0, kbuf + (uint32_t)(n * 272 + ((lane >> 3) & 1) * 16 + ks * 32));
                bh[gn * 2][0] = r0[0]; bh[gn * 2][1] = r0[1];
                bh[gn * 2 + 1][0] = r0[2]; bh[gn * 2 + 1][1] = r0[3];
            }
#pragma unroll
            for (int tm = 0; tm < 2; tm++)
#pragma unroll
                for (int tn = 0; tn < 4; tn++)
                    MMA16816(acc[tm][tn], ah[tm], bh[tn]);
        }

#pragma unroll
        for (int tm = 0; tm < 2; tm++) {
#pragma unroll
            for (int tn = 0; tn < 4; tn++) {
                const int row0 = warpM * 32 + tm * 16 + lr;
                const int col = kt * 128 + warpN * 32 + tn * 8 + lc;
                const float* a = acc[tm][tn];
#pragma unroll
                for (int half_ = 0; half_ < 2; half_++) {
                    *(__half2*)(sm + (row0 + half_ * 8) * PR_STRIDE + col * 2) =
                        __halves2half2(__float2half_rn(a[half_ * 2 + 0]),
                                       __float2half_rn(a[half_ * 2 + 1]));
                }
            }
        }
    }
    __syncthreads();

    load_v(0, 0); CP_COMMIT();

    // ================= softmax (warp per 8 rows, coalesced) =================
    {
        const float sc = 0.08838834764831845f;
        for (int rr = 0; rr < 8; rr++) {
            const int row = warp * 8 + rr;
            __half2* prow = (__half2*)(sm + row * PR_STRIDE);
            float v[32];
            float mx = -1e30f;
#pragma unroll
            for (int j = 0; j < 8; j++) {
                const int idx = j * 64 + lane * 2;
                const __half2 a2 = prow[idx];
                const __half2 b2 = prow[idx + 1];
                float f0 = __half2float(__low2half(a2)) * sc;
                float f1 = __half2float(__high2half(a2)) * sc;
                float f2 = __half2float(__low2half(b2)) * sc;
                float f3 = __half2float(__high2half(b2)) * sc;
                v[4 * j] = f0; v[4 * j + 1] = f1; v[4 * j + 2] = f2; v[4 * j + 3] = f3;
                mx = fmaxf(mx, fmaxf(fmaxf(f0, f1), fmaxf(f2, f3)));
            }
#pragma unroll
            for (int off = 16; off; off >>= 1)
                mx = fmaxf(mx, __shfl_xor_sync(0xFFFFFFFFu, mx, off));
            float s = 0.f;
#pragma unroll
            for (int i = 0; i < 32; i++) { v[i] = __expf(v[i] - mx); s += v[i]; }
#pragma unroll
            for (int off = 16; off; off >>= 1)
                s += __shfl_xor_sync(0xFFFFFFFFu, s, off);
            const float inv = 1.f / s;

            float* arow = atts_l + ((long long)hb * Ts + qt * 64 + row) * 1024;
#pragma unroll
            for (int j = 0; j < 8; j++) {
                const int idx = j * 64 + lane * 2;
                const float f0 = v[4 * j] * inv, f1 = v[4 * j + 1] * inv;
                const float f2 = v[4 * j + 2] * inv, f3 = v[4 * j + 3] * inv;
                prow[idx]     = __halves2half2(__float2half_rn(f0), __float2half_rn(f1));
                prow[idx + 1] = __halves2half2(__float2half_rn(f2), __float2half_rn(f3));
                float4 o4 = {f0, f1, f2, f3};
                __stcs((float4*)(arow + j * 128 + lane * 4), o4);
            }
        }
    }
    __syncthreads();

    // ================= phase 2: O = P @ vT (8 chunks of 128 cols) ==========
    float acc2[2][4][4];
#pragma unroll
    for (int i = 0; i < 2; i++)
#pragma unroll
        for (int j = 0; j < 4; j++)
#pragma unroll
            for (int q = 0; q < 4; q++) acc2[i][j][q] = 0.f;

    for (int kc = 0; kc < 8; kc++) {
        CP_WAIT(0);
        __syncthreads();
        if (kc + 1 < 8) { load_v(kc + 1, (kc + 1) & 1); CP_COMMIT(); }

        const uint32_t vbuf = kv + (uint32_t)(kc & 1) * 34816;
#pragma unroll
        for (int ks = 0; ks < 8; ks++) {
            uint32_t ah[2][4], bh[4][2];
#pragma unroll
            for (int tm = 0; tm < 2; tm++) {
                const int row = warpM * 32 + tm * 16 + (lane & 15);
                LDSM4(ah[tm], sb + (uint32_t)(row * PR_STRIDE + kc * 256 +
                                              ((lane >> 4) << 4) + ks * 32));
            }
#pragma unroll
            for (int gn = 0; gn < 2; gn++) {
                const int n = warpN * 32 + gn * 16 + ((lane >> 4) & 1) * 8 + (lane & 7);
                uint32_t r0[4];
                LDSM4(r0, vbuf + (uint32_t)(n * 272 + ((lane >> 3) & 1) * 16 + ks * 32));
                bh[gn * 2][0] = r0[0]; bh[gn * 2][1] = r0[1];
                bh[gn * 2 + 1][0] = r0[2]; bh[gn * 2 + 1][1] = r0[3];
            }
#pragma unroll
            for (int tm = 0; tm < 2; tm++)
#pragma unroll
                for (int tn = 0; tn < 4; tn++)
                    MMA16816(acc2[tm][tn], ah[tm], bh[tn]);
        }
    }

#pragma unroll
    for (int tm = 0; tm < 2; tm++) {
#pragma unroll
        for (int tn = 0; tn < 4; tn++) {
            const int row0 = warpM * 32 + tm * 16 + lr;
            const int col = warpN * 32 + tn * 8 + lc;
            const float* a = acc2[tm][tn];
#pragma unroll
            for (int half_ = 0; half_ < 2; half_++) {
                const long long grow = (long long)(bb * Ts + qt * 64 + row0 + half_ * 8);
                *(__half2*)(o + grow * Cc + hh * 128 + col) =
                    __halves2half2(__float2half_rn(a[half_ * 2 + 0]),
                                   __float2half_rn(a[half_ * 2 + 1]));
            }
        }
    }
}

// ---------------------------------------------------------------------------
// 64x64-tile weight transpose + fp16 convert, float4 loads, 8B stores.
// W[z][K,N] fp32 -> out[z][N,K] fp16, z offset = z*inSlo / z*outSlo.
// ---------------------------------------------------------------------------
__global__ void __launch_bounds__(256)
transpose64(const float* __restrict__ W, long long inSlo,
            __half* __restrict__ out, long long outSlo, int K, int N)
{
    const int z = blockIdx.z;
    W += (long long)z * inSlo;
    const long long oOff = (long long)z * outSlo;
    __shared__ float t[64][65];
    const int r  = threadIdx.x >> 4;       // 0..15
    const int c4 = threadIdx.x & 15;       // 0..15
    const int n0 = blockIdx.x * 64, k0 = blockIdx.y * 64;
#pragma unroll
    for (int i = 0; i < 4; i++) {
        const int row = i * 16 + r;
        float4 v = *(const float4*)(W + (long long)(k0 + row) * N + n0 + c4 * 4);
        t[c4 * 4 + 0][row] = v.x;
        t[c4 * 4 + 1][row] = v.y;
        t[c4 * 4 + 2][row] = v.z;
        t[c4 * 4 + 3][row] = v.w;
    }
    __syncthreads();
#pragma unroll
    for (int i = 0; i < 4; i++) {
        const int n = i * 16 + r;
        const float f0 = t[n][c4 * 4 + 0];
        const float f1 = t[n][c4 * 4 + 1];
        const float f2 = t[n][c4 * 4 + 2];
        const float f3 = t[n][c4 * 4 + 3];
        __half2* dst = (__half2*)(out + oOff + (long long)(n0 + n) * K + k0 + c4 * 4);
        dst[0] = __halves2half2(__float2half_rn(f0), __float2half_rn(f1));
        dst[1] = __halves2half2(__float2half_rn(f2), __float2half_rn(f3));
    }
}

// Merged QKV weight transpose (64x64 tiles): z in [0,96).
__global__ void __launch_bounds__(256)
transpose_qkv64(const float* __restrict__ Wq, const float* __restrict__ Wk,
                const float* __restrict__ Wv, __half* __restrict__ outw)
{
    const long long DK  = (long long)Dd * Cc;
    const long long HDK = Hh * DK;
    const int z = blockIdx.z;
    const int s = z >> 5;
    const int zz = z & 31;
    const float* W = (s == 0 ? Wq : s == 1 ? Wk : Wv) + (long long)zz * DK;
    const int l = zz >> 3, hd = zz & 7;
    __half* outp = outw + (long long)l * 3 * HDK + (long long)s * HDK + (long long)hd * DK;

    __shared__ float t[64][65];
    const int r  = threadIdx.x >> 4;
    const int c4 = threadIdx.x & 15;
    const int n0 = blockIdx.x * 64, k0 = blockIdx.y * 64;
#pragma unroll
    for (int i = 0; i < 4; i++) {
        const int row = i * 16 + r;
        float4 v = *(const float4*)(W + (long long)(k0 + row) * Dd + n0 + c4 * 4);
        t[c4 * 4 + 0][row] = v.x;
        t[c4 * 4 + 1][row] = v.y;
        t[c4 * 4 + 2][row] = v.z;
        t[c4 * 4 + 3][row] = v.w;
    }
    __syncthreads();
#pragma unroll
    for (int i = 0; i < 4; i++) {
        const int n = i * 16 + r;
        const float f0 = t[n][c4 * 4 + 0];
        const float f1 = t[n][c4 * 4 + 1];
        const float f2 = t[n][c4 * 4 + 2];
        const float f3 = t[n][c4 * 4 + 3];
        __half2* dst = (__half2*)(outp + (long long)(n0 + n) * Cc + k0 + c4 * 4);
        dst[0] = __halves2half2(__float2half_rn(f0), __float2half_rn(f1));
        dst[1] = __halves2half2(__float2half_rn(f2), __float2half_rn(f3));
    }
}

// ---------------------------------------------------------------------------
// LayerNorm (warp-shuffle reductions).
// MODE 0: fp32 out (streaming). MODE 1: fp16 out. MODE 2: x+pos fused.
// ---------------------------------------------------------------------------
template<int MODE>
__global__ void __launch_bounds__(256)
ln_kernel(const float* __restrict__ x, const float* __restrict__ pos,
          float* __restrict__ y, __half* __restrict__ yh,
          const float* __restrict__ s, const float* __restrict__ b)
{
    __shared__ float red[16];
    const int tid = threadIdx.x;
    const int lane = tid & 31;
    const int warp = tid >> 5;
    const long long row = blockIdx.x;

    float4 v = *(const float4*)(x + row * 1024 + tid * 4);
    if (MODE == 2) {
        const long long prow = row & (Ts - 1);
        float4 p = *(const float4*)(pos + prow * 1024 + tid * 4);
        v.x += p.x; v.y += p.y; v.z += p.z; v.w += p.w;
        *(float4*)(y + row * 1024 + tid * 4) = v;
    }

    float sm1 = v.x + v.y + v.z + v.w;
#pragma unroll
    for (int off = 16; off; off >>= 1)
        sm1 += __shfl_xor_sync(0xFFFFFFFFu, sm1, off);
    if (lane == 0) red[warp] = sm1;
    __syncthreads();
    float tot = 0.f;
#pragma unroll
    for (int w = 0; w < 8; w++) tot += red[w];
    const float mean = tot * (1.f / 1024.f);

    float dx = v.x - mean, dy = v.y - mean, dz = v.z - mean, dw = v.w - mean;
    float sm2 = dx * dx + dy * dy + dz * dz + dw * dw;
#pragma unroll
    for (int off = 16; off; off >>= 1)
        sm2 += __shfl_xor_sync(0xFFFFFFFFu, sm2, off);
    if (lane == 0) red[8 + warp] = sm2;
    __syncthreads();
    float tot2 = 0.f;
#pragma unroll
    for (int w = 0; w < 8; w++) tot2 += red[8 + w];
    const float rs = rsqrtf(tot2 * (1.f / 1024.f) + 1e-5f);

    const int c = tid * 4;
    float t0 = dx * rs * s[c + 0] + b[c + 0];
    float t1 = dy * rs * s[c + 1] + b[c + 1];
    float t2 = dz * rs * s[c + 2] + b[c + 2];
    float t3 = dw * rs * s[c + 3] + b[c + 3];
    if (MODE == 0) {
        float4 o4 = {t0, t1, t2, t3};
        __stcs((float4*)(y + row * 1024 + c), o4);
    } else {
        __half* ph = yh + row * 1024 + c;
        *(__half2*)ph = __halves2half2(__float2half_rn(t0), __float2half_rn(t1));
        *(__half2*)(ph + 2) = __halves2half2(__float2half_rn(t2), __float2half_rn(t3));
    }
}

// ---------------------------------------------------------------------------
extern "C" void kernel_launch(void* const* d_in, const int* in_sizes, int n_in,
                              void* d_out, int out_size)
{
    const float* x     = (const float*)d_in[0];
    const float* pos   = (const float*)d_in[1];
    const float* Wq    = (const float*)d_in[2];
    const float* Wk    = (const float*)d_in[3];
    const float* Wv    = (const float*)d_in[4];
    const float* Wo    = (const float*)d_in[5];
    const float* bo    = (const float*)d_in[6];
    const float* ln1_s = (const float*)d_in[7];
    const float* ln1_b = (const float*)d_in[8];
    const float* ln2_s = (const float*)d_in[9];
    const float* ln2_b = (const float*)d_in[10];
    const float* W1    = (const float*)d_in[11];
    const float* b1    = (const float*)d_in[12];
    const float* W2    = (const float*)d_in[13];
    const float* b2    = (const float*)d_in[14];
    const float* lnf_s = (const float*)d_in[15];
    const float* lnf_b = (const float*)d_in[16];

    float* out  = (float*)d_out;
    float* outx = out;
    float* atts = out + (long long)Mr * Cc;

    float* h;
    __half *qkv, *xn, *o, *u, *wqkv_h, *wo_h, *w1_h, *w2_h;
    cudaGetSymbolAddress((void**)&h,      g_h);
    cudaGetSymbolAddress((void**)&qkv,    g_qkv);
    cudaGetSymbolAddress((void**)&xn,     g_xn);
    cudaGetSymbolAddress((void**)&o,      g_o);
    cudaGetSymbolAddress((void**)&u,      g_u);
    cudaGetSymbolAddress((void**)&wqkv_h, g_wqkv_h);
    cudaGetSymbolAddress((void**)&wo_h,   g_wo_h);
    cudaGetSymbolAddress((void**)&w1_h,   g_w1_h);
    cudaGetSymbolAddress((void**)&w2_h,   g_w2_h);

    cudaFuncSetAttribute(gemm_mma<2>, cudaFuncAttributeMaxDynamicSharedMemorySize, SM_MM);
    cudaFuncSetAttribute(gemm_mma<4>, cudaFuncAttributeMaxDynamicSharedMemorySize, SM_MM);
    cudaFuncSetAttribute(gemm_mma<5>, cudaFuncAttributeMaxDynamicSharedMemorySize, SM_MM);
    cudaFuncSetAttribute(fused_attn,  cudaFuncAttributeMaxDynamicSharedMemorySize, SM_ATT);

    const long long DK   = (long long)Dd * Cc;       // 131072
    const long long HDK  = Hh * DK;
    const long long HBTT = (long long)Hh * Bb * Ts * Ts;

    // Weight transposes (64x64 tiles, float4)
    transpose_qkv64<<<dim3(Dd / 64, Cc / 64, 96), 256>>>(Wq, Wk, Wv, wqkv_h);
    transpose64<<<dim3(Cc / 64, Cc / 64, Ll), 256>>>(
        Wo, (long long)Cc * Cc, wo_h, (long long)Cc * Cc, Cc, Cc);
    transpose64<<<dim3(Ff / 64, Cc / 64, Ll), 256>>>(
        W1, (long long)Cc * Ff, w1_h, (long long)Ff * Cc, Cc, Ff);
    transpose64<<<dim3(Cc / 64, Ff / 64, Ll), 256>>>(
        W2, (long long)Ff * Cc, w2_h, (long long)Cc * Ff, Ff, Cc);

    for (int l = 0; l < Ll; l++) {
        float* atts_l = atts + (long long)l * HBTT;

        // LN1 (l==0 fuses add_pos)
        if (l == 0)
            ln_kernel<2><<<Mr, 256>>>(x, pos, h, xn, ln1_s, ln1_b);
        else
            ln_kernel<1><<<Mr, 256>>>(h, nullptr, nullptr, xn,
                                      ln1_s + l * Cc, ln1_b + l * Cc);

        // QKV: z = s*8+h (24). q,k: fp16 rows; v: vT via smem staging.
        gemm_mma<5><<<dim3(1, 32, 24), 256, SM_MM>>>(
            xn, Cc, 1, 0, 0,
            wqkv_h + (long long)l * 3 * HDK, Cc, 1, DK, 0,
            (float*)qkv, Dd, 1, (long long)Mr * Dd, 0,
            nullptr, Cc);

        // fused scores + softmax + att@V
        fused_attn<<<dim3(16, 32), 256, SM_ATT>>>(qkv, atts_l, o);

        // proj: h += o @ Wo + bo
        gemm_mma<2><<<dim3(8, 32, 1), 256, SM_MM>>>(
            o, Cc, 1, 0, 0,
            wo_h + (long long)l * Cc * Cc, Cc, 1, 0, 0,
            h, Cc, 1, 0, 0,
            bo + l * Cc, Cc);

        // LN2 -> xn fp16
        ln_kernel<1><<<Mr, 256>>>(h, nullptr, nullptr, xn,
                                  ln2_s + l * Cc, ln2_b + l * Cc);

        // FFN1: u = relu(xn @ W1 + b1) -> fp16
        gemm_mma<4><<<dim3(32, 32, 1), 256, SM_MM>>>(
            xn, Cc, 1, 0, 0,
            w1_h + (long long)l * Cc * Ff, Cc, 1, 0, 0,
            (float*)u, Ff, 1, 0, 0,
            b1 + l * Ff, Cc);

        // FFN2: h += u @ W2 + b2
        gemm_mma<2><<<dim3(8, 32, 1), 256, SM_MM>>>(
            u, Ff, 1, 0, 0,
            w2_h + (long long)l * Ff * Cc, Ff, 1, 0, 0,
            h, Cc, 1, 0, 0,
            b2 + l * Cc, Ff);
    }

    // final LN -> fp32 output (streaming store)
    ln_kernel<0><<<Mr, 256>>>(h, nullptr, outx, nullptr, lnf_s, lnf_b);
}

// round 14
// speedup vs baseline: 1.1913x; 1.0207x over previous
#include <cuda_runtime.h>
#include <cuda_fp16.h>
#include <cstdint>

// Problem constants
constexpr int Bb = 4, Ts = 1024, Cc = 1024, Hh = 8, Dd = 128, Ff = 4096, Ll = 4;
constexpr int Mr = Bb * Ts;  // 4096

// ---------------- scratch (device globals; allocation-free rule) ----------
__device__ float  g_h[(size_t)Mr * Cc];                    // residual fp32
__device__ __half g_qkv[(size_t)3 * Hh * Mr * Dd];         // q,k rows; vT cols
__device__ __half g_xn[(size_t)Mr * Cc];                   // LN out fp16
__device__ __half g_o[(size_t)Mr * Cc];                    // attn out fp16
__device__ __half g_u[(size_t)Mr * Ff];                    // FFN hidden fp16
__device__ __half g_wqkv_h[(size_t)Ll * 3 * Hh * Dd * Cc]; // fp16 weights [N,K]
__device__ __half g_wo_h[(size_t)Ll * Cc * Cc];
__device__ __half g_w1_h[(size_t)Ll * Cc * Ff];
__device__ __half g_w2_h[(size_t)Ll * Ff * Cc];

// ---------------- PTX helpers (sm_80-era; compiles for plain sm_103) ------
__device__ __forceinline__ uint32_t smem_u32(const void* p) {
    uint32_t a;
    asm("{ .reg .u64 t; cvta.to.shared.u64 t, %1; cvt.u32.u64 %0, t; }" : "=r"(a) : "l"(p));
    return a;
}
__device__ __forceinline__ void cp16(uint32_t s, const void* g) {
    asm volatile("cp.async.cg.shared.global [%0], [%1], 16;" :: "r"(s), "l"(g));
}
#define CP_COMMIT() asm volatile("cp.async.commit_group;" ::: "memory")
#define CP_WAIT(n)  asm volatile("cp.async.wait_group %0;" :: "n"(n) : "memory")

#define LDSM4(r, addr) \
    asm volatile("ldmatrix.sync.aligned.m8n8.x4.shared.b16 {%0,%1,%2,%3}, [%4];" \
        : "=r"((r)[0]), "=r"((r)[1]), "=r"((r)[2]), "=r"((r)[3]) : "r"(addr))

#define MMA16816(c, a, b) \
    asm volatile("mma.sync.aligned.m16n8k16.row.col.f32.f16.f16.f32 " \
        "{%0,%1,%2,%3}, {%4,%5,%6,%7}, {%8,%9}, {%0,%1,%2,%3};" \
        : "+f"((c)[0]), "+f"((c)[1]), "+f"((c)[2]), "+f"((c)[3]) \
        : "r"((a)[0]), "r"((a)[1]), "r"((a)[2]), "r"((a)[3]), \
          "r"((b)[0]), "r"((b)[1]))

// ---------------------------------------------------------------------------
// HMMA fp16 GEMM: C[M,N] = A[M,K] * Bt[N,K]^T, fp32 accum.
// Block 128x128, 8 warps (4M x 2N), K-chunks of 64, 3-stage cp.async, occ 2.
// NCH = K/64 (compile-time trip count for full scheduling).
// EPI: 2 fp32 += acc+bias | 4 relu(acc+bias)->fp16 rows
//      5 QKV: z<16 fp16 rows, z>=16 vT transposed via smem staging (ld = Mr)
// ---------------------------------------------------------------------------
constexpr int STG   = 36864;            // 128 rows * 144 B * 2 matrices
constexpr int B_OFF = 18432;
constexpr int SM_MM = 3 * STG;          // 110592

template<int EPI, int NCH>
__global__ void __launch_bounds__(256, 2)
gemm_mma(const __half* __restrict__ A, int lda,
         int aDiv, long long aShi, long long aSlo,
         const __half* __restrict__ B, int ldb,
         int bDiv, long long bShi, long long bSlo,
         float* __restrict__ Cm, int ldc,
         int cDiv, long long cShi, long long cSlo,
         const float* __restrict__ bias)
{
    extern __shared__ char sm[];
    const uint32_t sb = smem_u32(sm);

    const int tid = threadIdx.x;
    const int lane = tid & 31;
    const int warp = tid >> 5;
    const int warpM = warp & 3;
    const int warpN = warp >> 2;

    const int z = blockIdx.z;
    A  += (long long)(z / aDiv) * aShi + (long long)(z % aDiv) * aSlo;
    B  += (long long)(z / bDiv) * bShi + (long long)(z % bDiv) * bSlo;
    const long long cOff = (long long)(z / cDiv) * cShi + (long long)(z % cDiv) * cSlo;

    const int rowBase = blockIdx.y * 128;
    const int colBase = blockIdx.x * 128;

    float acc[2][8][4];
#pragma unroll
    for (int i = 0; i < 2; i++)
#pragma unroll
        for (int j = 0; j < 8; j++)
#pragma unroll
            for (int q = 0; q < 4; q++) acc[i][j][q] = 0.f;

    const int ldr = tid >> 3;            // 0..31
    const int c16 = (tid & 7) * 16;      // byte col in 128B row

    auto load_chunk = [&](int i, int st) {
        const long long k0 = (long long)i * 64;
        const uint32_t sbase = sb + (uint32_t)st * STG;
#pragma unroll
        for (int g = 0; g < 4; g++) {
            const int rr = g * 32 + ldr;
            const uint32_t so = sbase + (uint32_t)(rr * 144 + c16);
            cp16(so,
                 (const char*)(A + (long long)(rowBase + rr) * lda + k0) + c16);
            cp16(so + B_OFF,
                 (const char*)(B + (long long)(colBase + rr) * ldb + k0) + c16);
        }
    };

    load_chunk(0, 0); CP_COMMIT();
    load_chunk(1, 1); CP_COMMIT();

#pragma unroll 4
    for (int i = 0; i < NCH; i++) {
        if (i + 1 < NCH) { CP_WAIT(1); } else { CP_WAIT(0); }
        __syncthreads();
        if (i + 2 < NCH) { load_chunk(i + 2, (i + 2) % 3); CP_COMMIT(); }

        const uint32_t sbase = sb + (uint32_t)(i % 3) * STG;
#pragma unroll
        for (int ks = 0; ks < 4; ks++) {
            uint32_t ah[2][4], bh[8][2];
#pragma unroll
            for (int tm = 0; tm < 2; tm++) {
                const int row = warpM * 32 + tm * 16 + (lane & 15);
                const uint32_t addr =
                    sbase + (uint32_t)(row * 144 + ((lane >> 4) << 4) + ks * 32);
                LDSM4(ah[tm], addr);
            }
#pragma unroll
            for (int gn = 0; gn < 4; gn++) {
                const int n = warpN * 64 + gn * 16 + ((lane >> 4) & 1) * 8 + (lane & 7);
                const uint32_t addr =
                    sbase + (uint32_t)B_OFF +
                    (uint32_t)(n * 144 + ((lane >> 3) & 1) * 16 + ks * 32);
                uint32_t r0[4];
                LDSM4(r0, addr);
                bh[gn * 2][0] = r0[0]; bh[gn * 2][1] = r0[1];
                bh[gn * 2 + 1][0] = r0[2]; bh[gn * 2 + 1][1] = r0[3];
            }
#pragma unroll
            for (int tm = 0; tm < 2; tm++) {
#pragma unroll
                for (int tn = 0; tn < 8; tn++) {
                    MMA16816(acc[tm][tn], ah[tm], bh[tn]);
                }
            }
        }
    }

    const int lr = lane >> 2;
    const int lc = (lane & 3) * 2;

    if (EPI == 5 && blockIdx.z >= 16) {
        // ---- vT epilogue: stage transposed tile in smem, coalesced store ----
        __syncthreads();
        __half* st = (__half*)sm;                // [128 cols][136 halves stride]
#pragma unroll
        for (int tm = 0; tm < 2; tm++) {
#pragma unroll
            for (int tn = 0; tn < 8; tn++) {
                const int lrow = warpM * 32 + tm * 16 + lr;
                const int lcol = warpN * 64 + tn * 8 + lc;
                const float* a = acc[tm][tn];
                st[lcol * 136 + lrow]           = __float2half_rn(a[0]);
                st[(lcol + 1) * 136 + lrow]     = __float2half_rn(a[1]);
                st[lcol * 136 + lrow + 8]       = __float2half_rn(a[2]);
                st[(lcol + 1) * 136 + lrow + 8] = __float2half_rn(a[3]);
            }
        }
        __syncthreads();
        __half* base = (__half*)Cm + cOff;
        const int cr = tid >> 1;
        const int part = tid & 1;
        const uint4* src = (const uint4*)((const char*)st + cr * 272 + part * 128);
        uint4* dst = (uint4*)(base + (long long)(colBase + cr) * Mr + rowBase + part * 64);
#pragma unroll
        for (int i = 0; i < 8; i++) dst[i] = src[i];
        return;
    }

    // ---- standard epilogues from registers ----
    const int rB = rowBase + warpM * 32;
    const int cB = colBase + warpN * 64;
#pragma unroll
    for (int tm = 0; tm < 2; tm++) {
#pragma unroll
        for (int tn = 0; tn < 8; tn++) {
            const int row0 = rB + tm * 16 + lr;
            const int col  = cB + tn * 8 + lc;
            const float* a = acc[tm][tn];
            if (EPI == 2) {
                const float b0 = bias[col], b1 = bias[col + 1];
                float* p0 = Cm + cOff + (long long)row0 * ldc + col;
                float* p1 = Cm + cOff + (long long)(row0 + 8) * ldc + col;
                p0[0] += a[0] + b0;  p0[1] += a[1] + b1;
                p1[0] += a[2] + b0;  p1[1] += a[3] + b1;
            } else if (EPI == 4) {
                const float b0 = bias[col], b1 = bias[col + 1];
                __half* ph = (__half*)Cm + cOff;
#pragma unroll
                for (int half_ = 0; half_ < 2; half_++) {
                    float t0 = a[half_ * 2 + 0] + b0;
                    float t1 = a[half_ * 2 + 1] + b1;
                    t0 = t0 > 0.f ? t0 : 0.f;
                    t1 = t1 > 0.f ? t1 : 0.f;
                    *(__half2*)(ph + (long long)(row0 + half_ * 8) * ldc + col) =
                        __halves2half2(__float2half_rn(t0), __float2half_rn(t1));
                }
            } else {  // EPI 5 (q,k): fp16 row store
                __half* ph = (__half*)Cm + cOff;
#pragma unroll
                for (int half_ = 0; half_ < 2; half_++) {
                    *(__half2*)(ph + (long long)(row0 + half_ * 8) * ldc + col) =
                        __halves2half2(__float2half_rn(a[half_ * 2 + 0]),
                                       __float2half_rn(a[half_ * 2 + 1]));
                }
            }
        }
    }
}

// ---------------------------------------------------------------------------
// Fused attention: per block = (h, b, 64 q-rows). (R12/R13 version)
// ---------------------------------------------------------------------------
constexpr int PR_STRIDE = 2064;                  // 2048 + 16 pad
constexpr int Q_OFF  = 64 * PR_STRIDE;           // 132096
constexpr int KV_OFF = Q_OFF + 64 * 272;         // 149504
constexpr int SM_ATT = KV_OFF + 2 * 34816;       // 219136

__global__ void __launch_bounds__(256, 1)
fused_attn(const __half* __restrict__ qkv, float* __restrict__ atts_l,
           __half* __restrict__ o)
{
    extern __shared__ char sm[];
    const uint32_t sb = smem_u32(sm);

    const int tid = threadIdx.x;
    const int lane = tid & 31;
    const int warp = tid >> 5;
    const int warpM = warp & 1;
    const int warpN = warp >> 1;

    const int qt = blockIdx.x;
    const int hb = blockIdx.y;
    const int hh = hb >> 2, bb = hb & 3;

    const long long MrD = (long long)Mr * Dd;
    const __half* qbase = qkv + hh * MrD + (long long)(bb * Ts + qt * 64) * Dd;
    const __half* kbase = qkv + (long long)Hh * MrD + hh * MrD + (long long)(bb * Ts) * Dd;
    const __half* vbase = qkv + 2ll * Hh * MrD + hh * MrD + (long long)(bb * Ts);

    const uint32_t qs = sb + Q_OFF;
    const uint32_t kv = sb + KV_OFF;

    {
        const int r = tid >> 2;
        const int c = (tid & 3) * 16;
#pragma unroll
        for (int g = 0; g < 4; g++)
            cp16(qs + (uint32_t)(r * 272 + c + g * 64),
                 (const char*)(qbase + (long long)r * Dd) + c + g * 64);
    }
    CP_COMMIT();

    auto load_k = [&](int kt, int st) {
        const int r = tid >> 1;
        const int c = (tid & 1) * 16;
        const char* src = (const char*)(kbase + (long long)(kt * 128 + r) * Dd);
        const uint32_t dst = kv + (uint32_t)st * 34816 + (uint32_t)(r * 272);
#pragma unroll
        for (int g = 0; g < 8; g++)
            cp16(dst + c + g * 32, src + c + g * 32);
    };
    auto load_v = [&](int kc, int st) {
        const int r = tid >> 1;
        const int c = (tid & 1) * 16;
        const char* src = (const char*)(vbase + (long long)r * Mr + kc * 128);
        const uint32_t dst = kv + (uint32_t)st * 34816 + (uint32_t)(r * 272);
#pragma unroll
        for (int g = 0; g < 8; g++)
            cp16(dst + c + g * 32, src + c + g * 32);
    };

    const int lr = lane >> 2;
    const int lc = (lane & 3) * 2;

    // ================= phase 1: scores =================
    load_k(0, 0); CP_COMMIT();
    for (int kt = 0; kt < 8; kt++) {
        CP_WAIT(0);
        __syncthreads();
        if (kt + 1 < 8) { load_k(kt + 1, (kt + 1) & 1); CP_COMMIT(); }

        const uint32_t kbuf = kv + (uint32_t)(kt & 1) * 34816;
        float acc[2][4][4];
#pragma unroll
        for (int i = 0; i < 2; i++)
#pragma unroll
            for (int j = 0; j < 4; j++)
#pragma unroll
                for (int q = 0; q < 4; q++) acc[i][j][q] = 0.f;

#pragma unroll
        for (int ks = 0; ks < 8; ks++) {
            uint32_t ah[2][4], bh[4][2];
#pragma unroll
            for (int tm = 0; tm < 2; tm++) {
                const int row = warpM * 32 + tm * 16 + (lane & 15);
                LDSM4(ah[tm], qs + (uint32_t)(row * 272 + ((lane >> 4) << 4) + ks * 32));
            }
#pragma unroll
            for (int gn = 0; gn < 2; gn++) {
                const int n = warpN * 32 + gn * 16 + ((lane >> 4) & 1) * 8 + (lane & 7);
                uint32_t r0[4];
                LDSM4(r0, kbuf + (uint32_t)(n * 272 + ((lane >> 3) & 1) * 16 + ks * 32));
                bh[gn * 2][0] = r0[0]; bh[gn * 2][1] = r0[1];
                bh[gn * 2 + 1][0] = r0[2]; bh[gn * 2 + 1][1] = r0[3];
            }
#pragma unroll
            for (int tm = 0; tm < 2; tm++)
#pragma unroll
                for (int tn = 0; tn < 4; tn++)
                    MMA16816(acc[tm][tn], ah[tm], bh[tn]);
        }

#pragma unroll
        for (int tm = 0; tm < 2; tm++) {
#pragma unroll
            for (int tn = 0; tn < 4; tn++) {
                const int row0 = warpM * 32 + tm * 16 + lr;
                const int col = kt * 128 + warpN * 32 + tn * 8 + lc;
                const float* a = acc[tm][tn];
#pragma unroll
                for (int half_ = 0; half_ < 2; half_++) {
                    *(__half2*)(sm + (row0 + half_ * 8) * PR_STRIDE + col * 2) =
                        __halves2half2(__float2half_rn(a[half_ * 2 + 0]),
                                       __float2half_rn(a[half_ * 2 + 1]));
                }
            }
        }
    }
    __syncthreads();

    load_v(0, 0); CP_COMMIT();

    // ================= softmax (warp per 8 rows, coalesced) =================
    {
        const float sc = 0.08838834764831845f;
        for (int rr = 0; rr < 8; rr++) {
            const int row = warp * 8 + rr;
            __half2* prow = (__half2*)(sm + row * PR_STRIDE);
            float v[32];
            float mx = -1e30f;
#pragma unroll
            for (int j = 0; j < 8; j++) {
                const int idx = j * 64 + lane * 2;
                const __half2 a2 = prow[idx];
                const __half2 b2 = prow[idx + 1];
                float f0 = __half2float(__low2half(a2)) * sc;
                float f1 = __half2float(__high2half(a2)) * sc;
                float f2 = __half2float(__low2half(b2)) * sc;
                float f3 = __half2float(__high2half(b2)) * sc;
                v[4 * j] = f0; v[4 * j + 1] = f1; v[4 * j + 2] = f2; v[4 * j + 3] = f3;
                mx = fmaxf(mx, fmaxf(fmaxf(f0, f1), fmaxf(f2, f3)));
            }
#pragma unroll
            for (int off = 16; off; off >>= 1)
                mx = fmaxf(mx, __shfl_xor_sync(0xFFFFFFFFu, mx, off));
            float s = 0.f;
#pragma unroll
            for (int i = 0; i < 32; i++) { v[i] = __expf(v[i] - mx); s += v[i]; }
#pragma unroll
            for (int off = 16; off; off >>= 1)
                s += __shfl_xor_sync(0xFFFFFFFFu, s, off);
            const float inv = 1.f / s;

            float* arow = atts_l + ((long long)hb * Ts + qt * 64 + row) * 1024;
#pragma unroll
            for (int j = 0; j < 8; j++) {
                const int idx = j * 64 + lane * 2;
                const float f0 = v[4 * j] * inv, f1 = v[4 * j + 1] * inv;
                const float f2 = v[4 * j + 2] * inv, f3 = v[4 * j + 3] * inv;
                prow[idx]     = __halves2half2(__float2half_rn(f0), __float2half_rn(f1));
                prow[idx + 1] = __halves2half2(__float2half_rn(f2), __float2half_rn(f3));
                float4 o4 = {f0, f1, f2, f3};
                __stcs((float4*)(arow + j * 128 + lane * 4), o4);
            }
        }
    }
    __syncthreads();

    // ================= phase 2: O = P @ vT (8 chunks of 128 cols) ==========
    float acc2[2][4][4];
#pragma unroll
    for (int i = 0; i < 2; i++)
#pragma unroll
        for (int j = 0; j < 4; j++)
#pragma unroll
            for (int q = 0; q < 4; q++) acc2[i][j][q] = 0.f;

    for (int kc = 0; kc < 8; kc++) {
        CP_WAIT(0);
        __syncthreads();
        if (kc + 1 < 8) { load_v(kc + 1, (kc + 1) & 1); CP_COMMIT(); }

        const uint32_t vbuf = kv + (uint32_t)(kc & 1) * 34816;
#pragma unroll
        for (int ks = 0; ks < 8; ks++) {
            uint32_t ah[2][4], bh[4][2];
#pragma unroll
            for (int tm = 0; tm < 2; tm++) {
                const int row = warpM * 32 + tm * 16 + (lane & 15);
                LDSM4(ah[tm], sb + (uint32_t)(row * PR_STRIDE + kc * 256 +
                                              ((lane >> 4) << 4) + ks * 32));
            }
#pragma unroll
            for (int gn = 0; gn < 2; gn++) {
                const int n = warpN * 32 + gn * 16 + ((lane >> 4) & 1) * 8 + (lane & 7);
                uint32_t r0[4];
                LDSM4(r0, vbuf + (uint32_t)(n * 272 + ((lane >> 3) & 1) * 16 + ks * 32));
                bh[gn * 2][0] = r0[0]; bh[gn * 2][1] = r0[1];
                bh[gn * 2 + 1][0] = r0[2]; bh[gn * 2 + 1][1] = r0[3];
            }
#pragma unroll
            for (int tm = 0; tm < 2; tm++)
#pragma unroll
                for (int tn = 0; tn < 4; tn++)
                    MMA16816(acc2[tm][tn], ah[tm], bh[tn]);
        }
    }

#pragma unroll
    for (int tm = 0; tm < 2; tm++) {
#pragma unroll
        for (int tn = 0; tn < 4; tn++) {
            const int row0 = warpM * 32 + tm * 16 + lr;
            const int col = warpN * 32 + tn * 8 + lc;
            const float* a = acc2[tm][tn];
#pragma unroll
            for (int half_ = 0; half_ < 2; half_++) {
                const long long grow = (long long)(bb * Ts + qt * 64 + row0 + half_ * 8);
                *(__half2*)(o + grow * Cc + hh * 128 + col) =
                    __halves2half2(__float2half_rn(a[half_ * 2 + 0]),
                                   __float2half_rn(a[half_ * 2 + 1]));
            }
        }
    }
}

// ---------------------------------------------------------------------------
// 64x64-tile weight transpose + fp16 convert, float4 loads, 8B stores.
// ---------------------------------------------------------------------------
__global__ void __launch_bounds__(256)
transpose64(const float* __restrict__ W, long long inSlo,
            __half* __restrict__ out, long long outSlo, int K, int N)
{
    const int z = blockIdx.z;
    W += (long long)z * inSlo;
    const long long oOff = (long long)z * outSlo;
    __shared__ float t[64][65];
    const int r  = threadIdx.x >> 4;
    const int c4 = threadIdx.x & 15;
    const int n0 = blockIdx.x * 64, k0 = blockIdx.y * 64;
#pragma unroll
    for (int i = 0; i < 4; i++) {
        const int row = i * 16 + r;
        float4 v = *(const float4*)(W + (long long)(k0 + row) * N + n0 + c4 * 4);
        t[c4 * 4 + 0][row] = v.x;
        t[c4 * 4 + 1][row] = v.y;
        t[c4 * 4 + 2][row] = v.z;
        t[c4 * 4 + 3][row] = v.w;
    }
    __syncthreads();
#pragma unroll
    for (int i = 0; i < 4; i++) {
        const int n = i * 16 + r;
        const float f0 = t[n][c4 * 4 + 0];
        const float f1 = t[n][c4 * 4 + 1];
        const float f2 = t[n][c4 * 4 + 2];
        const float f3 = t[n][c4 * 4 + 3];
        __half2* dst = (__half2*)(out + oOff + (long long)(n0 + n) * K + k0 + c4 * 4);
        dst[0] = __halves2half2(__float2half_rn(f0), __float2half_rn(f1));
        dst[1] = __halves2half2(__float2half_rn(f2), __float2half_rn(f3));
    }
}

// Merged QKV weight transpose (64x64 tiles): z in [0,96).
__global__ void __launch_bounds__(256)
transpose_qkv64(const float* __restrict__ Wq, const float* __restrict__ Wk,
                const float* __restrict__ Wv, __half* __restrict__ outw)
{
    const long long DK  = (long long)Dd * Cc;
    const long long HDK = Hh * DK;
    const int z = blockIdx.z;
    const int s = z >> 5;
    const int zz = z & 31;
    const float* W = (s == 0 ? Wq : s == 1 ? Wk : Wv) + (long long)zz * DK;
    const int l = zz >> 3, hd = zz & 7;
    __half* outp = outw + (long long)l * 3 * HDK + (long long)s * HDK + (long long)hd * DK;

    __shared__ float t[64][65];
    const int r  = threadIdx.x >> 4;
    const int c4 = threadIdx.x & 15;
    const int n0 = blockIdx.x * 64, k0 = blockIdx.y * 64;
#pragma unroll
    for (int i = 0; i < 4; i++) {
        const int row = i * 16 + r;
        float4 v = *(const float4*)(W + (long long)(k0 + row) * Dd + n0 + c4 * 4);
        t[c4 * 4 + 0][row] = v.x;
        t[c4 * 4 + 1][row] = v.y;
        t[c4 * 4 + 2][row] = v.z;
        t[c4 * 4 + 3][row] = v.w;
    }
    __syncthreads();
#pragma unroll
    for (int i = 0; i < 4; i++) {
        const int n = i * 16 + r;
        const float f0 = t[n][c4 * 4 + 0];
        const float f1 = t[n][c4 * 4 + 1];
        const float f2 = t[n][c4 * 4 + 2];
        const float f3 = t[n][c4 * 4 + 3];
        __half2* dst = (__half2*)(outp + (long long)(n0 + n) * Cc + k0 + c4 * 4);
        dst[0] = __halves2half2(__float2half_rn(f0), __float2half_rn(f1));
        dst[1] = __halves2half2(__float2half_rn(f2), __float2half_rn(f3));
    }
}

// ---------------------------------------------------------------------------
// LayerNorm (warp-shuffle reductions).
// MODE 0: fp32 out (streaming). MODE 1: fp16 out. MODE 2: x+pos fused.
// ---------------------------------------------------------------------------
template<int MODE>
__global__ void __launch_bounds__(256)
ln_kernel(const float* __restrict__ x, const float* __restrict__ pos,
          float* __restrict__ y, __half* __restrict__ yh,
          const float* __restrict__ s, const float* __restrict__ b)
{
    __shared__ float red[16];
    const int tid = threadIdx.x;
    const int lane = tid & 31;
    const int warp = tid >> 5;
    const long long row = blockIdx.x;

    float4 v = *(const float4*)(x + row * 1024 + tid * 4);
    if (MODE == 2) {
        const long long prow = row & (Ts - 1);
        float4 p = *(const float4*)(pos + prow * 1024 + tid * 4);
        v.x += p.x; v.y += p.y; v.z += p.z; v.w += p.w;
        *(float4*)(y + row * 1024 + tid * 4) = v;
    }

    float sm1 = v.x + v.y + v.z + v.w;
#pragma unroll
    for (int off = 16; off; off >>= 1)
        sm1 += __shfl_xor_sync(0xFFFFFFFFu, sm1, off);
    if (lane == 0) red[warp] = sm1;
    __syncthreads();
    float tot = 0.f;
#pragma unroll
    for (int w = 0; w < 8; w++) tot += red[w];
    const float mean = tot * (1.f / 1024.f);

    float dx = v.x - mean, dy = v.y - mean, dz = v.z - mean, dw = v.w - mean;
    float sm2 = dx * dx + dy * dy + dz * dz + dw * dw;
#pragma unroll
    for (int off = 16; off; off >>= 1)
        sm2 += __shfl_xor_sync(0xFFFFFFFFu, sm2, off);
    if (lane == 0) red[8 + warp] = sm2;
    __syncthreads();
    float tot2 = 0.f;
#pragma unroll
    for (int w = 0; w < 8; w++) tot2 += red[8 + w];
    const float rs = rsqrtf(tot2 * (1.f / 1024.f) + 1e-5f);

    const int c = tid * 4;
    float t0 = dx * rs * s[c + 0] + b[c + 0];
    float t1 = dy * rs * s[c + 1] + b[c + 1];
    float t2 = dz * rs * s[c + 2] + b[c + 2];
    float t3 = dw * rs * s[c + 3] + b[c + 3];
    if (MODE == 0) {
        float4 o4 = {t0, t1, t2, t3};
        __stcs((float4*)(y + row * 1024 + c), o4);
    } else {
        __half* ph = yh + row * 1024 + c;
        *(__half2*)ph = __halves2half2(__float2half_rn(t0), __float2half_rn(t1));
        *(__half2*)(ph + 2) = __halves2half2(__float2half_rn(t2), __float2half_rn(t3));
    }
}

// ---------------------------------------------------------------------------
extern "C" void kernel_launch(void* const* d_in, const int* in_sizes, int n_in,
                              void* d_out, int out_size)
{
    const float* x     = (const float*)d_in[0];
    const float* pos   = (const float*)d_in[1];
    const float* Wq    = (const float*)d_in[2];
    const float* Wk    = (const float*)d_in[3];
    const float* Wv    = (const float*)d_in[4];
    const float* Wo    = (const float*)d_in[5];
    const float* bo    = (const float*)d_in[6];
    const float* ln1_s = (const float*)d_in[7];
    const float* ln1_b = (const float*)d_in[8];
    const float* ln2_s = (const float*)d_in[9];
    const float* ln2_b = (const float*)d_in[10];
    const float* W1    = (const float*)d_in[11];
    const float* b1    = (const float*)d_in[12];
    const float* W2    = (const float*)d_in[13];
    const float* b2    = (const float*)d_in[14];
    const float* lnf_s = (const float*)d_in[15];
    const float* lnf_b = (const float*)d_in[16];

    float* out  = (float*)d_out;
    float* outx = out;
    float* atts = out + (long long)Mr * Cc;

    float* h;
    __half *qkv, *xn, *o, *u, *wqkv_h, *wo_h, *w1_h, *w2_h;
    cudaGetSymbolAddress((void**)&h,      g_h);
    cudaGetSymbolAddress((void**)&qkv,    g_qkv);
    cudaGetSymbolAddress((void**)&xn,     g_xn);
    cudaGetSymbolAddress((void**)&o,      g_o);
    cudaGetSymbolAddress((void**)&u,      g_u);
    cudaGetSymbolAddress((void**)&wqkv_h, g_wqkv_h);
    cudaGetSymbolAddress((void**)&wo_h,   g_wo_h);
    cudaGetSymbolAddress((void**)&w1_h,   g_w1_h);
    cudaGetSymbolAddress((void**)&w2_h,   g_w2_h);

    cudaFuncSetAttribute((const void*)gemm_mma<2, 16>, cudaFuncAttributeMaxDynamicSharedMemorySize, SM_MM);
    cudaFuncSetAttribute((const void*)gemm_mma<2, 64>, cudaFuncAttributeMaxDynamicSharedMemorySize, SM_MM);
    cudaFuncSetAttribute((const void*)gemm_mma<4, 16>, cudaFuncAttributeMaxDynamicSharedMemorySize, SM_MM);
    cudaFuncSetAttribute((const void*)gemm_mma<5, 16>, cudaFuncAttributeMaxDynamicSharedMemorySize, SM_MM);
    cudaFuncSetAttribute((const void*)fused_attn, cudaFuncAttributeMaxDynamicSharedMemorySize, SM_ATT);

    const long long DK   = (long long)Dd * Cc;       // 131072
    const long long HDK  = Hh * DK;
    const long long HBTT = (long long)Hh * Bb * Ts * Ts;

    // Weight transposes (64x64 tiles, float4)
    transpose_qkv64<<<dim3(Dd / 64, Cc / 64, 96), 256>>>(Wq, Wk, Wv, wqkv_h);
    transpose64<<<dim3(Cc / 64, Cc / 64, Ll), 256>>>(
        Wo, (long long)Cc * Cc, wo_h, (long long)Cc * Cc, Cc, Cc);
    transpose64<<<dim3(Ff / 64, Cc / 64, Ll), 256>>>(
        W1, (long long)Cc * Ff, w1_h, (long long)Ff * Cc, Cc, Ff);
    transpose64<<<dim3(Cc / 64, Ff / 64, Ll), 256>>>(
        W2, (long long)Ff * Cc, w2_h, (long long)Cc * Ff, Ff, Cc);

    for (int l = 0; l < Ll; l++) {
        float* atts_l = atts + (long long)l * HBTT;

        // LN1 (l==0 fuses add_pos)
        if (l == 0)
            ln_kernel<2><<<Mr, 256>>>(x, pos, h, xn, ln1_s, ln1_b);
        else
            ln_kernel<1><<<Mr, 256>>>(h, nullptr, nullptr, xn,
                                      ln1_s + l * Cc, ln1_b + l * Cc);

        // QKV (K=1024): z = s*8+h (24). q,k: fp16 rows; v: vT via smem staging.
        gemm_mma<5, 16><<<dim3(1, 32, 24), 256, SM_MM>>>(
            xn, Cc, 1, 0, 0,
            wqkv_h + (long long)l * 3 * HDK, Cc, 1, DK, 0,
            (float*)qkv, Dd, 1, (long long)Mr * Dd, 0,
            nullptr);

        // fused scores + softmax + att@V
        fused_attn<<<dim3(16, 32), 256, SM_ATT>>>(qkv, atts_l, o);

        // proj (K=1024): h += o @ Wo + bo
        gemm_mma<2, 16><<<dim3(8, 32, 1), 256, SM_MM>>>(
            o, Cc, 1, 0, 0,
            wo_h + (long long)l * Cc * Cc, Cc, 1, 0, 0,
            h, Cc, 1, 0, 0,
            bo + l * Cc);

        // LN2 -> xn fp16
        ln_kernel<1><<<Mr, 256>>>(h, nullptr, nullptr, xn,
                                  ln2_s + l * Cc, ln2_b + l * Cc);

        // FFN1 (K=1024): u = relu(xn @ W1 + b1) -> fp16
        gemm_mma<4, 16><<<dim3(32, 32, 1), 256, SM_MM>>>(
            xn, Cc, 1, 0, 0,
            w1_h + (long long)l * Cc * Ff, Cc, 1, 0, 0,
            (float*)u, Ff, 1, 0, 0,
            b1 + l * Ff);

        // FFN2 (K=4096): h += u @ W2 + b2
        gemm_mma<2, 64><<<dim3(8, 32, 1), 256, SM_MM>>>(
            u, Ff, 1, 0, 0,
            w2_h + (long long)l * Ff * Cc, Ff, 1, 0, 0,
            h, Cc, 1, 0, 0,
            b2 + l * Cc);
    }

    // final LN -> fp32 output (streaming store)
    ln_kernel<0><<<Mr, 256>>>(h, nullptr, outx, nullptr, lnf_s, lnf_b);
}

// round 15
// speedup vs baseline: 1.2027x; 1.0096x over previous
#include <cuda_runtime.h>
#include <cuda_fp16.h>
#include <cstdint>

// Problem constants
constexpr int Bb = 4, Ts = 1024, Cc = 1024, Hh = 8, Dd = 128, Ff = 4096, Ll = 4;
constexpr int Mr = Bb * Ts;  // 4096

// ---------------- scratch (device globals; allocation-free rule) ----------
__device__ float  g_h[(size_t)Mr * Cc];                    // residual fp32
__device__ __half g_qkv[(size_t)3 * Hh * Mr * Dd];         // q,k rows; vT cols
__device__ __half g_xn[(size_t)Mr * Cc];                   // LN out fp16
__device__ __half g_o[(size_t)Mr * Cc];                    // attn out fp16
__device__ __half g_u[(size_t)Mr * Ff];                    // FFN hidden fp16
__device__ __half g_wqkv_h[(size_t)Ll * 3 * Hh * Dd * Cc]; // fp16 weights [N,K]
__device__ __half g_wo_h[(size_t)Ll * Cc * Cc];
__device__ __half g_w1_h[(size_t)Ll * Cc * Ff];
__device__ __half g_w2_h[(size_t)Ll * Ff * Cc];

// ---------------- PTX helpers (sm_80-era; compiles for plain sm_103) ------
__device__ __forceinline__ uint32_t smem_u32(const void* p) {
    uint32_t a;
    asm("{ .reg .u64 t; cvta.to.shared.u64 t, %1; cvt.u32.u64 %0, t; }" : "=r"(a) : "l"(p));
    return a;
}
__device__ __forceinline__ void cp16(uint32_t s, const void* g) {
    asm volatile("cp.async.cg.shared.global [%0], [%1], 16;" :: "r"(s), "l"(g));
}
#define CP_COMMIT() asm volatile("cp.async.commit_group;" ::: "memory")
#define CP_WAIT(n)  asm volatile("cp.async.wait_group %0;" :: "n"(n) : "memory")

#define LDSM4(r, addr) \
    asm volatile("ldmatrix.sync.aligned.m8n8.x4.shared.b16 {%0,%1,%2,%3}, [%4];" \
        : "=r"((r)[0]), "=r"((r)[1]), "=r"((r)[2]), "=r"((r)[3]) : "r"(addr))

#define MMA16816(c, a, b) \
    asm volatile("mma.sync.aligned.m16n8k16.row.col.f32.f16.f16.f32 " \
        "{%0,%1,%2,%3}, {%4,%5,%6,%7}, {%8,%9}, {%0,%1,%2,%3};" \
        : "+f"((c)[0]), "+f"((c)[1]), "+f"((c)[2]), "+f"((c)[3]) \
        : "r"((a)[0]), "r"((a)[1]), "r"((a)[2]), "r"((a)[3]), \
          "r"((b)[0]), "r"((b)[1]))

// ---------------------------------------------------------------------------
// HMMA fp16 GEMM: C[M,N] = A[M,K] * Bt[N,K]^T, fp32 accum.
// Block 128x128, 8 warps (4M x 2N), K-chunks of 64, 3-stage cp.async, occ 2.
// NCH = K/64 (compile-time trip count for full scheduling).
// EPI: 2 fp32 += acc+bias | 4 relu(acc+bias)->fp16 rows
//      5 QKV: z<16 fp16 rows, z>=16 vT transposed via smem staging (ld = Mr)
// ---------------------------------------------------------------------------
constexpr int STG   = 36864;            // 128 rows * 144 B * 2 matrices
constexpr int B_OFF = 18432;
constexpr int SM_MM = 3 * STG;          // 110592

template<int EPI, int NCH>
__global__ void __launch_bounds__(256, 2)
gemm_mma(const __half* __restrict__ A, int lda,
         int aDiv, long long aShi, long long aSlo,
         const __half* __restrict__ B, int ldb,
         int bDiv, long long bShi, long long bSlo,
         float* __restrict__ Cm, int ldc,
         int cDiv, long long cShi, long long cSlo,
         const float* __restrict__ bias)
{
    extern __shared__ char sm[];
    const uint32_t sb = smem_u32(sm);

    const int tid = threadIdx.x;
    const int lane = tid & 31;
    const int warp = tid >> 5;
    const int warpM = warp & 3;
    const int warpN = warp >> 2;

    const int z = blockIdx.z;
    A  += (long long)(z / aDiv) * aShi + (long long)(z % aDiv) * aSlo;
    B  += (long long)(z / bDiv) * bShi + (long long)(z % bDiv) * bSlo;
    const long long cOff = (long long)(z / cDiv) * cShi + (long long)(z % cDiv) * cSlo;

    const int rowBase = blockIdx.y * 128;
    const int colBase = blockIdx.x * 128;

    float acc[2][8][4];
#pragma unroll
    for (int i = 0; i < 2; i++)
#pragma unroll
        for (int j = 0; j < 8; j++)
#pragma unroll
            for (int q = 0; q < 4; q++) acc[i][j][q] = 0.f;

    const int ldr = tid >> 3;            // 0..31
    const int c16 = (tid & 7) * 16;      // byte col in 128B row

    auto load_chunk = [&](int i, int st) {
        const long long k0 = (long long)i * 64;
        const uint32_t sbase = sb + (uint32_t)st * STG;
#pragma unroll
        for (int g = 0; g < 4; g++) {
            const int rr = g * 32 + ldr;
            const uint32_t so = sbase + (uint32_t)(rr * 144 + c16);
            cp16(so,
                 (const char*)(A + (long long)(rowBase + rr) * lda + k0) + c16);
            cp16(so + B_OFF,
                 (const char*)(B + (long long)(colBase + rr) * ldb + k0) + c16);
        }
    };

    load_chunk(0, 0); CP_COMMIT();
    load_chunk(1, 1); CP_COMMIT();

#pragma unroll 4
    for (int i = 0; i < NCH; i++) {
        if (i + 1 < NCH) { CP_WAIT(1); } else { CP_WAIT(0); }
        __syncthreads();
        if (i + 2 < NCH) { load_chunk(i + 2, (i + 2) % 3); CP_COMMIT(); }

        const uint32_t sbase = sb + (uint32_t)(i % 3) * STG;
#pragma unroll
        for (int ks = 0; ks < 4; ks++) {
            uint32_t ah[2][4], bh[8][2];
#pragma unroll
            for (int tm = 0; tm < 2; tm++) {
                const int row = warpM * 32 + tm * 16 + (lane & 15);
                const uint32_t addr =
                    sbase + (uint32_t)(row * 144 + ((lane >> 4) << 4) + ks * 32);
                LDSM4(ah[tm], addr);
            }
#pragma unroll
            for (int gn = 0; gn < 4; gn++) {
                const int n = warpN * 64 + gn * 16 + ((lane >> 4) & 1) * 8 + (lane & 7);
                const uint32_t addr =
                    sbase + (uint32_t)B_OFF +
                    (uint32_t)(n * 144 + ((lane >> 3) & 1) * 16 + ks * 32);
                uint32_t r0[4];
                LDSM4(r0, addr);
                bh[gn * 2][0] = r0[0]; bh[gn * 2][1] = r0[1];
                bh[gn * 2 + 1][0] = r0[2]; bh[gn * 2 + 1][1] = r0[3];
            }
#pragma unroll
            for (int tm = 0; tm < 2; tm++) {
#pragma unroll
                for (int tn = 0; tn < 8; tn++) {
                    MMA16816(acc[tm][tn], ah[tm], bh[tn]);
                }
            }
        }
    }

    const int lr = lane >> 2;
    const int lc = (lane & 3) * 2;

    if (EPI == 5 && blockIdx.z >= 16) {
        // ---- vT epilogue: stage transposed tile in smem, coalesced store ----
        __syncthreads();
        __half* st = (__half*)sm;                // [128 cols][136 halves stride]
#pragma unroll
        for (int tm = 0; tm < 2; tm++) {
#pragma unroll
            for (int tn = 0; tn < 8; tn++) {
                const int lrow = warpM * 32 + tm * 16 + lr;
                const int lcol = warpN * 64 + tn * 8 + lc;
                const float* a = acc[tm][tn];
                st[lcol * 136 + lrow]           = __float2half_rn(a[0]);
                st[(lcol + 1) * 136 + lrow]     = __float2half_rn(a[1]);
                st[lcol * 136 + lrow + 8]       = __float2half_rn(a[2]);
                st[(lcol + 1) * 136 + lrow + 8] = __float2half_rn(a[3]);
            }
        }
        __syncthreads();
        __half* base = (__half*)Cm + cOff;
        const int cr = tid >> 1;
        const int part = tid & 1;
        const uint4* src = (const uint4*)((const char*)st + cr * 272 + part * 128);
        uint4* dst = (uint4*)(base + (long long)(colBase + cr) * Mr + rowBase + part * 64);
#pragma unroll
        for (int i = 0; i < 8; i++) dst[i] = src[i];
        return;
    }

    // ---- standard epilogues from registers ----
    const int rB = rowBase + warpM * 32;
    const int cB = colBase + warpN * 64;
#pragma unroll
    for (int tm = 0; tm < 2; tm++) {
#pragma unroll
        for (int tn = 0; tn < 8; tn++) {
            const int row0 = rB + tm * 16 + lr;
            const int col  = cB + tn * 8 + lc;
            const float* a = acc[tm][tn];
            if (EPI == 2) {
                const float b0 = bias[col], b1 = bias[col + 1];
                float* p0 = Cm + cOff + (long long)row0 * ldc + col;
                float* p1 = Cm + cOff + (long long)(row0 + 8) * ldc + col;
                p0[0] += a[0] + b0;  p0[1] += a[1] + b1;
                p1[0] += a[2] + b0;  p1[1] += a[3] + b1;
            } else if (EPI == 4) {
                const float b0 = bias[col], b1 = bias[col + 1];
                __half* ph = (__half*)Cm + cOff;
#pragma unroll
                for (int half_ = 0; half_ < 2; half_++) {
                    float t0 = a[half_ * 2 + 0] + b0;
                    float t1 = a[half_ * 2 + 1] + b1;
                    t0 = t0 > 0.f ? t0 : 0.f;
                    t1 = t1 > 0.f ? t1 : 0.f;
                    *(__half2*)(ph + (long long)(row0 + half_ * 8) * ldc + col) =
                        __halves2half2(__float2half_rn(t0), __float2half_rn(t1));
                }
            } else {  // EPI 5 (q,k): fp16 row store
                __half* ph = (__half*)Cm + cOff;
#pragma unroll
                for (int half_ = 0; half_ < 2; half_++) {
                    *(__half2*)(ph + (long long)(row0 + half_ * 8) * ldc + col) =
                        __halves2half2(__float2half_rn(a[half_ * 2 + 0]),
                                       __float2half_rn(a[half_ * 2 + 1]));
                }
            }
        }
    }
}

// ---------------------------------------------------------------------------
// Fused attention: per block = (h, b, 64 q-rows). (proven R12-R14 version)
// ---------------------------------------------------------------------------
constexpr int PR_STRIDE = 2064;                  // 2048 + 16 pad
constexpr int Q_OFF  = 64 * PR_STRIDE;           // 132096
constexpr int KV_OFF = Q_OFF + 64 * 272;         // 149504
constexpr int SM_ATT = KV_OFF + 2 * 34816;       // 219136

__global__ void __launch_bounds__(256, 1)
fused_attn(const __half* __restrict__ qkv, float* __restrict__ atts_l,
           __half* __restrict__ o)
{
    extern __shared__ char sm[];
    const uint32_t sb = smem_u32(sm);

    const int tid = threadIdx.x;
    const int lane = tid & 31;
    const int warp = tid >> 5;
    const int warpM = warp & 1;
    const int warpN = warp >> 1;

    const int qt = blockIdx.x;
    const int hb = blockIdx.y;
    const int hh = hb >> 2, bb = hb & 3;

    const long long MrD = (long long)Mr * Dd;
    const __half* qbase = qkv + hh * MrD + (long long)(bb * Ts + qt * 64) * Dd;
    const __half* kbase = qkv + (long long)Hh * MrD + hh * MrD + (long long)(bb * Ts) * Dd;
    const __half* vbase = qkv + 2ll * Hh * MrD + hh * MrD + (long long)(bb * Ts);

    const uint32_t qs = sb + Q_OFF;
    const uint32_t kv = sb + KV_OFF;

    {
        const int r = tid >> 2;
        const int c = (tid & 3) * 16;
#pragma unroll
        for (int g = 0; g < 4; g++)
            cp16(qs + (uint32_t)(r * 272 + c + g * 64),
                 (const char*)(qbase + (long long)r * Dd) + c + g * 64);
    }
    CP_COMMIT();

    auto load_k = [&](int kt, int st) {
        const int r = tid >> 1;
        const int c = (tid & 1) * 16;
        const char* src = (const char*)(kbase + (long long)(kt * 128 + r) * Dd);
        const uint32_t dst = kv + (uint32_t)st * 34816 + (uint32_t)(r * 272);
#pragma unroll
        for (int g = 0; g < 8; g++)
            cp16(dst + c + g * 32, src + c + g * 32);
    };
    auto load_v = [&](int kc, int st) {
        const int r = tid >> 1;
        const int c = (tid & 1) * 16;
        const char* src = (const char*)(vbase + (long long)r * Mr + kc * 128);
        const uint32_t dst = kv + (uint32_t)st * 34816 + (uint32_t)(r * 272);
#pragma unroll
        for (int g = 0; g < 8; g++)
            cp16(dst + c + g * 32, src + c + g * 32);
    };

    const int lr = lane >> 2;
    const int lc = (lane & 3) * 2;

    // ================= phase 1: scores =================
    load_k(0, 0); CP_COMMIT();
    for (int kt = 0; kt < 8; kt++) {
        CP_WAIT(0);
        __syncthreads();
        if (kt + 1 < 8) { load_k(kt + 1, (kt + 1) & 1); CP_COMMIT(); }

        const uint32_t kbuf = kv + (uint32_t)(kt & 1) * 34816;
        float acc[2][4][4];
#pragma unroll
        for (int i = 0; i < 2; i++)
#pragma unroll
            for (int j = 0; j < 4; j++)
#pragma unroll
                for (int q = 0; q < 4; q++) acc[i][j][q] = 0.f;

#pragma unroll
        for (int ks = 0; ks < 8; ks++) {
            uint32_t ah[2][4], bh[4][2];
#pragma unroll
            for (int tm = 0; tm < 2; tm++) {
                const int row = warpM * 32 + tm * 16 + (lane & 15);
                LDSM4(ah[tm], qs + (uint32_t)(row * 272 + ((lane >> 4) << 4) + ks * 32));
            }
#pragma unroll
            for (int gn = 0; gn < 2; gn++) {
                const int n = warpN * 32 + gn * 16 + ((lane >> 4) & 1) * 8 + (lane & 7);
                uint32_t r0[4];
                LDSM4(r0, kbuf + (uint32_t)(n * 272 + ((lane >> 3) & 1) * 16 + ks * 32));
                bh[gn * 2][0] = r0[0]; bh[gn * 2][1] = r0[1];
                bh[gn * 2 + 1][0] = r0[2]; bh[gn * 2 + 1][1] = r0[3];
            }
#pragma unroll
            for (int tm = 0; tm < 2; tm++)
#pragma unroll
                for (int tn = 0; tn < 4; tn++)
                    MMA16816(acc[tm][tn], ah[tm], bh[tn]);
        }

#pragma unroll
        for (int tm = 0; tm < 2; tm++) {
#pragma unroll
            for (int tn = 0; tn < 4; tn++) {
                const int row0 = warpM * 32 + tm * 16 + lr;
                const int col = kt * 128 + warpN * 32 + tn * 8 + lc;
                const float* a = acc[tm][tn];
#pragma unroll
                for (int half_ = 0; half_ < 2; half_++) {
                    *(__half2*)(sm + (row0 + half_ * 8) * PR_STRIDE + col * 2) =
                        __halves2half2(__float2half_rn(a[half_ * 2 + 0]),
                                       __float2half_rn(a[half_ * 2 + 1]));
                }
            }
        }
    }
    __syncthreads();

    load_v(0, 0); CP_COMMIT();

    // ================= softmax (warp per 8 rows, coalesced) =================
    {
        const float sc = 0.08838834764831845f;
        for (int rr = 0; rr < 8; rr++) {
            const int row = warp * 8 + rr;
            __half2* prow = (__half2*)(sm + row * PR_STRIDE);
            float v[32];
            float mx = -1e30f;
#pragma unroll
            for (int j = 0; j < 8; j++) {
                const int idx = j * 64 + lane * 2;
                const __half2 a2 = prow[idx];
                const __half2 b2 = prow[idx + 1];
                float f0 = __half2float(__low2half(a2)) * sc;
                float f1 = __half2float(__high2half(a2)) * sc;
                float f2 = __half2float(__low2half(b2)) * sc;
                float f3 = __half2float(__high2half(b2)) * sc;
                v[4 * j] = f0; v[4 * j + 1] = f1; v[4 * j + 2] = f2; v[4 * j + 3] = f3;
                mx = fmaxf(mx, fmaxf(fmaxf(f0, f1), fmaxf(f2, f3)));
            }
#pragma unroll
            for (int off = 16; off; off >>= 1)
                mx = fmaxf(mx, __shfl_xor_sync(0xFFFFFFFFu, mx, off));
            float s = 0.f;
#pragma unroll
            for (int i = 0; i < 32; i++) { v[i] = __expf(v[i] - mx); s += v[i]; }
#pragma unroll
            for (int off = 16; off; off >>= 1)
                s += __shfl_xor_sync(0xFFFFFFFFu, s, off);
            const float inv = 1.f / s;

            float* arow = atts_l + ((long long)hb * Ts + qt * 64 + row) * 1024;
#pragma unroll
            for (int j = 0; j < 8; j++) {
                const int idx = j * 64 + lane * 2;
                const float f0 = v[4 * j] * inv, f1 = v[4 * j + 1] * inv;
                const float f2 = v[4 * j + 2] * inv, f3 = v[4 * j + 3] * inv;
                prow[idx]     = __halves2half2(__float2half_rn(f0), __float2half_rn(f1));
                prow[idx + 1] = __halves2half2(__float2half_rn(f2), __float2half_rn(f3));
                float4 o4 = {f0, f1, f2, f3};
                __stcs((float4*)(arow + j * 128 + lane * 4), o4);
            }
        }
    }
    __syncthreads();

    // ================= phase 2: O = P @ vT (8 chunks of 128 cols) ==========
    float acc2[2][4][4];
#pragma unroll
    for (int i = 0; i < 2; i++)
#pragma unroll
        for (int j = 0; j < 4; j++)
#pragma unroll
            for (int q = 0; q < 4; q++) acc2[i][j][q] = 0.f;

    for (int kc = 0; kc < 8; kc++) {
        CP_WAIT(0);
        __syncthreads();
        if (kc + 1 < 8) { load_v(kc + 1, (kc + 1) & 1); CP_COMMIT(); }

        const uint32_t vbuf = kv + (uint32_t)(kc & 1) * 34816;
#pragma unroll
        for (int ks = 0; ks < 8; ks++) {
            uint32_t ah[2][4], bh[4][2];
#pragma unroll
            for (int tm = 0; tm < 2; tm++) {
                const int row = warpM * 32 + tm * 16 + (lane & 15);
                LDSM4(ah[tm], sb + (uint32_t)(row * PR_STRIDE + kc * 256 +
                                              ((lane >> 4) << 4) + ks * 32));
            }
#pragma unroll
            for (int gn = 0; gn < 2; gn++) {
                const int n = warpN * 32 + gn * 16 + ((lane >> 4) & 1) * 8 + (lane & 7);
                uint32_t r0[4];
                LDSM4(r0, vbuf + (uint32_t)(n * 272 + ((lane >> 3) & 1) * 16 + ks * 32));
                bh[gn * 2][0] = r0[0]; bh[gn * 2][1] = r0[1];
                bh[gn * 2 + 1][0] = r0[2]; bh[gn * 2 + 1][1] = r0[3];
            }
#pragma unroll
            for (int tm = 0; tm < 2; tm++)
#pragma unroll
                for (int tn = 0; tn < 4; tn++)
                    MMA16816(acc2[tm][tn], ah[tm], bh[tn]);
        }
    }

#pragma unroll
    for (int tm = 0; tm < 2; tm++) {
#pragma unroll
        for (int tn = 0; tn < 4; tn++) {
            const int row0 = warpM * 32 + tm * 16 + lr;
            const int col = warpN * 32 + tn * 8 + lc;
            const float* a = acc2[tm][tn];
#pragma unroll
            for (int half_ = 0; half_ < 2; half_++) {
                const long long grow = (long long)(bb * Ts + qt * 64 + row0 + half_ * 8);
                *(__half2*)(o + grow * Cc + hh * 128 + col) =
                    __halves2half2(__float2half_rn(a[half_ * 2 + 0]),
                                   __float2half_rn(a[half_ * 2 + 1]));
            }
        }
    }
}

// ---------------------------------------------------------------------------
// 64x64-tile weight transpose + fp16 convert, float4 loads, 8B stores.
// ---------------------------------------------------------------------------
__global__ void __launch_bounds__(256)
transpose64(const float* __restrict__ W, long long inSlo,
            __half* __restrict__ out, long long outSlo, int K, int N)
{
    const int z = blockIdx.z;
    W += (long long)z * inSlo;
    const long long oOff = (long long)z * outSlo;
    __shared__ float t[64][65];
    const int r  = threadIdx.x >> 4;
    const int c4 = threadIdx.x & 15;
    const int n0 = blockIdx.x * 64, k0 = blockIdx.y * 64;
#pragma unroll
    for (int i = 0; i < 4; i++) {
        const int row = i * 16 + r;
        float4 v = *(const float4*)(W + (long long)(k0 + row) * N + n0 + c4 * 4);
        t[c4 * 4 + 0][row] = v.x;
        t[c4 * 4 + 1][row] = v.y;
        t[c4 * 4 + 2][row] = v.z;
        t[c4 * 4 + 3][row] = v.w;
    }
    __syncthreads();
#pragma unroll
    for (int i = 0; i < 4; i++) {
        const int n = i * 16 + r;
        const float f0 = t[n][c4 * 4 + 0];
        const float f1 = t[n][c4 * 4 + 1];
        const float f2 = t[n][c4 * 4 + 2];
        const float f3 = t[n][c4 * 4 + 3];
        __half2* dst = (__half2*)(out + oOff + (long long)(n0 + n) * K + k0 + c4 * 4);
        dst[0] = __halves2half2(__float2half_rn(f0), __float2half_rn(f1));
        dst[1] = __halves2half2(__float2half_rn(f2), __float2half_rn(f3));
    }
}

// Merged QKV weight transpose (64x64 tiles): z in [0,96).
__global__ void __launch_bounds__(256)
transpose_qkv64(const float* __restrict__ Wq, const float* __restrict__ Wk,
                const float* __restrict__ Wv, __half* __restrict__ outw)
{
    const long long DK  = (long long)Dd * Cc;
    const long long HDK = Hh * DK;
    const int z = blockIdx.z;
    const int s = z >> 5;
    const int zz = z & 31;
    const float* W = (s == 0 ? Wq : s == 1 ? Wk : Wv) + (long long)zz * DK;
    const int l = zz >> 3, hd = zz & 7;
    __half* outp = outw + (long long)l * 3 * HDK + (long long)s * HDK + (long long)hd * DK;

    __shared__ float t[64][65];
    const int r  = threadIdx.x >> 4;
    const int c4 = threadIdx.x & 15;
    const int n0 = blockIdx.x * 64, k0 = blockIdx.y * 64;
#pragma unroll
    for (int i = 0; i < 4; i++) {
        const int row = i * 16 + r;
        float4 v = *(const float4*)(W + (long long)(k0 + row) * Dd + n0 + c4 * 4);
        t[c4 * 4 + 0][row] = v.x;
        t[c4 * 4 + 1][row] = v.y;
        t[c4 * 4 + 2][row] = v.z;
        t[c4 * 4 + 3][row] = v.w;
    }
    __syncthreads();
#pragma unroll
    for (int i = 0; i < 4; i++) {
        const int n = i * 16 + r;
        const float f0 = t[n][c4 * 4 + 0];
        const float f1 = t[n][c4 * 4 + 1];
        const float f2 = t[n][c4 * 4 + 2];
        const float f3 = t[n][c4 * 4 + 3];
        __half2* dst = (__half2*)(outp + (long long)(n0 + n) * Cc + k0 + c4 * 4);
        dst[0] = __halves2half2(__float2half_rn(f0), __float2half_rn(f1));
        dst[1] = __halves2half2(__float2half_rn(f2), __float2half_rn(f3));
    }
}

// ---------------------------------------------------------------------------
// LayerNorm (warp-shuffle reductions).
// MODE 0: fp32 out (streaming). MODE 1: fp16 out. MODE 2: x+pos fused.
// ---------------------------------------------------------------------------
template<int MODE>
__global__ void __launch_bounds__(256)
ln_kernel(const float* __restrict__ x, const float* __restrict__ pos,
          float* __restrict__ y, __half* __restrict__ yh,
          const float* __restrict__ s, const float* __restrict__ b)
{
    __shared__ float red[16];
    const int tid = threadIdx.x;
    const int lane = tid & 31;
    const int warp = tid >> 5;
    const long long row = blockIdx.x;

    float4 v = *(const float4*)(x + row * 1024 + tid * 4);
    if (MODE == 2) {
        const long long prow = row & (Ts - 1);
        float4 p = *(const float4*)(pos + prow * 1024 + tid * 4);
        v.x += p.x; v.y += p.y; v.z += p.z; v.w += p.w;
        *(float4*)(y + row * 1024 + tid * 4) = v;
    }

    float sm1 = v.x + v.y + v.z + v.w;
#pragma unroll
    for (int off = 16; off; off >>= 1)
        sm1 += __shfl_xor_sync(0xFFFFFFFFu, sm1, off);
    if (lane == 0) red[warp] = sm1;
    __syncthreads();
    float tot = 0.f;
#pragma unroll
    for (int w = 0; w < 8; w++) tot += red[w];
    const float mean = tot * (1.f / 1024.f);

    float dx = v.x - mean, dy = v.y - mean, dz = v.z - mean, dw = v.w - mean;
    float sm2 = dx * dx + dy * dy + dz * dz + dw * dw;
#pragma unroll
    for (int off = 16; off; off >>= 1)
        sm2 += __shfl_xor_sync(0xFFFFFFFFu, sm2, off);
    if (lane == 0) red[8 + warp] = sm2;
    __syncthreads();
    float tot2 = 0.f;
#pragma unroll
    for (int w = 0; w < 8; w++) tot2 += red[8 + w];
    const float rs = rsqrtf(tot2 * (1.f / 1024.f) + 1e-5f);

    const int c = tid * 4;
    float t0 = dx * rs * s[c + 0] + b[c + 0];
    float t1 = dy * rs * s[c + 1] + b[c + 1];
    float t2 = dz * rs * s[c + 2] + b[c + 2];
    float t3 = dw * rs * s[c + 3] + b[c + 3];
    if (MODE == 0) {
        float4 o4 = {t0, t1, t2, t3};
        __stcs((float4*)(y + row * 1024 + c), o4);
    } else {
        __half* ph = yh + row * 1024 + c;
        *(__half2*)ph = __halves2half2(__float2half_rn(t0), __float2half_rn(t1));
        *(__half2*)(ph + 2) = __halves2half2(__float2half_rn(t2), __float2half_rn(t3));
    }
}

// ---------------------------------------------------------------------------
extern "C" void kernel_launch(void* const* d_in, const int* in_sizes, int n_in,
                              void* d_out, int out_size)
{
    const float* x     = (const float*)d_in[0];
    const float* pos   = (const float*)d_in[1];
    const float* Wq    = (const float*)d_in[2];
    const float* Wk    = (const float*)d_in[3];
    const float* Wv    = (const float*)d_in[4];
    const float* Wo    = (const float*)d_in[5];
    const float* bo    = (const float*)d_in[6];
    const float* ln1_s = (const float*)d_in[7];
    const float* ln1_b = (const float*)d_in[8];
    const float* ln2_s = (const float*)d_in[9];
    const float* ln2_b = (const float*)d_in[10];
    const float* W1    = (const float*)d_in[11];
    const float* b1    = (const float*)d_in[12];
    const float* W2    = (const float*)d_in[13];
    const float* b2    = (const float*)d_in[14];
    const float* lnf_s = (const float*)d_in[15];
    const float* lnf_b = (const float*)d_in[16];

    float* out  = (float*)d_out;
    float* outx = out;
    float* atts = out + (long long)Mr * Cc;

    float* h;
    __half *qkv, *xn, *o, *u, *wqkv_h, *wo_h, *w1_h, *w2_h;
    cudaGetSymbolAddress((void**)&h,      g_h);
    cudaGetSymbolAddress((void**)&qkv,    g_qkv);
    cudaGetSymbolAddress((void**)&xn,     g_xn);
    cudaGetSymbolAddress((void**)&o,      g_o);
    cudaGetSymbolAddress((void**)&u,      g_u);
    cudaGetSymbolAddress((void**)&wqkv_h, g_wqkv_h);
    cudaGetSymbolAddress((void**)&wo_h,   g_wo_h);
    cudaGetSymbolAddress((void**)&w1_h,   g_w1_h);
    cudaGetSymbolAddress((void**)&w2_h,   g_w2_h);

    cudaFuncSetAttribute((const void*)gemm_mma<2, 16>, cudaFuncAttributeMaxDynamicSharedMemorySize, SM_MM);
    cudaFuncSetAttribute((const void*)gemm_mma<2, 64>, cudaFuncAttributeMaxDynamicSharedMemorySize, SM_MM);
    cudaFuncSetAttribute((const void*)gemm_mma<4, 16>, cudaFuncAttributeMaxDynamicSharedMemorySize, SM_MM);
    cudaFuncSetAttribute((const void*)gemm_mma<5, 16>, cudaFuncAttributeMaxDynamicSharedMemorySize, SM_MM);
    cudaFuncSetAttribute((const void*)fused_attn, cudaFuncAttributeMaxDynamicSharedMemorySize, SM_ATT);

    const long long DK   = (long long)Dd * Cc;       // 131072
    const long long HDK  = Hh * DK;
    const long long HBTT = (long long)Hh * Bb * Ts * Ts;

    // ---- fork a side stream (graph-capturable event fork/join) ----
    // Created fresh per call; kernel_launch is invoked only for the
    // correctness run and the capture run, so the handles are not freed
    // (freeing during an active capture is illegal; leak is 2 calls' worth
    // of host-side handles, no device memory).
    cudaStream_t s2;
    cudaStreamCreateWithFlags(&s2, cudaStreamNonBlocking);
    cudaEvent_t eFork, eQkvW, eRestW;
    cudaEventCreateWithFlags(&eFork,  cudaEventDisableTiming);
    cudaEventCreateWithFlags(&eQkvW,  cudaEventDisableTiming);
    cudaEventCreateWithFlags(&eRestW, cudaEventDisableTiming);

    cudaEventRecord(eFork, 0);
    cudaStreamWaitEvent(s2, eFork, 0);

    // side stream: weight transposes
    transpose_qkv64<<<dim3(Dd / 64, Cc / 64, 96), 256, 0, s2>>>(Wq, Wk, Wv, wqkv_h);
    cudaEventRecord(eQkvW, s2);
    transpose64<<<dim3(Cc / 64, Cc / 64, Ll), 256, 0, s2>>>(
        Wo, (long long)Cc * Cc, wo_h, (long long)Cc * Cc, Cc, Cc);
    transpose64<<<dim3(Ff / 64, Cc / 64, Ll), 256, 0, s2>>>(
        W1, (long long)Cc * Ff, w1_h, (long long)Ff * Cc, Cc, Ff);
    transpose64<<<dim3(Cc / 64, Ff / 64, Ll), 256, 0, s2>>>(
        W2, (long long)Ff * Cc, w2_h, (long long)Cc * Ff, Ff, Cc);
    cudaEventRecord(eRestW, s2);

    for (int l = 0; l < Ll; l++) {
        float* atts_l = atts + (long long)l * HBTT;

        // LN1 (l==0 fuses add_pos; runs concurrent with qkv weight transpose)
        if (l == 0)
            ln_kernel<2><<<Mr, 256>>>(x, pos, h, xn, ln1_s, ln1_b);
        else
            ln_kernel<1><<<Mr, 256>>>(h, nullptr, nullptr, xn,
                                      ln1_s + l * Cc, ln1_b + l * Cc);

        if (l == 0) cudaStreamWaitEvent(0, eQkvW, 0);   // wqkv ready

        // QKV (K=1024): z = s*8+h (24). q,k: fp16 rows; v: vT via smem staging.
        gemm_mma<5, 16><<<dim3(1, 32, 24), 256, SM_MM>>>(
            xn, Cc, 1, 0, 0,
            wqkv_h + (long long)l * 3 * HDK, Cc, 1, DK, 0,
            (float*)qkv, Dd, 1, (long long)Mr * Dd, 0,
            nullptr);

        // fused scores + softmax + att@V (concurrent with Wo/W1/W2 transposes)
        fused_attn<<<dim3(16, 32), 256, SM_ATT>>>(qkv, atts_l, o);

        if (l == 0) cudaStreamWaitEvent(0, eRestW, 0);  // Wo/W1/W2 ready

        // proj (K=1024): h += o @ Wo + bo
        gemm_mma<2, 16><<<dim3(8, 32, 1), 256, SM_MM>>>(
            o, Cc, 1, 0, 0,
            wo_h + (long long)l * Cc * Cc, Cc, 1, 0, 0,
            h, Cc, 1, 0, 0,
            bo + l * Cc);

        // LN2 -> xn fp16
        ln_kernel<1><<<Mr, 256>>>(h, nullptr, nullptr, xn,
                                  ln2_s + l * Cc, ln2_b + l * Cc);

        // FFN1 (K=1024): u = relu(xn @ W1 + b1) -> fp16
        gemm_mma<4, 16><<<dim3(32, 32, 1), 256, SM_MM>>>(
            xn, Cc, 1, 0, 0,
            w1_h + (long long)l * Cc * Ff, Cc, 1, 0, 0,
            (float*)u, Ff, 1, 0, 0,
            b1 + l * Ff);

        // FFN2 (K=4096): h += u @ W2 + b2
        gemm_mma<2, 64><<<dim3(8, 32, 1), 256, SM_MM>>>(
            u, Ff, 1, 0, 0,
            w2_h + (long long)l * Ff * Cc, Ff, 1, 0, 0,
            h, Cc, 1, 0, 0,
            b2 + l * Cc);
    }

    // final LN -> fp32 output (streaming store)
    ln_kernel<0><<<Mr, 256>>>(h, nullptr, outx, nullptr, lnf_s, lnf_b);
}